// round 1
// baseline (speedup 1.0000x reference)
#include <cuda_runtime.h>
#include <math.h>
#include <float.h>

#define NROWS 131072
#define E_DIM 1024
#define L_DIM 512
#define D_DIM 256
#define NI    50

// ---------------- device scratch (allocation-free rule) ----------------
__device__ float g_h[(size_t)NROWS * L_DIM];   // 268 MB
__device__ float g_g[(size_t)NROWS * D_DIM];   // 134 MB (tanh branch, then gated product)
__device__ float g_A[(size_t)NROWS * 2];       // pre-softmax attention scores
__device__ int      g_hist[16384];
__device__ unsigned g_maxkey[2];
__device__ float    g_Z[2];
__device__ float    g_bag[2 * L_DIM];
__device__ int      g_binhi, g_binlo;
__device__ int      g_nhi, g_nlo;
__device__ float g_chv[NROWS]; __device__ int g_chi[NROWS];
__device__ float g_clv[NROWS]; __device__ int g_cli[NROWS];
__device__ int   g_inst[2 * NI];

// monotone float <-> uint key (total order matches float compare)
__device__ __forceinline__ unsigned monoKey(float f) {
    unsigned u = __float_as_uint(f);
    return (u & 0x80000000u) ? ~u : (u | 0x80000000u);
}
__device__ __forceinline__ float monoDecode(unsigned k) {
    unsigned u = (k & 0x80000000u) ? (k & 0x7FFFFFFFu) : ~k;
    return __uint_as_float(u);
}

// ---------------- init ----------------
__global__ void init_kernel() {
    int i = blockIdx.x * blockDim.x + threadIdx.x; // 64*256 = 16384 threads
    if (i < 16384) g_hist[i] = 0;
    if (i < 2 * L_DIM) g_bag[i] = 0.f;
    if (i < 2) { g_Z[i] = 0.f; g_maxkey[i] = 0u; }
    if (i == 0) { g_nhi = 0; g_nlo = 0; }
}

// ---------------- SGEMM NT: C[M,Nc] = act(A[M,K] * B[Nc,K]^T + bias) ----------------
// ACT: 0 = relu, 1 = tanh, 2 = prev * sigmoid
template<int ACT>
__global__ __launch_bounds__(256)
void sgemm_nt(const float* __restrict__ A, const float* __restrict__ B,
              const float* __restrict__ bias, float* __restrict__ C,
              int Ncols, int K, const float* __restrict__ prev)
{
    __shared__ __align__(16) float As[16][128];
    __shared__ __align__(16) float Bs[16][128];
    const int bm = blockIdx.x, bn = blockIdx.y;
    const int tid = threadIdx.x;
    const int tx = tid & 15, ty = tid >> 4;

    float acc[8][8];
#pragma unroll
    for (int i = 0; i < 8; i++)
#pragma unroll
        for (int j = 0; j < 8; j++) acc[i][j] = 0.f;

    const float* Ablk = A + (size_t)bm * 128 * K;
    const float* Bblk = B + (size_t)bn * 128 * K;

    for (int k0 = 0; k0 < K; k0 += 16) {
#pragma unroll
        for (int l = 0; l < 2; l++) {
            int f4  = tid + l * 256;        // 0..511
            int row = f4 >> 2;
            int c4  = (f4 & 3) * 4;
            float4 va = *(const float4*)(Ablk + (size_t)row * K + k0 + c4);
            As[c4 + 0][row] = va.x; As[c4 + 1][row] = va.y;
            As[c4 + 2][row] = va.z; As[c4 + 3][row] = va.w;
            float4 vb = *(const float4*)(Bblk + (size_t)row * K + k0 + c4);
            Bs[c4 + 0][row] = vb.x; Bs[c4 + 1][row] = vb.y;
            Bs[c4 + 2][row] = vb.z; Bs[c4 + 3][row] = vb.w;
        }
        __syncthreads();
#pragma unroll
        for (int kk = 0; kk < 16; kk++) {
            float4 a0 = *(const float4*)&As[kk][ty * 8];
            float4 a1 = *(const float4*)&As[kk][ty * 8 + 4];
            float4 b0 = *(const float4*)&Bs[kk][tx * 8];
            float4 b1 = *(const float4*)&Bs[kk][tx * 8 + 4];
            float ra[8] = {a0.x,a0.y,a0.z,a0.w,a1.x,a1.y,a1.z,a1.w};
            float rb[8] = {b0.x,b0.y,b0.z,b0.w,b1.x,b1.y,b1.z,b1.w};
#pragma unroll
            for (int i = 0; i < 8; i++)
#pragma unroll
                for (int j = 0; j < 8; j++)
                    acc[i][j] = fmaf(ra[i], rb[j], acc[i][j]);
        }
        __syncthreads();
    }

    const int row0 = bm * 128 + ty * 8;
    const int col0 = bn * 128 + tx * 8;
    float bvals[8];
#pragma unroll
    for (int j = 0; j < 8; j++) bvals[j] = bias[col0 + j];

#pragma unroll
    for (int i = 0; i < 8; i++) {
        float* Crow = C + (size_t)(row0 + i) * Ncols + col0;
#pragma unroll
        for (int j = 0; j < 8; j++) {
            float v = acc[i][j] + bvals[j];
            if (ACT == 0) {
                v = fmaxf(v, 0.f);
            } else if (ACT == 1) {
                v = tanhf(v);
            } else {
                float pv = prev[(size_t)(row0 + i) * Ncols + col0 + j];
                v = pv * (1.f / (1.f + expf(-v)));
            }
            Crow[j] = v;
        }
    }
}

// ---------------- attention scores A = g @ Wa^T + ba, write raw_attention, track max ----------------
__global__ void attn_kernel(const float* __restrict__ Wa, const float* __restrict__ ba,
                            float* __restrict__ out_att)
{
    __shared__ unsigned sk0, sk1;
    if (threadIdx.x == 0) { sk0 = 0u; sk1 = 0u; }
    __syncthreads();

    int warp = (blockIdx.x * blockDim.x + threadIdx.x) >> 5;
    int lane = threadIdx.x & 31;
    if (warp < NROWS) {
        const float* gr = g_g + (size_t)warp * D_DIM;
        float s0 = 0.f, s1 = 0.f;
#pragma unroll
        for (int k = lane; k < D_DIM; k += 32) {
            float v = gr[k];
            s0 = fmaf(v, Wa[k], s0);
            s1 = fmaf(v, Wa[D_DIM + k], s1);
        }
#pragma unroll
        for (int o = 16; o; o >>= 1) {
            s0 += __shfl_xor_sync(0xFFFFFFFFu, s0, o);
            s1 += __shfl_xor_sync(0xFFFFFFFFu, s1, o);
        }
        if (lane == 0) {
            s0 += ba[0]; s1 += ba[1];
            g_A[2 * warp] = s0; g_A[2 * warp + 1] = s1;
            out_att[warp] = s0;
            out_att[NROWS + warp] = s1;
            atomicMax(&sk0, monoKey(s0));
            atomicMax(&sk1, monoKey(s1));
        }
    }
    __syncthreads();
    if (threadIdx.x == 0) {
        atomicMax(&g_maxkey[0], sk0);
        atomicMax(&g_maxkey[1], sk1);
    }
}

// ---------------- fused softmax-weighted bag accumulation + partition sums ----------------
__global__ void bag_kernel()
{
    const int t = threadIdx.x;                 // 256 threads
    const int rowsPerBlock = NROWS / gridDim.x;
    const int r0 = blockIdx.x * rowsPerBlock;
    const float m0 = monoDecode(g_maxkey[0]);
    const float m1 = monoDecode(g_maxkey[1]);

    float a00 = 0.f, a01 = 0.f, a10 = 0.f, a11 = 0.f;
    float z0 = 0.f, z1 = 0.f;
    for (int r = r0; r < r0 + rowsPerBlock; r++) {
        float w0 = expf(g_A[2 * r]     - m0);
        float w1 = expf(g_A[2 * r + 1] - m1);
        const float* hr = g_h + (size_t)r * L_DIM;
        float v0 = hr[t], v1 = hr[t + 256];
        a00 = fmaf(w0, v0, a00); a01 = fmaf(w0, v1, a01);
        a10 = fmaf(w1, v0, a10); a11 = fmaf(w1, v1, a11);
        if (t == 0) { z0 += w0; z1 += w1; }
    }
    atomicAdd(&g_bag[t], a00);
    atomicAdd(&g_bag[t + 256], a01);
    atomicAdd(&g_bag[L_DIM + t], a10);
    atomicAdd(&g_bag[L_DIM + t + 256], a11);
    if (t == 0) { atomicAdd(&g_Z[0], z0); atomicAdd(&g_Z[1], z1); }
}

// ---------------- top-k machinery: histogram, threshold scan, compact, select ----------------
__global__ void hist_kernel(const int* __restrict__ labelPtr)
{
    int lab = labelPtr ? *labelPtr : 0;
    for (int i = blockIdx.x * blockDim.x + threadIdx.x; i < NROWS; i += gridDim.x * blockDim.x) {
        unsigned key = monoKey(g_A[2 * i + lab]) >> 18; // 14 bits
        atomicAdd(&g_hist[key], 1);
    }
}

__global__ void scan_kernel()
{
    __shared__ int csum[256];
    int t = threadIdx.x;
    int s = 0;
    for (int b = t * 64; b < t * 64 + 64; b++) s += g_hist[b];
    csum[t] = s;
    __syncthreads();
    if (t == 0) {
        int cum = 0, binhi = 0;
        for (int c = 255; c >= 0; c--) {
            if (cum + csum[c] >= NI) {
                for (int b = c * 64 + 63; b >= c * 64; b--) {
                    cum += g_hist[b];
                    if (cum >= NI) { binhi = b; break; }
                }
                break;
            }
            cum += csum[c];
        }
        g_binhi = binhi;
        cum = 0; int binlo = 16383;
        for (int c = 0; c < 256; c++) {
            if (cum + csum[c] >= NI) {
                for (int b = c * 64; b < c * 64 + 64; b++) {
                    cum += g_hist[b];
                    if (cum >= NI) { binlo = b; break; }
                }
                break;
            }
            cum += csum[c];
        }
        g_binlo = binlo;
        g_nhi = 0; g_nlo = 0;
    }
}

__global__ void cand_kernel(const int* __restrict__ labelPtr)
{
    int lab = labelPtr ? *labelPtr : 0;
    int binhi = g_binhi, binlo = g_binlo;
    for (int i = blockIdx.x * blockDim.x + threadIdx.x; i < NROWS; i += gridDim.x * blockDim.x) {
        float v = g_A[2 * i + lab];
        unsigned key = monoKey(v) >> 18;
        if ((int)key >= binhi) {
            int p = atomicAdd(&g_nhi, 1);
            g_chv[p] = v; g_chi[p] = i;
        }
        if ((int)key <= binlo) {
            int p = atomicAdd(&g_nlo, 1);
            g_clv[p] = v; g_cli[p] = i;
        }
    }
}

__global__ void select_kernel()
{
    __shared__ float sv[256];
    __shared__ int   si[256];
    __shared__ int   sp[256];
    const int t = threadIdx.x;
    const float NEG_INF = __int_as_float(0xFF800000);
    const float POS_INF = __int_as_float(0x7F800000);
    int nhi = g_nhi, nlo = g_nlo;

    // top-50 (max, tie -> lower index)
    for (int it = 0; it < NI; it++) {
        float bv = NEG_INF; int bi = 0x7FFFFFFF; int bp = -1;
        for (int p = t; p < nhi; p += 256) {
            float v = g_chv[p]; int idx = g_chi[p];
            if (v > bv || (v == bv && idx < bi)) { bv = v; bi = idx; bp = p; }
        }
        sv[t] = bv; si[t] = bi; sp[t] = bp;
        __syncthreads();
        for (int s = 128; s; s >>= 1) {
            if (t < s) {
                if (sv[t + s] > sv[t] || (sv[t + s] == sv[t] && si[t + s] < si[t])) {
                    sv[t] = sv[t + s]; si[t] = si[t + s]; sp[t] = sp[t + s];
                }
            }
            __syncthreads();
        }
        if (t == 0) { g_inst[it] = si[0]; g_chv[sp[0]] = NEG_INF; }
        __syncthreads();
    }
    // bottom-50 (min, tie -> lower index)
    for (int it = 0; it < NI; it++) {
        float bv = POS_INF; int bi = 0x7FFFFFFF; int bp = -1;
        for (int p = t; p < nlo; p += 256) {
            float v = g_clv[p]; int idx = g_cli[p];
            if (v < bv || (v == bv && idx < bi)) { bv = v; bi = idx; bp = p; }
        }
        sv[t] = bv; si[t] = bi; sp[t] = bp;
        __syncthreads();
        for (int s = 128; s; s >>= 1) {
            if (t < s) {
                if (sv[t + s] < sv[t] || (sv[t + s] == sv[t] && si[t + s] < si[t])) {
                    sv[t] = sv[t + s]; si[t] = si[t + s]; sp[t] = sp[t + s];
                }
            }
            __syncthreads();
        }
        if (t == 0) { g_inst[NI + it] = si[0]; g_clv[sp[0]] = POS_INF; }
        __syncthreads();
    }
}

// ---------------- instance loss (SmoothTop1SVM, tau=alpha=1) ----------------
__global__ void loss_kernel(const int* __restrict__ labelPtr,
                            const float* __restrict__ Winst, const float* __restrict__ binst,
                            float* __restrict__ out_loss)
{
    __shared__ float sl[4];
    int lab = labelPtr ? *labelPtr : 0;
    const float* W0 = Winst + ((size_t)lab * 2 + 0) * L_DIM;
    const float* W1 = Winst + ((size_t)lab * 2 + 1) * L_DIM;
    float b0 = binst[lab * 2], b1 = binst[lab * 2 + 1];

    int warp = threadIdx.x >> 5, lane = threadIdx.x & 31;
    float lsum = 0.f;
    for (int r = warp; r < 2 * NI; r += 4) {
        const float* hr = g_h + (size_t)g_inst[r] * L_DIM;
        float s0 = 0.f, s1 = 0.f;
        for (int k = lane; k < L_DIM; k += 32) {
            float v = hr[k];
            s0 = fmaf(v, W0[k], s0);
            s1 = fmaf(v, W1[k], s1);
        }
#pragma unroll
        for (int o = 16; o; o >>= 1) {
            s0 += __shfl_xor_sync(0xFFFFFFFFu, s0, o);
            s1 += __shfl_xor_sync(0xFFFFFFFFu, s1, o);
        }
        if (lane == 0) {
            float l0 = s0 + b0, l1 = s1 + b1;
            int tgt = (r < NI) ? 1 : 0;
            float u0 = l0 + ((tgt != 0) ? 1.f : 0.f);
            float u1 = l1 + ((tgt != 1) ? 1.f : 0.f);
            float m = fmaxf(u0, u1);
            float lse = m + logf(expf(u0 - m) + expf(u1 - m));
            float sy = (tgt == 0) ? l0 : l1;
            lsum += lse - sy;
        }
    }
    if (lane == 0) sl[warp] = lsum;
    __syncthreads();
    if (threadIdx.x == 0)
        *out_loss = (sl[0] + sl[1] + sl[2] + sl[3]) * (1.f / (2 * NI));
}

// ---------------- bag logits + softmax ----------------
__global__ void final_kernel(const float* __restrict__ Wbag, const float* __restrict__ bbag,
                             float* __restrict__ out)
{
    __shared__ float lg[2];
    int warp = threadIdx.x >> 5, lane = threadIdx.x & 31;
    if (warp < 2) {
        float s = 0.f;
        for (int k = lane; k < L_DIM; k += 32)
            s = fmaf(g_bag[warp * L_DIM + k], Wbag[warp * L_DIM + k], s);
#pragma unroll
        for (int o = 16; o; o >>= 1) s += __shfl_xor_sync(0xFFFFFFFFu, s, o);
        if (lane == 0) lg[warp] = s / g_Z[warp] + bbag[warp];
    }
    __syncthreads();
    if (threadIdx.x == 0) {
        float l0 = lg[0], l1 = lg[1];
        out[0] = l0; out[1] = l1;
        float m = fmaxf(l0, l1);
        float e0 = expf(l0 - m), e1 = expf(l1 - m);
        float s = e0 + e1;
        out[2] = e0 / s; out[3] = e1 / s;
    }
}

// ---------------- launch ----------------
extern "C" void kernel_launch(void* const* d_in, const int* in_sizes, int n_in,
                              void* d_out, int out_size)
{
    const int off = (n_in >= 14) ? 1 : 0;
    const float* x     = (const float*)d_in[0];
    const int*   label = (n_in >= 14) ? (const int*)d_in[1] : nullptr;
    const float* Wc    = (const float*)d_in[1 + off];
    const float* bc    = (const float*)d_in[2 + off];
    const float* Wv    = (const float*)d_in[3 + off];
    const float* bv    = (const float*)d_in[4 + off];
    const float* Wu    = (const float*)d_in[5 + off];
    const float* bu    = (const float*)d_in[6 + off];
    const float* Wa    = (const float*)d_in[7 + off];
    const float* ba    = (const float*)d_in[8 + off];
    const float* Winst = (const float*)d_in[9 + off];
    const float* binst = (const float*)d_in[10 + off];
    const float* Wbag  = (const float*)d_in[11 + off];
    const float* bbag  = (const float*)d_in[12 + off];
    float* out = (float*)d_out;

    void* p;
    cudaGetSymbolAddress(&p, g_h); float* h = (float*)p;
    cudaGetSymbolAddress(&p, g_g); float* g = (float*)p;

    init_kernel<<<64, 256>>>();

    // h = relu(x @ Wc^T + bc)   [131072, 512]
    sgemm_nt<0><<<dim3(NROWS / 128, L_DIM / 128), 256>>>(x, Wc, bc, h, L_DIM, E_DIM, nullptr);
    // a = tanh(h @ Wv^T + bv)   [131072, 256] -> g
    sgemm_nt<1><<<dim3(NROWS / 128, D_DIM / 128), 256>>>(h, Wv, bv, g, D_DIM, L_DIM, nullptr);
    // g = a * sigmoid(h @ Wu^T + bu)  (in place over g)
    sgemm_nt<2><<<dim3(NROWS / 128, D_DIM / 128), 256>>>(h, Wu, bu, g, D_DIM, L_DIM, g);

    // A = g @ Wa^T + ba; write raw_attention to out+4; per-class max
    attn_kernel<<<NROWS / 8, 256>>>(Wa, ba, out + 4);

    // softmax denominators + unnormalized bag_rep
    bag_kernel<<<512, 256>>>();

    // top-50 / bottom-50 of A[:, label]
    hist_kernel<<<NROWS / 256, 256>>>(label);
    scan_kernel<<<1, 256>>>();
    cand_kernel<<<NROWS / 256, 256>>>(label);
    select_kernel<<<1, 256>>>();

    // instance loss -> last output element
    loss_kernel<<<1, 128>>>(label, Winst, binst, out + 4 + 2 * NROWS);

    // bag logits + softmax -> out[0..3]
    final_kernel<<<1, 64>>>(Wbag, bbag, out);
}

// round 3
// speedup vs baseline: 2.4473x; 2.4473x over previous
#include <cuda_runtime.h>
#include <cuda_bf16.h>
#include <math.h>
#include <stdint.h>

#define NROWS 131072
#define E_DIM 1024
#define L_DIM 512
#define D_DIM 256
#define NI    50

// ---------------- device scratch (allocation-free rule) ----------------
__device__ __nv_bfloat16 g_xhi[(size_t)NROWS * E_DIM];
__device__ __nv_bfloat16 g_xlo[(size_t)NROWS * E_DIM];
__device__ __nv_bfloat16 g_hhi[(size_t)NROWS * L_DIM];
__device__ __nv_bfloat16 g_hlo[(size_t)NROWS * L_DIM];
__device__ __nv_bfloat16 g_wchi[L_DIM * E_DIM];
__device__ __nv_bfloat16 g_wclo[L_DIM * E_DIM];
__device__ __nv_bfloat16 g_wthi[2 * D_DIM * L_DIM];
__device__ __nv_bfloat16 g_wtlo[2 * D_DIM * L_DIM];
__device__ float g_bcat[2 * D_DIM];
__device__ float g_g[(size_t)NROWS * D_DIM];
__device__ float g_A[(size_t)NROWS * 2];
__device__ int      g_hist[16384];
__device__ unsigned g_maxkey[2];
__device__ float    g_Z[2];
__device__ float    g_bag[2 * L_DIM];
__device__ int      g_binhi, g_binlo;
__device__ int      g_nhi, g_nlo;
__device__ float g_chv[NROWS]; __device__ int g_chi[NROWS];
__device__ float g_clv[NROWS]; __device__ int g_cli[NROWS];
__device__ int   g_inst[2 * NI];

// ---------------- PTX helpers ----------------
__device__ __forceinline__ uint32_t smem_u32(const void* p) {
    uint32_t a;
    asm("{ .reg .u64 t; cvta.to.shared.u64 t, %1; cvt.u32.u64 %0, t; }" : "=r"(a) : "l"(p));
    return a;
}
__device__ __forceinline__ void cp16(uint32_t s, const void* g) {
    asm volatile("cp.async.cg.shared.global [%0], [%1], 16;" :: "r"(s), "l"(g));
}
__device__ __forceinline__ void ldsm4(uint32_t* r, uint32_t addr) {
    asm volatile("ldmatrix.sync.aligned.m8n8.x4.shared.b16 {%0,%1,%2,%3}, [%4];"
                 : "=r"(r[0]), "=r"(r[1]), "=r"(r[2]), "=r"(r[3]) : "r"(addr));
}
__device__ __forceinline__ void mma16816(float* c, const uint32_t* a, const uint32_t* b) {
    asm volatile(
        "mma.sync.aligned.m16n8k16.row.col.f32.bf16.bf16.f32 "
        "{%0,%1,%2,%3}, {%4,%5,%6,%7}, {%8,%9}, {%0,%1,%2,%3};"
        : "+f"(c[0]), "+f"(c[1]), "+f"(c[2]), "+f"(c[3])
        : "r"(a[0]), "r"(a[1]), "r"(a[2]), "r"(a[3]), "r"(b[0]), "r"(b[1]));
}

// monotone float <-> uint key
__device__ __forceinline__ unsigned monoKey(float f) {
    unsigned u = __float_as_uint(f);
    return (u & 0x80000000u) ? ~u : (u | 0x80000000u);
}
__device__ __forceinline__ float monoDecode(unsigned k) {
    unsigned u = (k & 0x80000000u) ? (k & 0x7FFFFFFFu) : ~k;
    return __uint_as_float(u);
}

// ---------------- init ----------------
__global__ void init_kernel() {
    int i = blockIdx.x * blockDim.x + threadIdx.x;
    if (i < 16384) g_hist[i] = 0;
    if (i < 2 * L_DIM) g_bag[i] = 0.f;
    if (i < 2) { g_Z[i] = 0.f; g_maxkey[i] = 0u; }
    if (i == 0) { g_nhi = 0; g_nlo = 0; }
}

// ---------------- fp32 -> bf16 hi/lo split ----------------
__global__ void split_kernel(const float4* __restrict__ in, __nv_bfloat162* __restrict__ hi,
                             __nv_bfloat162* __restrict__ lo, int n4) {
    int i = blockIdx.x * blockDim.x + threadIdx.x;
    int stride = gridDim.x * blockDim.x;
    for (; i < n4; i += stride) {
        float4 v = in[i];
        __nv_bfloat16 h0 = __float2bfloat16(v.x), h1 = __float2bfloat16(v.y);
        __nv_bfloat16 h2 = __float2bfloat16(v.z), h3 = __float2bfloat16(v.w);
        hi[2 * i]     = __halves2bfloat162(h0, h1);
        hi[2 * i + 1] = __halves2bfloat162(h2, h3);
        lo[2 * i]     = __halves2bfloat162(__float2bfloat16(v.x - __bfloat162float(h0)),
                                           __float2bfloat16(v.y - __bfloat162float(h1)));
        lo[2 * i + 1] = __halves2bfloat162(__float2bfloat16(v.z - __bfloat162float(h2)),
                                           __float2bfloat16(v.w - __bfloat162float(h3)));
    }
}

// build interleaved Wcat (row 2j = Wv[j], row 2j+1 = Wu[j]) split into hi/lo + bcat
__global__ void cat_kernel(const float* __restrict__ Wv, const float* __restrict__ Wu,
                           const float* __restrict__ bv, const float* __restrict__ bu,
                           __nv_bfloat16* __restrict__ whi, __nv_bfloat16* __restrict__ wlo,
                           float* __restrict__ bcat) {
    int i = blockIdx.x * blockDim.x + threadIdx.x;
    if (i < 2 * D_DIM * L_DIM) {
        int row = i >> 9, k = i & 511;
        int j = row >> 1, e = row & 1;
        float v = e ? Wu[j * L_DIM + k] : Wv[j * L_DIM + k];
        __nv_bfloat16 h = __float2bfloat16(v);
        whi[i] = h;
        wlo[i] = __float2bfloat16(v - __bfloat162float(h));
    }
    if (i < 2 * D_DIM) {
        int j = i >> 1, e = i & 1;
        bcat[i] = e ? bu[j] : bv[j];
    }
}

// ---------------- HMMA split-fp32 GEMM ----------------
// C[M,512] = A[M,K] @ B[512,K]^T using bf16 hi/lo pairs, fp32 accumulate.
// D = Ahi*Bhi + Ahi*Blo + Alo*Bhi.
// EPI=0: v = relu(acc + bias[col]); write OutHi/OutLo bf16 [M,512]
// EPI=1: cols interleaved; g[r, col/2] = tanh(v_even)*sigmoid(v_odd) fp32 [M,256]
//
// CTA tile 128x128, BK=64, 8 warps (warp tile 32x64), 3-stage cp.async pipeline.
#define TILE_BYTES 16384            // 128 rows x 64 bf16 (swizzled 128B rows)
#define STAGE_BYTES (4 * TILE_BYTES) // Ahi, Alo, Bhi, Blo
#define NSTAGE 3
#define GSMEM (NSTAGE * STAGE_BYTES)

template<int EPI>
__global__ __launch_bounds__(256, 1)
void gemm_hmma(const __nv_bfloat16* __restrict__ Ahi, const __nv_bfloat16* __restrict__ Alo,
               const __nv_bfloat16* __restrict__ Bhi, const __nv_bfloat16* __restrict__ Blo,
               const float* __restrict__ bias,
               __nv_bfloat16* __restrict__ OutHi, __nv_bfloat16* __restrict__ OutLo,
               float* __restrict__ OutF,
               int K, int NC)
{
    extern __shared__ __align__(1024) unsigned char dsm[];
    const int tid  = threadIdx.x;
    const int bn   = blockIdx.x;          // n fastest -> A-tile L2 reuse
    const int bm   = blockIdx.y;
    const int wid  = tid >> 5, lane = tid & 31;
    const int wm   = wid & 3, wn = wid >> 2;  // warp grid 4(M) x 2(N)
    const int m0   = bm * 128, n0 = bn * 128;
    const uint32_t sb = smem_u32(dsm);

    // ---- cp.async stage loader ----
    auto loadTile = [&](uint32_t dst, const __nv_bfloat16* p, int gr0, int k0) {
#pragma unroll
        for (int it = 0; it < 4; it++) {
            int q = tid + it * 256;          // 0..1023
            int row = q >> 3;
            int inner = (q & 7) << 4;        // 0..112 step 16
            uint32_t off = (uint32_t)(row * 128 + (inner ^ ((row & 7) << 4)));
            cp16(dst + off, (const char*)p + ((size_t)(gr0 + row) * K + k0) * 2 + inner);
        }
    };
    auto loadStage = [&](int s, int k0) {
        uint32_t st = sb + s * STAGE_BYTES;
        loadTile(st,                  Ahi, m0, k0);
        loadTile(st + TILE_BYTES,     Alo, m0, k0);
        loadTile(st + 2 * TILE_BYTES, Bhi, n0, k0);
        loadTile(st + 3 * TILE_BYTES, Blo, n0, k0);
        asm volatile("cp.async.commit_group;" ::: "memory");
    };

    // ---- per-lane ldmatrix address pieces ----
    // A (16x16 frag): rows m = wm*32 + mi*16 + (lane&15); k half = ((lane>>4)&1)*16B
    const int aRow = wm * 32 + (lane & 15);
    const uint32_t aK  = ((lane >> 4) & 1) * 16;
    const uint32_t aXr = (uint32_t)((aRow & 7) << 4);
    // B (two n8 frags per x4): rows n = wn*64 + nj*16 + (lane&7) + ((lane>>4)&1)*8
    const int bRow = wn * 64 + (lane & 7) + (((lane >> 4) & 1) << 3);
    const uint32_t bK  = ((lane >> 3) & 1) * 16;
    const uint32_t bXr = (uint32_t)((bRow & 7) << 4);

    float acc[2][8][4];
#pragma unroll
    for (int mi = 0; mi < 2; mi++)
#pragma unroll
        for (int ni = 0; ni < 8; ni++)
#pragma unroll
            for (int e = 0; e < 4; e++) acc[mi][ni][e] = 0.f;

    loadStage(0, 0);
    loadStage(1, 64);

    for (int i = 0; i < NC; i++) {
        const int s = i % NSTAGE;
        if (i + 2 < NC) {
            loadStage((i + 2) % NSTAGE, (i + 2) * 64);
            asm volatile("cp.async.wait_group 2;" ::: "memory");
        } else if (i + 1 < NC) {
            asm volatile("cp.async.wait_group 1;" ::: "memory");
        } else {
            asm volatile("cp.async.wait_group 0;" ::: "memory");
        }
        __syncthreads();

        const uint32_t st  = sb + s * STAGE_BYTES;
        const uint32_t sAh = st, sAl = st + TILE_BYTES;
        const uint32_t sBh = st + 2 * TILE_BYTES, sBl = st + 3 * TILE_BYTES;

#pragma unroll
        for (int ks = 0; ks < 4; ks++) {
            const uint32_t ak = (uint32_t)(ks * 32) + aK;
            const uint32_t bk = (uint32_t)(ks * 32) + bK;
            uint32_t ah[2][4], al[2][4], bh[4][4], bl[4][4];
#pragma unroll
            for (int mi = 0; mi < 2; mi++) {
                uint32_t ro = (uint32_t)((aRow + mi * 16) * 128) + (ak ^ aXr);
                ldsm4(ah[mi], sAh + ro);
                ldsm4(al[mi], sAl + ro);
            }
#pragma unroll
            for (int nj = 0; nj < 4; nj++) {
                uint32_t ro = (uint32_t)((bRow + nj * 16) * 128) + (bk ^ bXr);
                ldsm4(bh[nj], sBh + ro);
                ldsm4(bl[nj], sBl + ro);
            }
#pragma unroll
            for (int mi = 0; mi < 2; mi++) {
#pragma unroll
                for (int nj = 0; nj < 4; nj++) {
                    mma16816(acc[mi][2 * nj],     ah[mi], &bh[nj][0]);
                    mma16816(acc[mi][2 * nj + 1], ah[mi], &bh[nj][2]);
                    mma16816(acc[mi][2 * nj],     ah[mi], &bl[nj][0]);
                    mma16816(acc[mi][2 * nj + 1], ah[mi], &bl[nj][2]);
                    mma16816(acc[mi][2 * nj],     al[mi], &bh[nj][0]);
                    mma16816(acc[mi][2 * nj + 1], al[mi], &bh[nj][2]);
                }
            }
        }
        __syncthreads();   // protect stage s before it is refilled next iteration
    }

    // ---- epilogue: fragments straight to global ----
    const int rBase = m0 + wm * 32 + (lane >> 2);
    const int cBase = n0 + wn * 64 + 2 * (lane & 3);
#pragma unroll
    for (int mi = 0; mi < 2; mi++) {
#pragma unroll
        for (int ni = 0; ni < 8; ni++) {
            const int c = cBase + ni * 8;
            const float b0 = bias[c], b1 = bias[c + 1];
#pragma unroll
            for (int half = 0; half < 2; half++) {
                const int r = rBase + mi * 16 + half * 8;
                float v0 = acc[mi][ni][2 * half]     + b0;
                float v1 = acc[mi][ni][2 * half + 1] + b1;
                if (EPI == 0) {
                    v0 = fmaxf(v0, 0.f); v1 = fmaxf(v1, 0.f);
                    __nv_bfloat16 h0 = __float2bfloat16(v0), h1 = __float2bfloat16(v1);
                    size_t o = ((size_t)r * 512 + c) >> 1;
                    ((__nv_bfloat162*)OutHi)[o] = __halves2bfloat162(h0, h1);
                    ((__nv_bfloat162*)OutLo)[o] = __halves2bfloat162(
                        __float2bfloat16(v0 - __bfloat162float(h0)),
                        __float2bfloat16(v1 - __bfloat162float(h1)));
                } else {
                    OutF[(size_t)r * 256 + (c >> 1)] = tanhf(v0) / (1.f + expf(-v1));
                }
            }
        }
    }
}

// ---------------- attention scores A = g @ Wa^T + ba ----------------
__global__ void attn_kernel(const float* __restrict__ Wa, const float* __restrict__ ba,
                            float* __restrict__ out_att)
{
    __shared__ unsigned sk0, sk1;
    if (threadIdx.x == 0) { sk0 = 0u; sk1 = 0u; }
    __syncthreads();

    int warp = (blockIdx.x * blockDim.x + threadIdx.x) >> 5;
    int lane = threadIdx.x & 31;
    if (warp < NROWS) {
        const float* gr = g_g + (size_t)warp * D_DIM;
        float s0 = 0.f, s1 = 0.f;
#pragma unroll
        for (int k = lane; k < D_DIM; k += 32) {
            float v = gr[k];
            s0 = fmaf(v, Wa[k], s0);
            s1 = fmaf(v, Wa[D_DIM + k], s1);
        }
#pragma unroll
        for (int o = 16; o; o >>= 1) {
            s0 += __shfl_xor_sync(0xFFFFFFFFu, s0, o);
            s1 += __shfl_xor_sync(0xFFFFFFFFu, s1, o);
        }
        if (lane == 0) {
            s0 += ba[0]; s1 += ba[1];
            g_A[2 * warp] = s0; g_A[2 * warp + 1] = s1;
            out_att[warp] = s0;
            out_att[NROWS + warp] = s1;
            atomicMax(&sk0, monoKey(s0));
            atomicMax(&sk1, monoKey(s1));
        }
    }
    __syncthreads();
    if (threadIdx.x == 0) {
        atomicMax(&g_maxkey[0], sk0);
        atomicMax(&g_maxkey[1], sk1);
    }
}

// ---------------- fused softmax-weighted bag accumulation (h = hi+lo) ----------------
__global__ void bag_kernel()
{
    const int t = threadIdx.x;                 // 256 threads -> col pair (2t, 2t+1)
    const int rowsPerBlock = NROWS / gridDim.x;
    const int r0 = blockIdx.x * rowsPerBlock;
    const float m0 = monoDecode(g_maxkey[0]);
    const float m1 = monoDecode(g_maxkey[1]);

    float a00 = 0.f, a01 = 0.f, a10 = 0.f, a11 = 0.f;
    float z0 = 0.f, z1 = 0.f;
    for (int r = r0; r < r0 + rowsPerBlock; r++) {
        float w0 = expf(g_A[2 * r]     - m0);
        float w1 = expf(g_A[2 * r + 1] - m1);
        const __nv_bfloat162* hh = (const __nv_bfloat162*)(g_hhi + (size_t)r * L_DIM);
        const __nv_bfloat162* hl = (const __nv_bfloat162*)(g_hlo + (size_t)r * L_DIM);
        __nv_bfloat162 a2 = hh[t], b2 = hl[t];
        float v0 = __low2float(a2)  + __low2float(b2);
        float v1 = __high2float(a2) + __high2float(b2);
        a00 = fmaf(w0, v0, a00); a01 = fmaf(w0, v1, a01);
        a10 = fmaf(w1, v0, a10); a11 = fmaf(w1, v1, a11);
        if (t == 0) { z0 += w0; z1 += w1; }
    }
    atomicAdd(&g_bag[2 * t], a00);
    atomicAdd(&g_bag[2 * t + 1], a01);
    atomicAdd(&g_bag[L_DIM + 2 * t], a10);
    atomicAdd(&g_bag[L_DIM + 2 * t + 1], a11);
    if (t == 0) { atomicAdd(&g_Z[0], z0); atomicAdd(&g_Z[1], z1); }
}

// ---------------- top-k machinery ----------------
__global__ void hist_kernel(const int* __restrict__ labelPtr)
{
    int lab = labelPtr ? *labelPtr : 0;
    for (int i = blockIdx.x * blockDim.x + threadIdx.x; i < NROWS; i += gridDim.x * blockDim.x) {
        unsigned key = monoKey(g_A[2 * i + lab]) >> 18;
        atomicAdd(&g_hist[key], 1);
    }
}

__global__ void scan_kernel()
{
    __shared__ int csum[256];
    int t = threadIdx.x;
    int s = 0;
    for (int b = t * 64; b < t * 64 + 64; b++) s += g_hist[b];
    csum[t] = s;
    __syncthreads();
    if (t == 0) {
        int cum = 0, binhi = 0;
        for (int c = 255; c >= 0; c--) {
            if (cum + csum[c] >= NI) {
                for (int b = c * 64 + 63; b >= c * 64; b--) {
                    cum += g_hist[b];
                    if (cum >= NI) { binhi = b; break; }
                }
                break;
            }
            cum += csum[c];
        }
        g_binhi = binhi;
        cum = 0; int binlo = 16383;
        for (int c = 0; c < 256; c++) {
            if (cum + csum[c] >= NI) {
                for (int b = c * 64; b < c * 64 + 64; b++) {
                    cum += g_hist[b];
                    if (cum >= NI) { binlo = b; break; }
                }
                break;
            }
            cum += csum[c];
        }
        g_binlo = binlo;
        g_nhi = 0; g_nlo = 0;
    }
}

__global__ void cand_kernel(const int* __restrict__ labelPtr)
{
    int lab = labelPtr ? *labelPtr : 0;
    int binhi = g_binhi, binlo = g_binlo;
    for (int i = blockIdx.x * blockDim.x + threadIdx.x; i < NROWS; i += gridDim.x * blockDim.x) {
        float v = g_A[2 * i + lab];
        unsigned key = monoKey(v) >> 18;
        if ((int)key >= binhi) {
            int p = atomicAdd(&g_nhi, 1);
            g_chv[p] = v; g_chi[p] = i;
        }
        if ((int)key <= binlo) {
            int p = atomicAdd(&g_nlo, 1);
            g_clv[p] = v; g_cli[p] = i;
        }
    }
}

__global__ void select_kernel()
{
    __shared__ float sv[256];
    __shared__ int   si[256];
    __shared__ int   sp[256];
    const int t = threadIdx.x;
    const float NEG_INF = __int_as_float(0xFF800000);
    const float POS_INF = __int_as_float(0x7F800000);
    int nhi = g_nhi, nlo = g_nlo;

    for (int it = 0; it < NI; it++) {
        float bv = NEG_INF; int bi = 0x7FFFFFFF; int bp = -1;
        for (int p = t; p < nhi; p += 256) {
            float v = g_chv[p]; int idx = g_chi[p];
            if (v > bv || (v == bv && idx < bi)) { bv = v; bi = idx; bp = p; }
        }
        sv[t] = bv; si[t] = bi; sp[t] = bp;
        __syncthreads();
        for (int s = 128; s; s >>= 1) {
            if (t < s) {
                if (sv[t + s] > sv[t] || (sv[t + s] == sv[t] && si[t + s] < si[t])) {
                    sv[t] = sv[t + s]; si[t] = si[t + s]; sp[t] = sp[t + s];
                }
            }
            __syncthreads();
        }
        if (t == 0) { g_inst[it] = si[0]; g_chv[sp[0]] = NEG_INF; }
        __syncthreads();
    }
    for (int it = 0; it < NI; it++) {
        float bv = POS_INF; int bi = 0x7FFFFFFF; int bp = -1;
        for (int p = t; p < nlo; p += 256) {
            float v = g_clv[p]; int idx = g_cli[p];
            if (v < bv || (v == bv && idx < bi)) { bv = v; bi = idx; bp = p; }
        }
        sv[t] = bv; si[t] = bi; sp[t] = bp;
        __syncthreads();
        for (int s = 128; s; s >>= 1) {
            if (t < s) {
                if (sv[t + s] < sv[t] || (sv[t + s] == sv[t] && si[t + s] < si[t])) {
                    sv[t] = sv[t + s]; si[t] = si[t + s]; sp[t] = sp[t + s];
                }
            }
            __syncthreads();
        }
        if (t == 0) { g_inst[NI + it] = si[0]; g_clv[sp[0]] = POS_INF; }
        __syncthreads();
    }
}

// ---------------- instance loss ----------------
__global__ void loss_kernel(const int* __restrict__ labelPtr,
                            const float* __restrict__ Winst, const float* __restrict__ binst,
                            float* __restrict__ out_loss)
{
    __shared__ float sl[4];
    int lab = labelPtr ? *labelPtr : 0;
    const float* W0 = Winst + ((size_t)lab * 2 + 0) * L_DIM;
    const float* W1 = Winst + ((size_t)lab * 2 + 1) * L_DIM;
    float b0 = binst[lab * 2], b1 = binst[lab * 2 + 1];

    int warp = threadIdx.x >> 5, lane = threadIdx.x & 31;
    float lsum = 0.f;
    for (int r = warp; r < 2 * NI; r += 4) {
        const __nv_bfloat16* hh = g_hhi + (size_t)g_inst[r] * L_DIM;
        const __nv_bfloat16* hl = g_hlo + (size_t)g_inst[r] * L_DIM;
        float s0 = 0.f, s1 = 0.f;
        for (int k = lane; k < L_DIM; k += 32) {
            float v = __bfloat162float(hh[k]) + __bfloat162float(hl[k]);
            s0 = fmaf(v, W0[k], s0);
            s1 = fmaf(v, W1[k], s1);
        }
#pragma unroll
        for (int o = 16; o; o >>= 1) {
            s0 += __shfl_xor_sync(0xFFFFFFFFu, s0, o);
            s1 += __shfl_xor_sync(0xFFFFFFFFu, s1, o);
        }
        if (lane == 0) {
            float l0 = s0 + b0, l1 = s1 + b1;
            int tgt = (r < NI) ? 1 : 0;
            float u0 = l0 + ((tgt != 0) ? 1.f : 0.f);
            float u1 = l1 + ((tgt != 1) ? 1.f : 0.f);
            float m = fmaxf(u0, u1);
            float lse = m + logf(expf(u0 - m) + expf(u1 - m));
            float sy = (tgt == 0) ? l0 : l1;
            lsum += lse - sy;
        }
    }
    if (lane == 0) sl[warp] = lsum;
    __syncthreads();
    if (threadIdx.x == 0)
        *out_loss = (sl[0] + sl[1] + sl[2] + sl[3]) * (1.f / (2 * NI));
}

// ---------------- bag logits + softmax ----------------
__global__ void final_kernel(const float* __restrict__ Wbag, const float* __restrict__ bbag,
                             float* __restrict__ out)
{
    __shared__ float lg[2];
    int warp = threadIdx.x >> 5, lane = threadIdx.x & 31;
    if (warp < 2) {
        float s = 0.f;
        for (int k = lane; k < L_DIM; k += 32)
            s = fmaf(g_bag[warp * L_DIM + k], Wbag[warp * L_DIM + k], s);
#pragma unroll
        for (int o = 16; o; o >>= 1) s += __shfl_xor_sync(0xFFFFFFFFu, s, o);
        if (lane == 0) lg[warp] = s / g_Z[warp] + bbag[warp];
    }
    __syncthreads();
    if (threadIdx.x == 0) {
        float l0 = lg[0], l1 = lg[1];
        out[0] = l0; out[1] = l1;
        float m = fmaxf(l0, l1);
        float e0 = expf(l0 - m), e1 = expf(l1 - m);
        float s = e0 + e1;
        out[2] = e0 / s; out[3] = e1 / s;
    }
}

// ---------------- launch ----------------
extern "C" void kernel_launch(void* const* d_in, const int* in_sizes, int n_in,
                              void* d_out, int out_size)
{
    const int off = (n_in >= 14) ? 1 : 0;
    const float* x     = (const float*)d_in[0];
    const int*   label = (n_in >= 14) ? (const int*)d_in[1] : nullptr;
    const float* Wc    = (const float*)d_in[1 + off];
    const float* bc    = (const float*)d_in[2 + off];
    const float* Wv    = (const float*)d_in[3 + off];
    const float* bv    = (const float*)d_in[4 + off];
    const float* Wu    = (const float*)d_in[5 + off];
    const float* bu    = (const float*)d_in[6 + off];
    const float* Wa    = (const float*)d_in[7 + off];
    const float* ba    = (const float*)d_in[8 + off];
    const float* Winst = (const float*)d_in[9 + off];
    const float* binst = (const float*)d_in[10 + off];
    const float* Wbag  = (const float*)d_in[11 + off];
    const float* bbag  = (const float*)d_in[12 + off];
    float* out = (float*)d_out;

    void* p;
    cudaGetSymbolAddress(&p, g_xhi);  __nv_bfloat16* xhi = (__nv_bfloat16*)p;
    cudaGetSymbolAddress(&p, g_xlo);  __nv_bfloat16* xlo = (__nv_bfloat16*)p;
    cudaGetSymbolAddress(&p, g_hhi);  __nv_bfloat16* hhi = (__nv_bfloat16*)p;
    cudaGetSymbolAddress(&p, g_hlo);  __nv_bfloat16* hlo = (__nv_bfloat16*)p;
    cudaGetSymbolAddress(&p, g_wchi); __nv_bfloat16* wchi = (__nv_bfloat16*)p;
    cudaGetSymbolAddress(&p, g_wclo); __nv_bfloat16* wclo = (__nv_bfloat16*)p;
    cudaGetSymbolAddress(&p, g_wthi); __nv_bfloat16* wthi = (__nv_bfloat16*)p;
    cudaGetSymbolAddress(&p, g_wtlo); __nv_bfloat16* wtlo = (__nv_bfloat16*)p;
    cudaGetSymbolAddress(&p, g_bcat); float* bcat = (float*)p;
    cudaGetSymbolAddress(&p, g_g);    float* gbuf = (float*)p;

    cudaFuncSetAttribute(gemm_hmma<0>, cudaFuncAttributeMaxDynamicSharedMemorySize, GSMEM);
    cudaFuncSetAttribute(gemm_hmma<1>, cudaFuncAttributeMaxDynamicSharedMemorySize, GSMEM);

    init_kernel<<<64, 256>>>();

    // conversions
    split_kernel<<<2048, 256>>>((const float4*)x, (__nv_bfloat162*)xhi, (__nv_bfloat162*)xlo,
                                (int)(((size_t)NROWS * E_DIM) / 4));
    split_kernel<<<256, 256>>>((const float4*)Wc, (__nv_bfloat162*)wchi, (__nv_bfloat162*)wclo,
                               (L_DIM * E_DIM) / 4);
    cat_kernel<<<(2 * D_DIM * L_DIM + 255) / 256, 256>>>(Wv, Wu, bv, bu, wthi, wtlo, bcat);

    // GEMM1: h = relu(x @ Wc^T + bc) -> h_hi/h_lo  [131072, 512]
    gemm_hmma<0><<<dim3(4, NROWS / 128), 256, GSMEM>>>(
        xhi, xlo, wchi, wclo, bc, hhi, hlo, nullptr, E_DIM, E_DIM / 64);

    // GEMM2+3 fused: g = tanh(h@Wv^T+bv) * sigmoid(h@Wu^T+bu)  [131072, 256]
    gemm_hmma<1><<<dim3(4, NROWS / 128), 256, GSMEM>>>(
        hhi, hlo, wthi, wtlo, bcat, nullptr, nullptr, gbuf, L_DIM, L_DIM / 64);

    // A = g @ Wa^T + ba; raw_attention; per-class max
    attn_kernel<<<NROWS / 8, 256>>>(Wa, ba, out + 4);

    // softmax denominators + unnormalized bag_rep
    bag_kernel<<<512, 256>>>();

    // top-50 / bottom-50 of A[:, label]
    hist_kernel<<<NROWS / 256, 256>>>(label);
    scan_kernel<<<1, 256>>>();
    cand_kernel<<<NROWS / 256, 256>>>(label);
    select_kernel<<<1, 256>>>();

    // instance loss
    loss_kernel<<<1, 128>>>(label, Winst, binst, out + 4 + 2 * NROWS);

    // bag logits + softmax
    final_kernel<<<1, 64>>>(Wbag, bbag, out);
}

// round 4
// speedup vs baseline: 2.4848x; 1.0153x over previous
#include <cuda_runtime.h>
#include <cuda_bf16.h>
#include <math.h>
#include <stdint.h>

#define NROWS 131072
#define E_DIM 1024
#define L_DIM 512
#define D_DIM 256
#define NI    50

// ---------------- device scratch (allocation-free rule) ----------------
__device__ __nv_bfloat16 g_xhi[(size_t)NROWS * E_DIM];
__device__ __nv_bfloat16 g_xlo[(size_t)NROWS * E_DIM];
__device__ __nv_bfloat16 g_hhi[(size_t)NROWS * L_DIM];
__device__ __nv_bfloat16 g_hlo[(size_t)NROWS * L_DIM];
__device__ __nv_bfloat16 g_wchi[L_DIM * E_DIM];
__device__ __nv_bfloat16 g_wclo[L_DIM * E_DIM];
__device__ __nv_bfloat16 g_wthi[2 * D_DIM * L_DIM];
__device__ __nv_bfloat16 g_wtlo[2 * D_DIM * L_DIM];
__device__ float g_bcat[2 * D_DIM];
__device__ float g_A[(size_t)NROWS * 2];
__device__ int      g_hist[16384];
__device__ unsigned g_maxkey[2];
__device__ float    g_Z[2];
__device__ float    g_bag[2 * L_DIM];
__device__ int      g_binhi, g_binlo;
__device__ int      g_nhi, g_nlo;
__device__ float g_chv[NROWS]; __device__ int g_chi[NROWS];
__device__ float g_clv[NROWS]; __device__ int g_cli[NROWS];
__device__ int   g_inst[2 * NI];

// ---------------- PTX helpers ----------------
__device__ __forceinline__ uint32_t smem_u32(const void* p) {
    uint32_t a;
    asm("{ .reg .u64 t; cvta.to.shared.u64 t, %1; cvt.u32.u64 %0, t; }" : "=r"(a) : "l"(p));
    return a;
}
__device__ __forceinline__ void cp16(uint32_t s, const void* g) {
    asm volatile("cp.async.cg.shared.global [%0], [%1], 16;" :: "r"(s), "l"(g));
}
__device__ __forceinline__ void ldsm4(uint32_t* r, uint32_t addr) {
    asm volatile("ldmatrix.sync.aligned.m8n8.x4.shared.b16 {%0,%1,%2,%3}, [%4];"
                 : "=r"(r[0]), "=r"(r[1]), "=r"(r[2]), "=r"(r[3]) : "r"(addr));
}
__device__ __forceinline__ void mma16816(float* c, const uint32_t* a, const uint32_t* b) {
    asm volatile(
        "mma.sync.aligned.m16n8k16.row.col.f32.bf16.bf16.f32 "
        "{%0,%1,%2,%3}, {%4,%5,%6,%7}, {%8,%9}, {%0,%1,%2,%3};"
        : "+f"(c[0]), "+f"(c[1]), "+f"(c[2]), "+f"(c[3])
        : "r"(a[0]), "r"(a[1]), "r"(a[2]), "r"(a[3]), "r"(b[0]), "r"(b[1]));
}

// monotone float <-> uint key
__device__ __forceinline__ unsigned monoKey(float f) {
    unsigned u = __float_as_uint(f);
    return (u & 0x80000000u) ? ~u : (u | 0x80000000u);
}
__device__ __forceinline__ float monoDecode(unsigned k) {
    unsigned u = (k & 0x80000000u) ? (k & 0x7FFFFFFFu) : ~k;
    return __uint_as_float(u);
}

// ---------------- init ----------------
__global__ void init_kernel() {
    int i = blockIdx.x * blockDim.x + threadIdx.x;   // 1024*256 = 262144
    if (i < 2 * NROWS) g_A[i] = 0.f;
    if (i < 16384) g_hist[i] = 0;
    if (i < 2 * L_DIM) g_bag[i] = 0.f;
    if (i < 2) { g_Z[i] = 0.f; g_maxkey[i] = 0u; }
    if (i == 0) { g_nhi = 0; g_nlo = 0; }
}

// ---------------- fp32 -> bf16 hi/lo split ----------------
__global__ void split_kernel(const float4* __restrict__ in, __nv_bfloat162* __restrict__ hi,
                             __nv_bfloat162* __restrict__ lo, int n4) {
    int i = blockIdx.x * blockDim.x + threadIdx.x;
    int stride = gridDim.x * blockDim.x;
    for (; i < n4; i += stride) {
        float4 v = in[i];
        __nv_bfloat16 h0 = __float2bfloat16(v.x), h1 = __float2bfloat16(v.y);
        __nv_bfloat16 h2 = __float2bfloat16(v.z), h3 = __float2bfloat16(v.w);
        hi[2 * i]     = __halves2bfloat162(h0, h1);
        hi[2 * i + 1] = __halves2bfloat162(h2, h3);
        lo[2 * i]     = __halves2bfloat162(__float2bfloat16(v.x - __bfloat162float(h0)),
                                           __float2bfloat16(v.y - __bfloat162float(h1)));
        lo[2 * i + 1] = __halves2bfloat162(__float2bfloat16(v.z - __bfloat162float(h2)),
                                           __float2bfloat16(v.w - __bfloat162float(h3)));
    }
}

// build interleaved Wcat (row 2j = Wv[j], row 2j+1 = Wu[j]) split into hi/lo + bcat
__global__ void cat_kernel(const float* __restrict__ Wv, const float* __restrict__ Wu,
                           const float* __restrict__ bv, const float* __restrict__ bu,
                           __nv_bfloat16* __restrict__ whi, __nv_bfloat16* __restrict__ wlo,
                           float* __restrict__ bcat) {
    int i = blockIdx.x * blockDim.x + threadIdx.x;
    if (i < 2 * D_DIM * L_DIM) {
        int row = i >> 9, k = i & 511;
        int j = row >> 1, e = row & 1;
        float v = e ? Wu[j * L_DIM + k] : Wv[j * L_DIM + k];
        __nv_bfloat16 h = __float2bfloat16(v);
        whi[i] = h;
        wlo[i] = __float2bfloat16(v - __bfloat162float(h));
    }
    if (i < 2 * D_DIM) {
        int j = i >> 1, e = i & 1;
        bcat[i] = e ? bu[j] : bv[j];
    }
}

// ---------------- HMMA split-fp32 GEMM ----------------
// C[M,512] = A[M,K] @ B[512,K]^T using bf16 hi/lo pairs, fp32 accumulate.
// D = Ahi*Bhi + Ahi*Blo + Alo*Bhi.
// EPI=0: v = relu(acc + bias[col]); write OutHi/OutLo bf16 [M,512]
// EPI=1: cols interleaved; g = tanh(v_even)*sigmoid(v_odd); fused attention:
//        atomicAdd partial (g . Wa[class]) into g_A  (g never materialized)
//
// CTA tile 128x128, BK=64, 8 warps (warp tile 32x64), 3-stage cp.async pipeline,
// double-buffered register fragments (ldsm of ks+1 overlaps mma of ks).
#define TILE_BYTES 16384            // 128 rows x 64 bf16 (swizzled 128B rows)
#define STAGE_BYTES (4 * TILE_BYTES) // Ahi, Alo, Bhi, Blo
#define NSTAGE 3
#define GSMEM (NSTAGE * STAGE_BYTES)

template<int EPI>
__global__ __launch_bounds__(256, 1)
void gemm_hmma(const __nv_bfloat16* __restrict__ Ahi, const __nv_bfloat16* __restrict__ Alo,
               const __nv_bfloat16* __restrict__ Bhi, const __nv_bfloat16* __restrict__ Blo,
               const float* __restrict__ bias,
               __nv_bfloat16* __restrict__ OutHi, __nv_bfloat16* __restrict__ OutLo,
               const float* __restrict__ Wa,
               int K, int NC)
{
    extern __shared__ __align__(1024) unsigned char dsm[];
    const int tid  = threadIdx.x;
    const int bn   = blockIdx.x;          // n fastest -> A-tile L2 reuse
    const int bm   = blockIdx.y;
    const int wid  = tid >> 5, lane = tid & 31;
    const int wm   = wid & 3, wn = wid >> 2;  // warp grid 4(M) x 2(N)
    const int m0   = bm * 128, n0 = bn * 128;
    const uint32_t sb = smem_u32(dsm);

    // ---- cp.async stage loader ----
    auto loadTile = [&](uint32_t dst, const __nv_bfloat16* p, int gr0, int k0) {
#pragma unroll
        for (int it = 0; it < 4; it++) {
            int q = tid + it * 256;          // 0..1023
            int row = q >> 3;
            int inner = (q & 7) << 4;        // 0..112 step 16
            uint32_t off = (uint32_t)(row * 128 + (inner ^ ((row & 7) << 4)));
            cp16(dst + off, (const char*)p + ((size_t)(gr0 + row) * K + k0) * 2 + inner);
        }
    };
    auto loadStage = [&](int s, int k0) {
        uint32_t st = sb + s * STAGE_BYTES;
        loadTile(st,                  Ahi, m0, k0);
        loadTile(st + TILE_BYTES,     Alo, m0, k0);
        loadTile(st + 2 * TILE_BYTES, Bhi, n0, k0);
        loadTile(st + 3 * TILE_BYTES, Blo, n0, k0);
        asm volatile("cp.async.commit_group;" ::: "memory");
    };

    // ---- per-lane ldmatrix address pieces ----
    const int aRow = wm * 32 + (lane & 15);
    const uint32_t aK  = ((lane >> 4) & 1) * 16;
    const uint32_t aXr = (uint32_t)((aRow & 7) << 4);
    const int bRow = wn * 64 + (lane & 7) + (((lane >> 4) & 1) << 3);
    const uint32_t bK  = ((lane >> 3) & 1) * 16;
    const uint32_t bXr = (uint32_t)((bRow & 7) << 4);

    float acc[2][8][4];
#pragma unroll
    for (int mi = 0; mi < 2; mi++)
#pragma unroll
        for (int ni = 0; ni < 8; ni++)
#pragma unroll
            for (int e = 0; e < 4; e++) acc[mi][ni][e] = 0.f;

    // double-buffered fragments
    uint32_t ah[2][2][4], al[2][2][4], bh[2][4][4], bl[2][4][4];

    loadStage(0, 0);
    loadStage(1, 64);

    for (int i = 0; i < NC; i++) {
        const int s = i % NSTAGE;
        if (i + 2 < NC) {
            loadStage((i + 2) % NSTAGE, (i + 2) * 64);
            asm volatile("cp.async.wait_group 2;" ::: "memory");
        } else if (i + 1 < NC) {
            asm volatile("cp.async.wait_group 1;" ::: "memory");
        } else {
            asm volatile("cp.async.wait_group 0;" ::: "memory");
        }
        __syncthreads();

        const uint32_t st  = sb + s * STAGE_BYTES;
        const uint32_t sAh = st, sAl = st + TILE_BYTES;
        const uint32_t sBh = st + 2 * TILE_BYTES, sBl = st + 3 * TILE_BYTES;

        auto ldFrags = [&](int buf, int ks) {
            const uint32_t ak = (uint32_t)(ks * 32) + aK;
            const uint32_t bk = (uint32_t)(ks * 32) + bK;
#pragma unroll
            for (int mi = 0; mi < 2; mi++) {
                uint32_t ro = (uint32_t)((aRow + mi * 16) * 128) + (ak ^ aXr);
                ldsm4(ah[buf][mi], sAh + ro);
                ldsm4(al[buf][mi], sAl + ro);
            }
#pragma unroll
            for (int nj = 0; nj < 4; nj++) {
                uint32_t ro = (uint32_t)((bRow + nj * 16) * 128) + (bk ^ bXr);
                ldsm4(bh[buf][nj], sBh + ro);
                ldsm4(bl[buf][nj], sBl + ro);
            }
        };

        ldFrags(0, 0);
#pragma unroll
        for (int ks = 0; ks < 4; ks++) {
            const int cur = ks & 1;
            if (ks < 3) ldFrags(cur ^ 1, ks + 1);   // prefetch next slice
#pragma unroll
            for (int mi = 0; mi < 2; mi++) {
#pragma unroll
                for (int nj = 0; nj < 4; nj++) {
                    mma16816(acc[mi][2 * nj],     ah[cur][mi], &bh[cur][nj][0]);
                    mma16816(acc[mi][2 * nj + 1], ah[cur][mi], &bh[cur][nj][2]);
                    mma16816(acc[mi][2 * nj],     ah[cur][mi], &bl[cur][nj][0]);
                    mma16816(acc[mi][2 * nj + 1], ah[cur][mi], &bl[cur][nj][2]);
                    mma16816(acc[mi][2 * nj],     al[cur][mi], &bh[cur][nj][0]);
                    mma16816(acc[mi][2 * nj + 1], al[cur][mi], &bh[cur][nj][2]);
                }
            }
        }
        __syncthreads();   // protect stage s before refill
    }

    // ---- epilogue ----
    const int rBase = m0 + wm * 32 + (lane >> 2);
    const int cBase = n0 + wn * 64 + 2 * (lane & 3);
    if (EPI == 0) {
#pragma unroll
        for (int mi = 0; mi < 2; mi++) {
#pragma unroll
            for (int ni = 0; ni < 8; ni++) {
                const int c = cBase + ni * 8;
                const float b0 = bias[c], b1 = bias[c + 1];
#pragma unroll
                for (int half = 0; half < 2; half++) {
                    const int r = rBase + mi * 16 + half * 8;
                    float v0 = fmaxf(acc[mi][ni][2 * half]     + b0, 0.f);
                    float v1 = fmaxf(acc[mi][ni][2 * half + 1] + b1, 0.f);
                    __nv_bfloat16 h0 = __float2bfloat16(v0), h1 = __float2bfloat16(v1);
                    size_t o = ((size_t)r * 512 + c) >> 1;
                    ((__nv_bfloat162*)OutHi)[o] = __halves2bfloat162(h0, h1);
                    ((__nv_bfloat162*)OutLo)[o] = __halves2bfloat162(
                        __float2bfloat16(v0 - __bfloat162float(h0)),
                        __float2bfloat16(v1 - __bfloat162float(h1)));
                }
            }
        }
    } else {
        // fused gated-attention projection: partial A[r, :] += g[r, gc] * Wa[:, gc]
#pragma unroll
        for (int mi = 0; mi < 2; mi++) {
#pragma unroll
            for (int half = 0; half < 2; half++) {
                const int r = rBase + mi * 16 + half * 8;
                float s0 = 0.f, s1 = 0.f;
#pragma unroll
                for (int ni = 0; ni < 8; ni++) {
                    const int c = cBase + ni * 8;
                    float v0 = acc[mi][ni][2 * half]     + bias[c];
                    float v1 = acc[mi][ni][2 * half + 1] + bias[c + 1];
                    float gg = tanhf(v0) / (1.f + expf(-v1));
                    const int gc = c >> 1;
                    s0 = fmaf(gg, Wa[gc], s0);
                    s1 = fmaf(gg, Wa[D_DIM + gc], s1);
                }
                s0 += __shfl_xor_sync(0xFFFFFFFFu, s0, 1);
                s0 += __shfl_xor_sync(0xFFFFFFFFu, s0, 2);
                s1 += __shfl_xor_sync(0xFFFFFFFFu, s1, 1);
                s1 += __shfl_xor_sync(0xFFFFFFFFu, s1, 2);
                if ((lane & 3) == 0) {
                    atomicAdd(&g_A[2 * r],     s0);
                    atomicAdd(&g_A[2 * r + 1], s1);
                }
            }
        }
    }
}

// ---------------- finalize: +ba, raw_attention out, per-class max, histogram ----------------
__global__ void finalize_kernel(const float* __restrict__ ba, const int* __restrict__ labelPtr,
                                float* __restrict__ out_att)
{
    __shared__ unsigned sk0, sk1;
    if (threadIdx.x == 0) { sk0 = 0u; sk1 = 0u; }
    __syncthreads();
    int i = blockIdx.x * blockDim.x + threadIdx.x;
    int lab = labelPtr ? *labelPtr : 0;
    float a0 = g_A[2 * i] + ba[0];
    float a1 = g_A[2 * i + 1] + ba[1];
    g_A[2 * i] = a0; g_A[2 * i + 1] = a1;
    out_att[i] = a0;
    out_att[NROWS + i] = a1;
    atomicMax(&sk0, monoKey(a0));
    atomicMax(&sk1, monoKey(a1));
    float sel = lab ? a1 : a0;
    atomicAdd(&g_hist[monoKey(sel) >> 18], 1);
    __syncthreads();
    if (threadIdx.x == 0) {
        atomicMax(&g_maxkey[0], sk0);
        atomicMax(&g_maxkey[1], sk1);
    }
}

// ---------------- fused softmax-weighted bag accumulation (h = hi+lo) ----------------
__global__ void bag_kernel()
{
    const int t = threadIdx.x;                 // 256 threads -> col pair (2t, 2t+1)
    const int rowsPerBlock = NROWS / gridDim.x;
    const int r0 = blockIdx.x * rowsPerBlock;
    const float m0 = monoDecode(g_maxkey[0]);
    const float m1 = monoDecode(g_maxkey[1]);

    float a00 = 0.f, a01 = 0.f, a10 = 0.f, a11 = 0.f;
    float z0 = 0.f, z1 = 0.f;
    for (int r = r0; r < r0 + rowsPerBlock; r++) {
        float w0 = expf(g_A[2 * r]     - m0);
        float w1 = expf(g_A[2 * r + 1] - m1);
        const __nv_bfloat162* hh = (const __nv_bfloat162*)(g_hhi + (size_t)r * L_DIM);
        const __nv_bfloat162* hl = (const __nv_bfloat162*)(g_hlo + (size_t)r * L_DIM);
        __nv_bfloat162 a2 = hh[t], b2 = hl[t];
        float v0 = __low2float(a2)  + __low2float(b2);
        float v1 = __high2float(a2) + __high2float(b2);
        a00 = fmaf(w0, v0, a00); a01 = fmaf(w0, v1, a01);
        a10 = fmaf(w1, v0, a10); a11 = fmaf(w1, v1, a11);
        if (t == 0) { z0 += w0; z1 += w1; }
    }
    atomicAdd(&g_bag[2 * t], a00);
    atomicAdd(&g_bag[2 * t + 1], a01);
    atomicAdd(&g_bag[L_DIM + 2 * t], a10);
    atomicAdd(&g_bag[L_DIM + 2 * t + 1], a11);
    if (t == 0) { atomicAdd(&g_Z[0], z0); atomicAdd(&g_Z[1], z1); }
}

// ---------------- top-k machinery ----------------
__global__ void scan_kernel()
{
    __shared__ int csum[256];
    int t = threadIdx.x;
    int s = 0;
    for (int b = t * 64; b < t * 64 + 64; b++) s += g_hist[b];
    csum[t] = s;
    __syncthreads();
    if (t == 0) {
        int cum = 0, binhi = 0;
        for (int c = 255; c >= 0; c--) {
            if (cum + csum[c] >= NI) {
                for (int b = c * 64 + 63; b >= c * 64; b--) {
                    cum += g_hist[b];
                    if (cum >= NI) { binhi = b; break; }
                }
                break;
            }
            cum += csum[c];
        }
        g_binhi = binhi;
        cum = 0; int binlo = 16383;
        for (int c = 0; c < 256; c++) {
            if (cum + csum[c] >= NI) {
                for (int b = c * 64; b < c * 64 + 64; b++) {
                    cum += g_hist[b];
                    if (cum >= NI) { binlo = b; break; }
                }
                break;
            }
            cum += csum[c];
        }
        g_binlo = binlo;
        g_nhi = 0; g_nlo = 0;
    }
}

__global__ void cand_kernel(const int* __restrict__ labelPtr)
{
    int lab = labelPtr ? *labelPtr : 0;
    int binhi = g_binhi, binlo = g_binlo;
    for (int i = blockIdx.x * blockDim.x + threadIdx.x; i < NROWS; i += gridDim.x * blockDim.x) {
        float v = g_A[2 * i + lab];
        unsigned key = monoKey(v) >> 18;
        if ((int)key >= binhi) {
            int p = atomicAdd(&g_nhi, 1);
            g_chv[p] = v; g_chi[p] = i;
        }
        if ((int)key <= binlo) {
            int p = atomicAdd(&g_nlo, 1);
            g_clv[p] = v; g_cli[p] = i;
        }
    }
}

__global__ void select_kernel()
{
    __shared__ float sv[256];
    __shared__ int   si[256];
    __shared__ int   sp[256];
    const int t = threadIdx.x;
    const float NEG_INF = __int_as_float(0xFF800000);
    const float POS_INF = __int_as_float(0x7F800000);
    int nhi = g_nhi, nlo = g_nlo;

    for (int it = 0; it < NI; it++) {
        float bv = NEG_INF; int bi = 0x7FFFFFFF; int bp = -1;
        for (int p = t; p < nhi; p += 256) {
            float v = g_chv[p]; int idx = g_chi[p];
            if (v > bv || (v == bv && idx < bi)) { bv = v; bi = idx; bp = p; }
        }
        sv[t] = bv; si[t] = bi; sp[t] = bp;
        __syncthreads();
        for (int s = 128; s; s >>= 1) {
            if (t < s) {
                if (sv[t + s] > sv[t] || (sv[t + s] == sv[t] && si[t + s] < si[t])) {
                    sv[t] = sv[t + s]; si[t] = si[t + s]; sp[t] = sp[t + s];
                }
            }
            __syncthreads();
        }
        if (t == 0) { g_inst[it] = si[0]; g_chv[sp[0]] = NEG_INF; }
        __syncthreads();
    }
    for (int it = 0; it < NI; it++) {
        float bv = POS_INF; int bi = 0x7FFFFFFF; int bp = -1;
        for (int p = t; p < nlo; p += 256) {
            float v = g_clv[p]; int idx = g_cli[p];
            if (v < bv || (v == bv && idx < bi)) { bv = v; bi = idx; bp = p; }
        }
        sv[t] = bv; si[t] = bi; sp[t] = bp;
        __syncthreads();
        for (int s = 128; s; s >>= 1) {
            if (t < s) {
                if (sv[t + s] < sv[t] || (sv[t + s] == sv[t] && si[t + s] < si[t])) {
                    sv[t] = sv[t + s]; si[t] = si[t + s]; sp[t] = sp[t + s];
                }
            }
            __syncthreads();
        }
        if (t == 0) { g_inst[NI + it] = si[0]; g_clv[sp[0]] = POS_INF; }
        __syncthreads();
    }
}

// ---------------- instance loss ----------------
__global__ void loss_kernel(const int* __restrict__ labelPtr,
                            const float* __restrict__ Winst, const float* __restrict__ binst,
                            float* __restrict__ out_loss)
{
    __shared__ float sl[4];
    int lab = labelPtr ? *labelPtr : 0;
    const float* W0 = Winst + ((size_t)lab * 2 + 0) * L_DIM;
    const float* W1 = Winst + ((size_t)lab * 2 + 1) * L_DIM;
    float b0 = binst[lab * 2], b1 = binst[lab * 2 + 1];

    int warp = threadIdx.x >> 5, lane = threadIdx.x & 31;
    float lsum = 0.f;
    for (int r = warp; r < 2 * NI; r += 4) {
        const __nv_bfloat16* hh = g_hhi + (size_t)g_inst[r] * L_DIM;
        const __nv_bfloat16* hl = g_hlo + (size_t)g_inst[r] * L_DIM;
        float s0 = 0.f, s1 = 0.f;
        for (int k = lane; k < L_DIM; k += 32) {
            float v = __bfloat162float(hh[k]) + __bfloat162float(hl[k]);
            s0 = fmaf(v, W0[k], s0);
            s1 = fmaf(v, W1[k], s1);
        }
#pragma unroll
        for (int o = 16; o; o >>= 1) {
            s0 += __shfl_xor_sync(0xFFFFFFFFu, s0, o);
            s1 += __shfl_xor_sync(0xFFFFFFFFu, s1, o);
        }
        if (lane == 0) {
            float l0 = s0 + b0, l1 = s1 + b1;
            int tgt = (r < NI) ? 1 : 0;
            float u0 = l0 + ((tgt != 0) ? 1.f : 0.f);
            float u1 = l1 + ((tgt != 1) ? 1.f : 0.f);
            float m = fmaxf(u0, u1);
            float lse = m + logf(expf(u0 - m) + expf(u1 - m));
            float sy = (tgt == 0) ? l0 : l1;
            lsum += lse - sy;
        }
    }
    if (lane == 0) sl[warp] = lsum;
    __syncthreads();
    if (threadIdx.x == 0)
        *out_loss = (sl[0] + sl[1] + sl[2] + sl[3]) * (1.f / (2 * NI));
}

// ---------------- bag logits + softmax ----------------
__global__ void final_kernel(const float* __restrict__ Wbag, const float* __restrict__ bbag,
                             float* __restrict__ out)
{
    __shared__ float lg[2];
    int warp = threadIdx.x >> 5, lane = threadIdx.x & 31;
    if (warp < 2) {
        float s = 0.f;
        for (int k = lane; k < L_DIM; k += 32)
            s = fmaf(g_bag[warp * L_DIM + k], Wbag[warp * L_DIM + k], s);
#pragma unroll
        for (int o = 16; o; o >>= 1) s += __shfl_xor_sync(0xFFFFFFFFu, s, o);
        if (lane == 0) lg[warp] = s / g_Z[warp] + bbag[warp];
    }
    __syncthreads();
    if (threadIdx.x == 0) {
        float l0 = lg[0], l1 = lg[1];
        out[0] = l0; out[1] = l1;
        float m = fmaxf(l0, l1);
        float e0 = expf(l0 - m), e1 = expf(l1 - m);
        float s = e0 + e1;
        out[2] = e0 / s; out[3] = e1 / s;
    }
}

// ---------------- launch ----------------
extern "C" void kernel_launch(void* const* d_in, const int* in_sizes, int n_in,
                              void* d_out, int out_size)
{
    const int off = (n_in >= 14) ? 1 : 0;
    const float* x     = (const float*)d_in[0];
    const int*   label = (n_in >= 14) ? (const int*)d_in[1] : nullptr;
    const float* Wc    = (const float*)d_in[1 + off];
    const float* bc    = (const float*)d_in[2 + off];
    const float* Wv    = (const float*)d_in[3 + off];
    const float* bv    = (const float*)d_in[4 + off];
    const float* Wu    = (const float*)d_in[5 + off];
    const float* bu    = (const float*)d_in[6 + off];
    const float* Wa    = (const float*)d_in[7 + off];
    const float* ba    = (const float*)d_in[8 + off];
    const float* Winst = (const float*)d_in[9 + off];
    const float* binst = (const float*)d_in[10 + off];
    const float* Wbag  = (const float*)d_in[11 + off];
    const float* bbag  = (const float*)d_in[12 + off];
    float* out = (float*)d_out;

    void* p;
    cudaGetSymbolAddress(&p, g_xhi);  __nv_bfloat16* xhi = (__nv_bfloat16*)p;
    cudaGetSymbolAddress(&p, g_xlo);  __nv_bfloat16* xlo = (__nv_bfloat16*)p;
    cudaGetSymbolAddress(&p, g_hhi);  __nv_bfloat16* hhi = (__nv_bfloat16*)p;
    cudaGetSymbolAddress(&p, g_hlo);  __nv_bfloat16* hlo = (__nv_bfloat16*)p;
    cudaGetSymbolAddress(&p, g_wchi); __nv_bfloat16* wchi = (__nv_bfloat16*)p;
    cudaGetSymbolAddress(&p, g_wclo); __nv_bfloat16* wclo = (__nv_bfloat16*)p;
    cudaGetSymbolAddress(&p, g_wthi); __nv_bfloat16* wthi = (__nv_bfloat16*)p;
    cudaGetSymbolAddress(&p, g_wtlo); __nv_bfloat16* wtlo = (__nv_bfloat16*)p;
    cudaGetSymbolAddress(&p, g_bcat); float* bcat = (float*)p;

    cudaFuncSetAttribute(gemm_hmma<0>, cudaFuncAttributeMaxDynamicSharedMemorySize, GSMEM);
    cudaFuncSetAttribute(gemm_hmma<1>, cudaFuncAttributeMaxDynamicSharedMemorySize, GSMEM);

    init_kernel<<<1024, 256>>>();

    // conversions
    split_kernel<<<2048, 256>>>((const float4*)x, (__nv_bfloat162*)xhi, (__nv_bfloat162*)xlo,
                                (int)(((size_t)NROWS * E_DIM) / 4));
    split_kernel<<<256, 256>>>((const float4*)Wc, (__nv_bfloat162*)wchi, (__nv_bfloat162*)wclo,
                               (L_DIM * E_DIM) / 4);
    cat_kernel<<<(2 * D_DIM * L_DIM + 255) / 256, 256>>>(Wv, Wu, bv, bu, wthi, wtlo, bcat);

    // GEMM1: h = relu(x @ Wc^T + bc) -> h_hi/h_lo  [131072, 512]
    gemm_hmma<0><<<dim3(4, NROWS / 128), 256, GSMEM>>>(
        xhi, xlo, wchi, wclo, bc, hhi, hlo, nullptr, E_DIM, E_DIM / 64);

    // GEMM2+3 + attention fused: atomic partial A = (tanh*sigmoid) @ Wa^T into g_A
    gemm_hmma<1><<<dim3(4, NROWS / 128), 256, GSMEM>>>(
        hhi, hlo, wthi, wtlo, bcat, nullptr, nullptr, Wa, L_DIM, L_DIM / 64);

    // finalize: +ba, raw_attention, per-class max, label-class histogram
    finalize_kernel<<<NROWS / 256, 256>>>(ba, label, out + 4);

    // top-50 / bottom-50 of A[:, label]
    scan_kernel<<<1, 256>>>();
    cand_kernel<<<NROWS / 256, 256>>>(label);
    select_kernel<<<1, 256>>>();

    // instance loss
    loss_kernel<<<1, 128>>>(label, Winst, binst, out + 4 + 2 * NROWS);

    // softmax denominators + unnormalized bag_rep
    bag_kernel<<<512, 256>>>();

    // bag logits + softmax
    final_kernel<<<1, 64>>>(Wbag, bbag, out);
}

// round 5
// speedup vs baseline: 2.4907x; 1.0024x over previous
#include <cuda_runtime.h>
#include <cuda_bf16.h>
#include <math.h>
#include <stdint.h>

#define NROWS 131072
#define E_DIM 1024
#define L_DIM 512
#define D_DIM 256
#define NI    50

// ---------------- device scratch (allocation-free rule) ----------------
__device__ __nv_bfloat16 g_xhi[(size_t)NROWS * E_DIM];
__device__ __nv_bfloat16 g_xlo[(size_t)NROWS * E_DIM];
__device__ __nv_bfloat16 g_hhi[(size_t)NROWS * L_DIM];
__device__ __nv_bfloat16 g_hlo[(size_t)NROWS * L_DIM];
__device__ __nv_bfloat16 g_wchi[L_DIM * E_DIM];
__device__ __nv_bfloat16 g_wclo[L_DIM * E_DIM];
__device__ __nv_bfloat16 g_wthi[2 * D_DIM * L_DIM];
__device__ __nv_bfloat16 g_wtlo[2 * D_DIM * L_DIM];
__device__ float g_bcat[2 * D_DIM];
__device__ float g_A[(size_t)NROWS * 2];
__device__ int      g_hist[16384];
__device__ unsigned g_maxkey[2];
__device__ float    g_Z[2];
__device__ float    g_bag[2 * L_DIM];
__device__ int      g_binhi, g_binlo;
__device__ int      g_nhi, g_nlo;
__device__ float g_chv[NROWS]; __device__ int g_chi[NROWS];
__device__ float g_clv[NROWS]; __device__ int g_cli[NROWS];
__device__ int   g_inst[2 * NI];

// ---------------- PTX helpers ----------------
__device__ __forceinline__ uint32_t smem_u32(const void* p) {
    uint32_t a;
    asm("{ .reg .u64 t; cvta.to.shared.u64 t, %1; cvt.u32.u64 %0, t; }" : "=r"(a) : "l"(p));
    return a;
}
__device__ __forceinline__ void cp16(uint32_t s, const void* g) {
    asm volatile("cp.async.cg.shared.global [%0], [%1], 16;" :: "r"(s), "l"(g));
}
__device__ __forceinline__ void ldsm4(uint32_t* r, uint32_t addr) {
    asm volatile("ldmatrix.sync.aligned.m8n8.x4.shared.b16 {%0,%1,%2,%3}, [%4];"
                 : "=r"(r[0]), "=r"(r[1]), "=r"(r[2]), "=r"(r[3]) : "r"(addr));
}
__device__ __forceinline__ void mma16816(float* c, const uint32_t* a, const uint32_t* b) {
    asm volatile(
        "mma.sync.aligned.m16n8k16.row.col.f32.bf16.bf16.f32 "
        "{%0,%1,%2,%3}, {%4,%5,%6,%7}, {%8,%9}, {%0,%1,%2,%3};"
        : "+f"(c[0]), "+f"(c[1]), "+f"(c[2]), "+f"(c[3])
        : "r"(a[0]), "r"(a[1]), "r"(a[2]), "r"(a[3]), "r"(b[0]), "r"(b[1]));
}

// monotone float <-> uint key
__device__ __forceinline__ unsigned monoKey(float f) {
    unsigned u = __float_as_uint(f);
    return (u & 0x80000000u) ? ~u : (u | 0x80000000u);
}
__device__ __forceinline__ float monoDecode(unsigned k) {
    unsigned u = (k & 0x80000000u) ? (k & 0x7FFFFFFFu) : ~k;
    return __uint_as_float(u);
}

// ---------------- init ----------------
__global__ void init_kernel() {
    int i = blockIdx.x * blockDim.x + threadIdx.x;   // 1024*256 = 262144
    if (i < 2 * NROWS) g_A[i] = 0.f;
    if (i < 16384) g_hist[i] = 0;
    if (i < 2 * L_DIM) g_bag[i] = 0.f;
    if (i < 2) { g_Z[i] = 0.f; g_maxkey[i] = 0u; }
    if (i == 0) { g_nhi = 0; g_nlo = 0; }
}

// ---------------- fp32 -> bf16 hi/lo split ----------------
__global__ void split_kernel(const float4* __restrict__ in, __nv_bfloat162* __restrict__ hi,
                             __nv_bfloat162* __restrict__ lo, int n4) {
    int i = blockIdx.x * blockDim.x + threadIdx.x;
    int stride = gridDim.x * blockDim.x;
    for (; i < n4; i += stride) {
        float4 v = in[i];
        __nv_bfloat16 h0 = __float2bfloat16(v.x), h1 = __float2bfloat16(v.y);
        __nv_bfloat16 h2 = __float2bfloat16(v.z), h3 = __float2bfloat16(v.w);
        hi[2 * i]     = __halves2bfloat162(h0, h1);
        hi[2 * i + 1] = __halves2bfloat162(h2, h3);
        lo[2 * i]     = __halves2bfloat162(__float2bfloat16(v.x - __bfloat162float(h0)),
                                           __float2bfloat16(v.y - __bfloat162float(h1)));
        lo[2 * i + 1] = __halves2bfloat162(__float2bfloat16(v.z - __bfloat162float(h2)),
                                           __float2bfloat16(v.w - __bfloat162float(h3)));
    }
}

// build interleaved Wcat (row 2j = Wv[j], row 2j+1 = Wu[j]) split into hi/lo + bcat
__global__ void cat_kernel(const float* __restrict__ Wv, const float* __restrict__ Wu,
                           const float* __restrict__ bv, const float* __restrict__ bu,
                           __nv_bfloat16* __restrict__ whi, __nv_bfloat16* __restrict__ wlo,
                           float* __restrict__ bcat) {
    int i = blockIdx.x * blockDim.x + threadIdx.x;
    if (i < 2 * D_DIM * L_DIM) {
        int row = i >> 9, k = i & 511;
        int j = row >> 1, e = row & 1;
        float v = e ? Wu[j * L_DIM + k] : Wv[j * L_DIM + k];
        __nv_bfloat16 h = __float2bfloat16(v);
        whi[i] = h;
        wlo[i] = __float2bfloat16(v - __bfloat162float(h));
    }
    if (i < 2 * D_DIM) {
        int j = i >> 1, e = i & 1;
        bcat[i] = e ? bu[j] : bv[j];
    }
}

// ---------------- HMMA split-fp32 GEMM ----------------
// C[M,512] = A[M,K] @ B[512,K]^T using bf16 hi/lo pairs, fp32 accumulate.
// D = Ahi*Bhi + Ahi*Blo + Alo*Bhi, issued product-major (no acc RAW chains).
// EPI=0: v = relu(acc + bias[col]); write OutHi/OutLo bf16 [M,512]
// EPI=1: cols interleaved; g = tanh(v_even)*sigmoid(v_odd); fused attention:
//        atomicAdd partial (g . Wa[class]) into g_A  (g never materialized)
#define TILE_BYTES 16384            // 128 rows x 64 bf16 (swizzled 128B rows)
#define STAGE_BYTES (4 * TILE_BYTES) // Ahi, Alo, Bhi, Blo
#define NSTAGE 3
#define GSMEM (NSTAGE * STAGE_BYTES)

template<int EPI>
__global__ __launch_bounds__(256, 1)
void gemm_hmma(const __nv_bfloat16* __restrict__ Ahi, const __nv_bfloat16* __restrict__ Alo,
               const __nv_bfloat16* __restrict__ Bhi, const __nv_bfloat16* __restrict__ Blo,
               const float* __restrict__ bias,
               __nv_bfloat16* __restrict__ OutHi, __nv_bfloat16* __restrict__ OutLo,
               const float* __restrict__ Wa,
               int K, int NC)
{
    extern __shared__ __align__(1024) unsigned char dsm[];
    const int tid  = threadIdx.x;
    const int bn   = blockIdx.x;          // n fastest -> A-tile L2 reuse
    const int bm   = blockIdx.y;
    const int wid  = tid >> 5, lane = tid & 31;
    const int wm   = wid & 3, wn = wid >> 2;  // warp grid 4(M) x 2(N)
    const int m0   = bm * 128, n0 = bn * 128;
    const uint32_t sb = smem_u32(dsm);

    // ---- cp.async stage loader ----
    auto loadTile = [&](uint32_t dst, const __nv_bfloat16* p, int gr0, int k0) {
#pragma unroll
        for (int it = 0; it < 4; it++) {
            int q = tid + it * 256;          // 0..1023
            int row = q >> 3;
            int inner = (q & 7) << 4;        // 0..112 step 16
            uint32_t off = (uint32_t)(row * 128 + (inner ^ ((row & 7) << 4)));
            cp16(dst + off, (const char*)p + ((size_t)(gr0 + row) * K + k0) * 2 + inner);
        }
    };
    auto loadStage = [&](int s, int k0) {
        uint32_t st = sb + s * STAGE_BYTES;
        loadTile(st,                  Ahi, m0, k0);
        loadTile(st + TILE_BYTES,     Alo, m0, k0);
        loadTile(st + 2 * TILE_BYTES, Bhi, n0, k0);
        loadTile(st + 3 * TILE_BYTES, Blo, n0, k0);
        asm volatile("cp.async.commit_group;" ::: "memory");
    };

    // ---- per-lane ldmatrix address pieces ----
    const int aRow = wm * 32 + (lane & 15);
    const uint32_t aK  = ((lane >> 4) & 1) * 16;
    const uint32_t aXr = (uint32_t)((aRow & 7) << 4);
    const int bRow = wn * 64 + (lane & 7) + (((lane >> 4) & 1) << 3);
    const uint32_t bK  = ((lane >> 3) & 1) * 16;
    const uint32_t bXr = (uint32_t)((bRow & 7) << 4);

    float acc[2][8][4];
#pragma unroll
    for (int mi = 0; mi < 2; mi++)
#pragma unroll
        for (int ni = 0; ni < 8; ni++)
#pragma unroll
            for (int e = 0; e < 4; e++) acc[mi][ni][e] = 0.f;

    // double-buffered fragments
    uint32_t ah[2][2][4], al[2][2][4], bh[2][4][4], bl[2][4][4];

    loadStage(0, 0);
    loadStage(1, 64);

    for (int i = 0; i < NC; i++) {
        const int s = i % NSTAGE;
        if (i + 1 < NC) asm volatile("cp.async.wait_group 1;" ::: "memory");
        else            asm volatile("cp.async.wait_group 0;" ::: "memory");
        __syncthreads();                       // single barrier per iteration
        if (i + 2 < NC) loadStage((i + 2) % NSTAGE, (i + 2) * 64);

        const uint32_t st  = sb + s * STAGE_BYTES;
        const uint32_t sAh = st, sAl = st + TILE_BYTES;
        const uint32_t sBh = st + 2 * TILE_BYTES, sBl = st + 3 * TILE_BYTES;

        auto ldFrags = [&](int buf, int ks) {
            const uint32_t ak = (uint32_t)(ks * 32) + aK;
            const uint32_t bk = (uint32_t)(ks * 32) + bK;
#pragma unroll
            for (int mi = 0; mi < 2; mi++) {
                uint32_t ro = (uint32_t)((aRow + mi * 16) * 128) + (ak ^ aXr);
                ldsm4(ah[buf][mi], sAh + ro);
                ldsm4(al[buf][mi], sAl + ro);
            }
#pragma unroll
            for (int nj = 0; nj < 4; nj++) {
                uint32_t ro = (uint32_t)((bRow + nj * 16) * 128) + (bk ^ bXr);
                ldsm4(bh[buf][nj], sBh + ro);
                ldsm4(bl[buf][nj], sBl + ro);
            }
        };

        ldFrags(0, 0);
#pragma unroll
        for (int ks = 0; ks < 4; ks++) {
            const int cur = ks & 1;
            if (ks < 3) ldFrags(cur ^ 1, ks + 1);   // prefetch next slice
            // --- product-major: each acc touched once per pass (16 mma apart) ---
#pragma unroll
            for (int mi = 0; mi < 2; mi++)
#pragma unroll
                for (int nj = 0; nj < 4; nj++) {
                    mma16816(acc[mi][2 * nj],     ah[cur][mi], &bh[cur][nj][0]);
                    mma16816(acc[mi][2 * nj + 1], ah[cur][mi], &bh[cur][nj][2]);
                }
#pragma unroll
            for (int mi = 0; mi < 2; mi++)
#pragma unroll
                for (int nj = 0; nj < 4; nj++) {
                    mma16816(acc[mi][2 * nj],     ah[cur][mi], &bl[cur][nj][0]);
                    mma16816(acc[mi][2 * nj + 1], ah[cur][mi], &bl[cur][nj][2]);
                }
#pragma unroll
            for (int mi = 0; mi < 2; mi++)
#pragma unroll
                for (int nj = 0; nj < 4; nj++) {
                    mma16816(acc[mi][2 * nj],     al[cur][mi], &bh[cur][nj][0]);
                    mma16816(acc[mi][2 * nj + 1], al[cur][mi], &bh[cur][nj][2]);
                }
        }
    }

    // ---- epilogue ----
    const int rBase = m0 + wm * 32 + (lane >> 2);
    const int cBase = n0 + wn * 64 + 2 * (lane & 3);
    if (EPI == 0) {
#pragma unroll
        for (int mi = 0; mi < 2; mi++) {
#pragma unroll
            for (int ni = 0; ni < 8; ni++) {
                const int c = cBase + ni * 8;
                const float b0 = bias[c], b1 = bias[c + 1];
#pragma unroll
                for (int half = 0; half < 2; half++) {
                    const int r = rBase + mi * 16 + half * 8;
                    float v0 = fmaxf(acc[mi][ni][2 * half]     + b0, 0.f);
                    float v1 = fmaxf(acc[mi][ni][2 * half + 1] + b1, 0.f);
                    __nv_bfloat16 h0 = __float2bfloat16(v0), h1 = __float2bfloat16(v1);
                    size_t o = ((size_t)r * 512 + c) >> 1;
                    ((__nv_bfloat162*)OutHi)[o] = __halves2bfloat162(h0, h1);
                    ((__nv_bfloat162*)OutLo)[o] = __halves2bfloat162(
                        __float2bfloat16(v0 - __bfloat162float(h0)),
                        __float2bfloat16(v1 - __bfloat162float(h1)));
                }
            }
        }
    } else {
        // fused gated-attention projection: partial A[r, :] += g[r, gc] * Wa[:, gc]
#pragma unroll
        for (int mi = 0; mi < 2; mi++) {
#pragma unroll
            for (int half = 0; half < 2; half++) {
                const int r = rBase + mi * 16 + half * 8;
                float s0 = 0.f, s1 = 0.f;
#pragma unroll
                for (int ni = 0; ni < 8; ni++) {
                    const int c = cBase + ni * 8;
                    float v0 = acc[mi][ni][2 * half]     + bias[c];
                    float v1 = acc[mi][ni][2 * half + 1] + bias[c + 1];
                    float gg = tanhf(v0) / (1.f + expf(-v1));
                    const int gc = c >> 1;
                    s0 = fmaf(gg, Wa[gc], s0);
                    s1 = fmaf(gg, Wa[D_DIM + gc], s1);
                }
                s0 += __shfl_xor_sync(0xFFFFFFFFu, s0, 1);
                s0 += __shfl_xor_sync(0xFFFFFFFFu, s0, 2);
                s1 += __shfl_xor_sync(0xFFFFFFFFu, s1, 1);
                s1 += __shfl_xor_sync(0xFFFFFFFFu, s1, 2);
                if ((lane & 3) == 0) {
                    atomicAdd(&g_A[2 * r],     s0);
                    atomicAdd(&g_A[2 * r + 1], s1);
                }
            }
        }
    }
}

// ---------------- finalize: +ba, raw_attention out, per-class max, histogram ----------------
__global__ void finalize_kernel(const float* __restrict__ ba, const int* __restrict__ labelPtr,
                                float* __restrict__ out_att)
{
    __shared__ unsigned sk0, sk1;
    if (threadIdx.x == 0) { sk0 = 0u; sk1 = 0u; }
    __syncthreads();
    int i = blockIdx.x * blockDim.x + threadIdx.x;
    int lab = labelPtr ? *labelPtr : 0;
    float a0 = g_A[2 * i] + ba[0];
    float a1 = g_A[2 * i + 1] + ba[1];
    g_A[2 * i] = a0; g_A[2 * i + 1] = a1;
    out_att[i] = a0;
    out_att[NROWS + i] = a1;
    atomicMax(&sk0, monoKey(a0));
    atomicMax(&sk1, monoKey(a1));
    float sel = lab ? a1 : a0;
    atomicAdd(&g_hist[monoKey(sel) >> 18], 1);
    __syncthreads();
    if (threadIdx.x == 0) {
        atomicMax(&g_maxkey[0], sk0);
        atomicMax(&g_maxkey[1], sk1);
    }
}

// ---------------- fused softmax-weighted bag accumulation (h = hi+lo) ----------------
__global__ void bag_kernel()
{
    const int t = threadIdx.x;                 // 256 threads -> col pair (2t, 2t+1)
    const int rowsPerBlock = NROWS / gridDim.x;
    const int r0 = blockIdx.x * rowsPerBlock;
    const float m0 = monoDecode(g_maxkey[0]);
    const float m1 = monoDecode(g_maxkey[1]);

    float a00 = 0.f, a01 = 0.f, a10 = 0.f, a11 = 0.f;
    float z0 = 0.f, z1 = 0.f;
    for (int r = r0; r < r0 + rowsPerBlock; r++) {
        float w0 = expf(g_A[2 * r]     - m0);
        float w1 = expf(g_A[2 * r + 1] - m1);
        const __nv_bfloat162* hh = (const __nv_bfloat162*)(g_hhi + (size_t)r * L_DIM);
        const __nv_bfloat162* hl = (const __nv_bfloat162*)(g_hlo + (size_t)r * L_DIM);
        __nv_bfloat162 a2 = hh[t], b2 = hl[t];
        float v0 = __low2float(a2)  + __low2float(b2);
        float v1 = __high2float(a2) + __high2float(b2);
        a00 = fmaf(w0, v0, a00); a01 = fmaf(w0, v1, a01);
        a10 = fmaf(w1, v0, a10); a11 = fmaf(w1, v1, a11);
        if (t == 0) { z0 += w0; z1 += w1; }
    }
    atomicAdd(&g_bag[2 * t], a00);
    atomicAdd(&g_bag[2 * t + 1], a01);
    atomicAdd(&g_bag[L_DIM + 2 * t], a10);
    atomicAdd(&g_bag[L_DIM + 2 * t + 1], a11);
    if (t == 0) { atomicAdd(&g_Z[0], z0); atomicAdd(&g_Z[1], z1); }
}

// ---------------- top-k machinery ----------------
__global__ void scan_kernel()
{
    __shared__ int csum[256];
    int t = threadIdx.x;
    int s = 0;
    for (int b = t * 64; b < t * 64 + 64; b++) s += g_hist[b];
    csum[t] = s;
    __syncthreads();
    if (t == 0) {
        int cum = 0, binhi = 0;
        for (int c = 255; c >= 0; c--) {
            if (cum + csum[c] >= NI) {
                for (int b = c * 64 + 63; b >= c * 64; b--) {
                    cum += g_hist[b];
                    if (cum >= NI) { binhi = b; break; }
                }
                break;
            }
            cum += csum[c];
        }
        g_binhi = binhi;
        cum = 0; int binlo = 16383;
        for (int c = 0; c < 256; c++) {
            if (cum + csum[c] >= NI) {
                for (int b = c * 64; b < c * 64 + 64; b++) {
                    cum += g_hist[b];
                    if (cum >= NI) { binlo = b; break; }
                }
                break;
            }
            cum += csum[c];
        }
        g_binlo = binlo;
        g_nhi = 0; g_nlo = 0;
    }
}

__global__ void cand_kernel(const int* __restrict__ labelPtr)
{
    int lab = labelPtr ? *labelPtr : 0;
    int binhi = g_binhi, binlo = g_binlo;
    for (int i = blockIdx.x * blockDim.x + threadIdx.x; i < NROWS; i += gridDim.x * blockDim.x) {
        float v = g_A[2 * i + lab];
        unsigned key = monoKey(v) >> 18;
        if ((int)key >= binhi) {
            int p = atomicAdd(&g_nhi, 1);
            g_chv[p] = v; g_chi[p] = i;
        }
        if ((int)key <= binlo) {
            int p = atomicAdd(&g_nlo, 1);
            g_clv[p] = v; g_cli[p] = i;
        }
    }
}

__global__ void select_kernel()
{
    __shared__ float sv[256];
    __shared__ int   si[256];
    __shared__ int   sp[256];
    const int t = threadIdx.x;
    const float NEG_INF = __int_as_float(0xFF800000);
    const float POS_INF = __int_as_float(0x7F800000);
    int nhi = g_nhi, nlo = g_nlo;

    for (int it = 0; it < NI; it++) {
        float bv = NEG_INF; int bi = 0x7FFFFFFF; int bp = -1;
        for (int p = t; p < nhi; p += 256) {
            float v = g_chv[p]; int idx = g_chi[p];
            if (v > bv || (v == bv && idx < bi)) { bv = v; bi = idx; bp = p; }
        }
        sv[t] = bv; si[t] = bi; sp[t] = bp;
        __syncthreads();
        for (int s = 128; s; s >>= 1) {
            if (t < s) {
                if (sv[t + s] > sv[t] || (sv[t + s] == sv[t] && si[t + s] < si[t])) {
                    sv[t] = sv[t + s]; si[t] = si[t + s]; sp[t] = sp[t + s];
                }
            }
            __syncthreads();
        }
        if (t == 0) { g_inst[it] = si[0]; g_chv[sp[0]] = NEG_INF; }
        __syncthreads();
    }
    for (int it = 0; it < NI; it++) {
        float bv = POS_INF; int bi = 0x7FFFFFFF; int bp = -1;
        for (int p = t; p < nlo; p += 256) {
            float v = g_clv[p]; int idx = g_cli[p];
            if (v < bv || (v == bv && idx < bi)) { bv = v; bi = idx; bp = p; }
        }
        sv[t] = bv; si[t] = bi; sp[t] = bp;
        __syncthreads();
        for (int s = 128; s; s >>= 1) {
            if (t < s) {
                if (sv[t + s] < sv[t] || (sv[t + s] == sv[t] && si[t + s] < si[t])) {
                    sv[t] = sv[t + s]; si[t] = si[t + s]; sp[t] = sp[t + s];
                }
            }
            __syncthreads();
        }
        if (t == 0) { g_inst[NI + it] = si[0]; g_clv[sp[0]] = POS_INF; }
        __syncthreads();
    }
}

// ---------------- instance loss ----------------
__global__ void loss_kernel(const int* __restrict__ labelPtr,
                            const float* __restrict__ Winst, const float* __restrict__ binst,
                            float* __restrict__ out_loss)
{
    __shared__ float sl[4];
    int lab = labelPtr ? *labelPtr : 0;
    const float* W0 = Winst + ((size_t)lab * 2 + 0) * L_DIM;
    const float* W1 = Winst + ((size_t)lab * 2 + 1) * L_DIM;
    float b0 = binst[lab * 2], b1 = binst[lab * 2 + 1];

    int warp = threadIdx.x >> 5, lane = threadIdx.x & 31;
    float lsum = 0.f;
    for (int r = warp; r < 2 * NI; r += 4) {
        const __nv_bfloat16* hh = g_hhi + (size_t)g_inst[r] * L_DIM;
        const __nv_bfloat16* hl = g_hlo + (size_t)g_inst[r] * L_DIM;
        float s0 = 0.f, s1 = 0.f;
        for (int k = lane; k < L_DIM; k += 32) {
            float v = __bfloat162float(hh[k]) + __bfloat162float(hl[k]);
            s0 = fmaf(v, W0[k], s0);
            s1 = fmaf(v, W1[k], s1);
        }
#pragma unroll
        for (int o = 16; o; o >>= 1) {
            s0 += __shfl_xor_sync(0xFFFFFFFFu, s0, o);
            s1 += __shfl_xor_sync(0xFFFFFFFFu, s1, o);
        }
        if (lane == 0) {
            float l0 = s0 + b0, l1 = s1 + b1;
            int tgt = (r < NI) ? 1 : 0;
            float u0 = l0 + ((tgt != 0) ? 1.f : 0.f);
            float u1 = l1 + ((tgt != 1) ? 1.f : 0.f);
            float m = fmaxf(u0, u1);
            float lse = m + logf(expf(u0 - m) + expf(u1 - m));
            float sy = (tgt == 0) ? l0 : l1;
            lsum += lse - sy;
        }
    }
    if (lane == 0) sl[warp] = lsum;
    __syncthreads();
    if (threadIdx.x == 0)
        *out_loss = (sl[0] + sl[1] + sl[2] + sl[3]) * (1.f / (2 * NI));
}

// ---------------- bag logits + softmax ----------------
__global__ void final_kernel(const float* __restrict__ Wbag, const float* __restrict__ bbag,
                             float* __restrict__ out)
{
    __shared__ float lg[2];
    int warp = threadIdx.x >> 5, lane = threadIdx.x & 31;
    if (warp < 2) {
        float s = 0.f;
        for (int k = lane; k < L_DIM; k += 32)
            s = fmaf(g_bag[warp * L_DIM + k], Wbag[warp * L_DIM + k], s);
#pragma unroll
        for (int o = 16; o; o >>= 1) s += __shfl_xor_sync(0xFFFFFFFFu, s, o);
        if (lane == 0) lg[warp] = s / g_Z[warp] + bbag[warp];
    }
    __syncthreads();
    if (threadIdx.x == 0) {
        float l0 = lg[0], l1 = lg[1];
        out[0] = l0; out[1] = l1;
        float m = fmaxf(l0, l1);
        float e0 = expf(l0 - m), e1 = expf(l1 - m);
        float s = e0 + e1;
        out[2] = e0 / s; out[3] = e1 / s;
    }
}

// ---------------- launch ----------------
extern "C" void kernel_launch(void* const* d_in, const int* in_sizes, int n_in,
                              void* d_out, int out_size)
{
    const int off = (n_in >= 14) ? 1 : 0;
    const float* x     = (const float*)d_in[0];
    const int*   label = (n_in >= 14) ? (const int*)d_in[1] : nullptr;
    const float* Wc    = (const float*)d_in[1 + off];
    const float* bc    = (const float*)d_in[2 + off];
    const float* Wv    = (const float*)d_in[3 + off];
    const float* bv    = (const float*)d_in[4 + off];
    const float* Wu    = (const float*)d_in[5 + off];
    const float* bu    = (const float*)d_in[6 + off];
    const float* Wa    = (const float*)d_in[7 + off];
    const float* ba    = (const float*)d_in[8 + off];
    const float* Winst = (const float*)d_in[9 + off];
    const float* binst = (const float*)d_in[10 + off];
    const float* Wbag  = (const float*)d_in[11 + off];
    const float* bbag  = (const float*)d_in[12 + off];
    float* out = (float*)d_out;

    void* p;
    cudaGetSymbolAddress(&p, g_xhi);  __nv_bfloat16* xhi = (__nv_bfloat16*)p;
    cudaGetSymbolAddress(&p, g_xlo);  __nv_bfloat16* xlo = (__nv_bfloat16*)p;
    cudaGetSymbolAddress(&p, g_hhi);  __nv_bfloat16* hhi = (__nv_bfloat16*)p;
    cudaGetSymbolAddress(&p, g_hlo);  __nv_bfloat16* hlo = (__nv_bfloat16*)p;
    cudaGetSymbolAddress(&p, g_wchi); __nv_bfloat16* wchi = (__nv_bfloat16*)p;
    cudaGetSymbolAddress(&p, g_wclo); __nv_bfloat16* wclo = (__nv_bfloat16*)p;
    cudaGetSymbolAddress(&p, g_wthi); __nv_bfloat16* wthi = (__nv_bfloat16*)p;
    cudaGetSymbolAddress(&p, g_wtlo); __nv_bfloat16* wtlo = (__nv_bfloat16*)p;
    cudaGetSymbolAddress(&p, g_bcat); float* bcat = (float*)p;

    cudaFuncSetAttribute(gemm_hmma<0>, cudaFuncAttributeMaxDynamicSharedMemorySize, GSMEM);
    cudaFuncSetAttribute(gemm_hmma<1>, cudaFuncAttributeMaxDynamicSharedMemorySize, GSMEM);

    init_kernel<<<1024, 256>>>();

    // conversions
    split_kernel<<<2048, 256>>>((const float4*)x, (__nv_bfloat162*)xhi, (__nv_bfloat162*)xlo,
                                (int)(((size_t)NROWS * E_DIM) / 4));
    split_kernel<<<256, 256>>>((const float4*)Wc, (__nv_bfloat162*)wchi, (__nv_bfloat162*)wclo,
                               (L_DIM * E_DIM) / 4);
    cat_kernel<<<(2 * D_DIM * L_DIM + 255) / 256, 256>>>(Wv, Wu, bv, bu, wthi, wtlo, bcat);

    // GEMM1: h = relu(x @ Wc^T + bc) -> h_hi/h_lo  [131072, 512]
    gemm_hmma<0><<<dim3(4, NROWS / 128), 256, GSMEM>>>(
        xhi, xlo, wchi, wclo, bc, hhi, hlo, nullptr, E_DIM, E_DIM / 64);

    // GEMM2+3 + attention fused: atomic partial A = (tanh*sigmoid) @ Wa^T into g_A
    gemm_hmma<1><<<dim3(4, NROWS / 128), 256, GSMEM>>>(
        hhi, hlo, wthi, wtlo, bcat, nullptr, nullptr, Wa, L_DIM, L_DIM / 64);

    // finalize: +ba, raw_attention, per-class max, label-class histogram
    finalize_kernel<<<NROWS / 256, 256>>>(ba, label, out + 4);

    // top-50 / bottom-50 of A[:, label]
    scan_kernel<<<1, 256>>>();
    cand_kernel<<<NROWS / 256, 256>>>(label);
    select_kernel<<<1, 256>>>();

    // instance loss
    loss_kernel<<<1, 128>>>(label, Winst, binst, out + 4 + 2 * NROWS);

    // softmax denominators + unnormalized bag_rep
    bag_kernel<<<512, 256>>>();

    // bag logits + softmax
    final_kernel<<<1, 64>>>(Wbag, bbag, out);
}

// round 6
// speedup vs baseline: 2.5039x; 1.0053x over previous
#include <cuda_runtime.h>
#include <cuda_bf16.h>
#include <math.h>
#include <stdint.h>

#define NROWS 131072
#define E_DIM 1024
#define L_DIM 512
#define D_DIM 256
#define NI    50

// ---------------- device scratch (allocation-free rule) ----------------
__device__ __nv_bfloat16 g_hhi[(size_t)NROWS * L_DIM];
__device__ __nv_bfloat16 g_hlo[(size_t)NROWS * L_DIM];
__device__ __nv_bfloat16 g_wchi[L_DIM * E_DIM];
__device__ __nv_bfloat16 g_wclo[L_DIM * E_DIM];
__device__ __nv_bfloat16 g_wthi[2 * D_DIM * L_DIM];
__device__ __nv_bfloat16 g_wtlo[2 * D_DIM * L_DIM];
__device__ float g_bcat[2 * D_DIM];
__device__ float g_A[(size_t)NROWS * 2];
__device__ int      g_hist[16384];
__device__ unsigned g_maxkey[2];
__device__ float    g_Z[2];
__device__ float    g_bag[2 * L_DIM];
__device__ int      g_binhi, g_binlo;
__device__ int      g_nhi, g_nlo;
__device__ float g_chv[NROWS]; __device__ int g_chi[NROWS];
__device__ float g_clv[NROWS]; __device__ int g_cli[NROWS];
__device__ int   g_inst[2 * NI];

// ---------------- PTX helpers ----------------
__device__ __forceinline__ uint32_t smem_u32(const void* p) {
    uint32_t a;
    asm("{ .reg .u64 t; cvta.to.shared.u64 t, %1; cvt.u32.u64 %0, t; }" : "=r"(a) : "l"(p));
    return a;
}
__device__ __forceinline__ void cp16(uint32_t s, const void* g) {
    asm volatile("cp.async.cg.shared.global [%0], [%1], 16;" :: "r"(s), "l"(g));
}
__device__ __forceinline__ void ldsm4(uint32_t* r, uint32_t addr) {
    asm volatile("ldmatrix.sync.aligned.m8n8.x4.shared.b16 {%0,%1,%2,%3}, [%4];"
                 : "=r"(r[0]), "=r"(r[1]), "=r"(r[2]), "=r"(r[3]) : "r"(addr));
}
__device__ __forceinline__ void mma16816(float* c, const uint32_t* a, const uint32_t* b) {
    asm volatile(
        "mma.sync.aligned.m16n8k16.row.col.f32.bf16.bf16.f32 "
        "{%0,%1,%2,%3}, {%4,%5,%6,%7}, {%8,%9}, {%0,%1,%2,%3};"
        : "+f"(c[0]), "+f"(c[1]), "+f"(c[2]), "+f"(c[3])
        : "r"(a[0]), "r"(a[1]), "r"(a[2]), "r"(a[3]), "r"(b[0]), "r"(b[1]));
}

// monotone float <-> uint key
__device__ __forceinline__ unsigned monoKey(float f) {
    unsigned u = __float_as_uint(f);
    return (u & 0x80000000u) ? ~u : (u | 0x80000000u);
}
__device__ __forceinline__ float monoDecode(unsigned k) {
    unsigned u = (k & 0x80000000u) ? (k & 0x7FFFFFFFu) : ~k;
    return __uint_as_float(u);
}

// ---------------- init ----------------
__global__ void init_kernel() {
    int i = blockIdx.x * blockDim.x + threadIdx.x;   // 1024*256 = 262144
    if (i < 2 * NROWS) g_A[i] = 0.f;
    if (i < 16384) g_hist[i] = 0;
    if (i < 2 * L_DIM) g_bag[i] = 0.f;
    if (i < 2) { g_Z[i] = 0.f; g_maxkey[i] = 0u; }
    if (i == 0) { g_nhi = 0; g_nlo = 0; }
}

// ---------------- fp32 -> bf16 hi/lo split (weights only now) ----------------
__global__ void split_kernel(const float4* __restrict__ in, __nv_bfloat162* __restrict__ hi,
                             __nv_bfloat162* __restrict__ lo, int n4) {
    int i = blockIdx.x * blockDim.x + threadIdx.x;
    int stride = gridDim.x * blockDim.x;
    for (; i < n4; i += stride) {
        float4 v = in[i];
        __nv_bfloat16 h0 = __float2bfloat16(v.x), h1 = __float2bfloat16(v.y);
        __nv_bfloat16 h2 = __float2bfloat16(v.z), h3 = __float2bfloat16(v.w);
        hi[2 * i]     = __halves2bfloat162(h0, h1);
        hi[2 * i + 1] = __halves2bfloat162(h2, h3);
        lo[2 * i]     = __halves2bfloat162(__float2bfloat16(v.x - __bfloat162float(h0)),
                                           __float2bfloat16(v.y - __bfloat162float(h1)));
        lo[2 * i + 1] = __halves2bfloat162(__float2bfloat16(v.z - __bfloat162float(h2)),
                                           __float2bfloat16(v.w - __bfloat162float(h3)));
    }
}

// build interleaved Wcat (row 2j = Wv[j], row 2j+1 = Wu[j]) split into hi/lo + bcat
__global__ void cat_kernel(const float* __restrict__ Wv, const float* __restrict__ Wu,
                           const float* __restrict__ bv, const float* __restrict__ bu,
                           __nv_bfloat16* __restrict__ whi, __nv_bfloat16* __restrict__ wlo,
                           float* __restrict__ bcat) {
    int i = blockIdx.x * blockDim.x + threadIdx.x;
    if (i < 2 * D_DIM * L_DIM) {
        int row = i >> 9, k = i & 511;
        int j = row >> 1, e = row & 1;
        float v = e ? Wu[j * L_DIM + k] : Wv[j * L_DIM + k];
        __nv_bfloat16 h = __float2bfloat16(v);
        whi[i] = h;
        wlo[i] = __float2bfloat16(v - __bfloat162float(h));
    }
    if (i < 2 * D_DIM) {
        int j = i >> 1, e = i & 1;
        bcat[i] = e ? bu[j] : bv[j];
    }
}

// ================= GEMM1: fused fp32->bf16 conversion, h = relu(x@Wc^T+bc) =================
// A (x fp32) loaded by LDG into regs, converted to bf16 hi/lo in smem (double-buffered).
// B (Wc hi/lo bf16) via 3-stage cp.async. D = Ahi*Bhi + Ahi*Blo + Alo*Bhi, fp32 acc.
#define G1_CONV 32768                 // one conv buffer: Ahi 16KB + Alo 16KB
#define G1_BST  32768                 // one B stage: Bhi 16KB + Blo 16KB
#define G1_SMEM (2 * G1_CONV + 3 * G1_BST)   // 64KB + 96KB = 160KB

__global__ __launch_bounds__(256, 1)
void gemm1_fused(const float* __restrict__ X,
                 const __nv_bfloat16* __restrict__ Bhi, const __nv_bfloat16* __restrict__ Blo,
                 const float* __restrict__ bias,
                 __nv_bfloat16* __restrict__ OutHi, __nv_bfloat16* __restrict__ OutLo)
{
    extern __shared__ __align__(1024) unsigned char dsm[];
    const int tid  = threadIdx.x;
    const int bn   = blockIdx.x;     // 0..3
    const int bm   = blockIdx.y;
    const int wid  = tid >> 5, lane = tid & 31;
    const int wm   = wid & 3, wn = wid >> 2;
    const int m0   = bm * 128, n0 = bn * 128;
    const int K = E_DIM, NC = E_DIM / 64;     // 16
    const uint32_t sb = smem_u32(dsm);
    const uint32_t convBase = sb;             // conv[c] at sb + c*G1_CONV
    const uint32_t bBase    = sb + 2 * G1_CONV;

    auto loadBtile = [&](uint32_t dst, const __nv_bfloat16* p, int k0) {
#pragma unroll
        for (int it = 0; it < 4; it++) {
            int q = tid + it * 256;
            int row = q >> 3;
            int inner = (q & 7) << 4;
            uint32_t off = (uint32_t)(row * 128 + (inner ^ ((row & 7) << 4)));
            cp16(dst + off, (const char*)p + ((size_t)(n0 + row) * K + k0) * 2 + inner);
        }
    };
    auto loadB = [&](int s, int k0) {
        uint32_t st = bBase + s * G1_BST;
        loadBtile(st, Bhi, k0);
        loadBtile(st + 16384, Blo, k0);
        asm volatile("cp.async.commit_group;" ::: "memory");
    };

    // x register staging + conversion
    float4 xr[8];
    auto ldgX = [&](int k0) {
#pragma unroll
        for (int j = 0; j < 8; j++) {
            int f = j * 256 + tid;
            xr[j] = *(const float4*)(X + (size_t)(m0 + (f >> 4)) * K + k0 + (f & 15) * 4);
        }
    };
    auto cvtX = [&](int c) {
        unsigned char* hiP = dsm + c * G1_CONV;
        unsigned char* loP = hiP + 16384;
#pragma unroll
        for (int j = 0; j < 8; j++) {
            int f = j * 256 + tid;
            int row = f >> 4;
            uint32_t colb = (uint32_t)((f & 15) * 8);
            uint32_t off = (uint32_t)(row * 128) + (colb ^ ((uint32_t)(row & 7) << 4));
            float4 v = xr[j];
            __nv_bfloat16 h0 = __float2bfloat16(v.x), h1 = __float2bfloat16(v.y);
            __nv_bfloat16 h2 = __float2bfloat16(v.z), h3 = __float2bfloat16(v.w);
            __nv_bfloat162 ph[2] = { __halves2bfloat162(h0, h1), __halves2bfloat162(h2, h3) };
            __nv_bfloat162 pl[2] = {
                __halves2bfloat162(__float2bfloat16(v.x - __bfloat162float(h0)),
                                   __float2bfloat16(v.y - __bfloat162float(h1))),
                __halves2bfloat162(__float2bfloat16(v.z - __bfloat162float(h2)),
                                   __float2bfloat16(v.w - __bfloat162float(h3))) };
            *(uint2*)(hiP + off) = *(uint2*)ph;
            *(uint2*)(loP + off) = *(uint2*)pl;
        }
    };

    // ldmatrix address pieces
    const int aRow = wm * 32 + (lane & 15);
    const uint32_t aK  = ((lane >> 4) & 1) * 16;
    const uint32_t aXr = (uint32_t)((aRow & 7) << 4);
    const int bRow = wn * 64 + (lane & 7) + (((lane >> 4) & 1) << 3);
    const uint32_t bK  = ((lane >> 3) & 1) * 16;
    const uint32_t bXr = (uint32_t)((bRow & 7) << 4);

    float acc[2][8][4];
#pragma unroll
    for (int mi = 0; mi < 2; mi++)
#pragma unroll
        for (int ni = 0; ni < 8; ni++)
#pragma unroll
            for (int e = 0; e < 4; e++) acc[mi][ni][e] = 0.f;

    uint32_t ah[2][2][4], al[2][2][4], bh[2][4][4], bl[2][4][4];

    // prologue
    loadB(0, 0);
    loadB(1, 64);
    ldgX(0);
    cvtX(0);
    ldgX(64);

    for (int i = 0; i < NC; i++) {
        if (i + 1 < NC) asm volatile("cp.async.wait_group 1;" ::: "memory");
        else            asm volatile("cp.async.wait_group 0;" ::: "memory");
        __syncthreads();
        if (i + 2 < NC) loadB((i + 2) % 3, (i + 2) * 64);
        if (i + 1 < NC) cvtX((i + 1) & 1);      // convert next stage (xr holds it)
        if (i + 2 < NC) ldgX((i + 2) * 64);     // prefetch stage i+2 into regs

        const uint32_t sAh = convBase + (i & 1) * G1_CONV, sAl = sAh + 16384;
        const uint32_t st  = bBase + (i % 3) * G1_BST;
        const uint32_t sBh = st, sBl = st + 16384;

        auto ldFrags = [&](int buf, int ks) {
            const uint32_t ak = (uint32_t)(ks * 32) + aK;
            const uint32_t bk = (uint32_t)(ks * 32) + bK;
#pragma unroll
            for (int mi = 0; mi < 2; mi++) {
                uint32_t ro = (uint32_t)((aRow + mi * 16) * 128) + (ak ^ aXr);
                ldsm4(ah[buf][mi], sAh + ro);
                ldsm4(al[buf][mi], sAl + ro);
            }
#pragma unroll
            for (int nj = 0; nj < 4; nj++) {
                uint32_t ro = (uint32_t)((bRow + nj * 16) * 128) + (bk ^ bXr);
                ldsm4(bh[buf][nj], sBh + ro);
                ldsm4(bl[buf][nj], sBl + ro);
            }
        };

        ldFrags(0, 0);
#pragma unroll
        for (int ks = 0; ks < 4; ks++) {
            const int cur = ks & 1;
            if (ks < 3) ldFrags(cur ^ 1, ks + 1);
#pragma unroll
            for (int mi = 0; mi < 2; mi++)
#pragma unroll
                for (int nj = 0; nj < 4; nj++) {
                    mma16816(acc[mi][2 * nj],     ah[cur][mi], &bh[cur][nj][0]);
                    mma16816(acc[mi][2 * nj + 1], ah[cur][mi], &bh[cur][nj][2]);
                }
#pragma unroll
            for (int mi = 0; mi < 2; mi++)
#pragma unroll
                for (int nj = 0; nj < 4; nj++) {
                    mma16816(acc[mi][2 * nj],     ah[cur][mi], &bl[cur][nj][0]);
                    mma16816(acc[mi][2 * nj + 1], ah[cur][mi], &bl[cur][nj][2]);
                }
#pragma unroll
            for (int mi = 0; mi < 2; mi++)
#pragma unroll
                for (int nj = 0; nj < 4; nj++) {
                    mma16816(acc[mi][2 * nj],     al[cur][mi], &bh[cur][nj][0]);
                    mma16816(acc[mi][2 * nj + 1], al[cur][mi], &bh[cur][nj][2]);
                }
        }
    }

    // epilogue: relu(acc+bias) -> hi/lo bf16
    const int rBase = m0 + wm * 32 + (lane >> 2);
    const int cBase = n0 + wn * 64 + 2 * (lane & 3);
#pragma unroll
    for (int mi = 0; mi < 2; mi++) {
#pragma unroll
        for (int ni = 0; ni < 8; ni++) {
            const int c = cBase + ni * 8;
            const float b0 = bias[c], b1 = bias[c + 1];
#pragma unroll
            for (int half = 0; half < 2; half++) {
                const int r = rBase + mi * 16 + half * 8;
                float v0 = fmaxf(acc[mi][ni][2 * half]     + b0, 0.f);
                float v1 = fmaxf(acc[mi][ni][2 * half + 1] + b1, 0.f);
                __nv_bfloat16 h0 = __float2bfloat16(v0), h1 = __float2bfloat16(v1);
                size_t o = ((size_t)r * 512 + c) >> 1;
                ((__nv_bfloat162*)OutHi)[o] = __halves2bfloat162(h0, h1);
                ((__nv_bfloat162*)OutLo)[o] = __halves2bfloat162(
                    __float2bfloat16(v0 - __bfloat162float(h0)),
                    __float2bfloat16(v1 - __bfloat162float(h1)));
            }
        }
    }
}

// ================= GEMM2 (+fused attention projection), as before =================
#define TILE_BYTES 16384
#define STAGE_BYTES (4 * TILE_BYTES)
#define NSTAGE 3
#define GSMEM (NSTAGE * STAGE_BYTES)

__global__ __launch_bounds__(256, 1)
void gemm2_hmma(const __nv_bfloat16* __restrict__ Ahi, const __nv_bfloat16* __restrict__ Alo,
                const __nv_bfloat16* __restrict__ Bhi, const __nv_bfloat16* __restrict__ Blo,
                const float* __restrict__ bias, const float* __restrict__ Wa,
                int K, int NC)
{
    extern __shared__ __align__(1024) unsigned char dsm[];
    const int tid  = threadIdx.x;
    const int bn   = blockIdx.x;
    const int bm   = blockIdx.y;
    const int wid  = tid >> 5, lane = tid & 31;
    const int wm   = wid & 3, wn = wid >> 2;
    const int m0   = bm * 128, n0 = bn * 128;
    const uint32_t sb = smem_u32(dsm);

    auto loadTile = [&](uint32_t dst, const __nv_bfloat16* p, int gr0, int k0) {
#pragma unroll
        for (int it = 0; it < 4; it++) {
            int q = tid + it * 256;
            int row = q >> 3;
            int inner = (q & 7) << 4;
            uint32_t off = (uint32_t)(row * 128 + (inner ^ ((row & 7) << 4)));
            cp16(dst + off, (const char*)p + ((size_t)(gr0 + row) * K + k0) * 2 + inner);
        }
    };
    auto loadStage = [&](int s, int k0) {
        uint32_t st = sb + s * STAGE_BYTES;
        loadTile(st,                  Ahi, m0, k0);
        loadTile(st + TILE_BYTES,     Alo, m0, k0);
        loadTile(st + 2 * TILE_BYTES, Bhi, n0, k0);
        loadTile(st + 3 * TILE_BYTES, Blo, n0, k0);
        asm volatile("cp.async.commit_group;" ::: "memory");
    };

    const int aRow = wm * 32 + (lane & 15);
    const uint32_t aK  = ((lane >> 4) & 1) * 16;
    const uint32_t aXr = (uint32_t)((aRow & 7) << 4);
    const int bRow = wn * 64 + (lane & 7) + (((lane >> 4) & 1) << 3);
    const uint32_t bK  = ((lane >> 3) & 1) * 16;
    const uint32_t bXr = (uint32_t)((bRow & 7) << 4);

    float acc[2][8][4];
#pragma unroll
    for (int mi = 0; mi < 2; mi++)
#pragma unroll
        for (int ni = 0; ni < 8; ni++)
#pragma unroll
            for (int e = 0; e < 4; e++) acc[mi][ni][e] = 0.f;

    uint32_t ah[2][2][4], al[2][2][4], bh[2][4][4], bl[2][4][4];

    loadStage(0, 0);
    loadStage(1, 64);

    for (int i = 0; i < NC; i++) {
        const int s = i % NSTAGE;
        if (i + 1 < NC) asm volatile("cp.async.wait_group 1;" ::: "memory");
        else            asm volatile("cp.async.wait_group 0;" ::: "memory");
        __syncthreads();
        if (i + 2 < NC) loadStage((i + 2) % NSTAGE, (i + 2) * 64);

        const uint32_t st  = sb + s * STAGE_BYTES;
        const uint32_t sAh = st, sAl = st + TILE_BYTES;
        const uint32_t sBh = st + 2 * TILE_BYTES, sBl = st + 3 * TILE_BYTES;

        auto ldFrags = [&](int buf, int ks) {
            const uint32_t ak = (uint32_t)(ks * 32) + aK;
            const uint32_t bk = (uint32_t)(ks * 32) + bK;
#pragma unroll
            for (int mi = 0; mi < 2; mi++) {
                uint32_t ro = (uint32_t)((aRow + mi * 16) * 128) + (ak ^ aXr);
                ldsm4(ah[buf][mi], sAh + ro);
                ldsm4(al[buf][mi], sAl + ro);
            }
#pragma unroll
            for (int nj = 0; nj < 4; nj++) {
                uint32_t ro = (uint32_t)((bRow + nj * 16) * 128) + (bk ^ bXr);
                ldsm4(bh[buf][nj], sBh + ro);
                ldsm4(bl[buf][nj], sBl + ro);
            }
        };

        ldFrags(0, 0);
#pragma unroll
        for (int ks = 0; ks < 4; ks++) {
            const int cur = ks & 1;
            if (ks < 3) ldFrags(cur ^ 1, ks + 1);
#pragma unroll
            for (int mi = 0; mi < 2; mi++)
#pragma unroll
                for (int nj = 0; nj < 4; nj++) {
                    mma16816(acc[mi][2 * nj],     ah[cur][mi], &bh[cur][nj][0]);
                    mma16816(acc[mi][2 * nj + 1], ah[cur][mi], &bh[cur][nj][2]);
                }
#pragma unroll
            for (int mi = 0; mi < 2; mi++)
#pragma unroll
                for (int nj = 0; nj < 4; nj++) {
                    mma16816(acc[mi][2 * nj],     ah[cur][mi], &bl[cur][nj][0]);
                    mma16816(acc[mi][2 * nj + 1], ah[cur][mi], &bl[cur][nj][2]);
                }
#pragma unroll
            for (int mi = 0; mi < 2; mi++)
#pragma unroll
                for (int nj = 0; nj < 4; nj++) {
                    mma16816(acc[mi][2 * nj],     al[cur][mi], &bh[cur][nj][0]);
                    mma16816(acc[mi][2 * nj + 1], al[cur][mi], &bh[cur][nj][2]);
                }
        }
    }

    // fused gated-attention projection epilogue
    const int rBase = m0 + wm * 32 + (lane >> 2);
    const int cBase = n0 + wn * 64 + 2 * (lane & 3);
#pragma unroll
    for (int mi = 0; mi < 2; mi++) {
#pragma unroll
        for (int half = 0; half < 2; half++) {
            const int r = rBase + mi * 16 + half * 8;
            float s0 = 0.f, s1 = 0.f;
#pragma unroll
            for (int ni = 0; ni < 8; ni++) {
                const int c = cBase + ni * 8;
                float v0 = acc[mi][ni][2 * half]     + bias[c];
                float v1 = acc[mi][ni][2 * half + 1] + bias[c + 1];
                float gg = tanhf(v0) / (1.f + expf(-v1));
                const int gc = c >> 1;
                s0 = fmaf(gg, Wa[gc], s0);
                s1 = fmaf(gg, Wa[D_DIM + gc], s1);
            }
            s0 += __shfl_xor_sync(0xFFFFFFFFu, s0, 1);
            s0 += __shfl_xor_sync(0xFFFFFFFFu, s0, 2);
            s1 += __shfl_xor_sync(0xFFFFFFFFu, s1, 1);
            s1 += __shfl_xor_sync(0xFFFFFFFFu, s1, 2);
            if ((lane & 3) == 0) {
                atomicAdd(&g_A[2 * r],     s0);
                atomicAdd(&g_A[2 * r + 1], s1);
            }
        }
    }
}

// ---------------- finalize: +ba, raw_attention out, per-class max, histogram ----------------
__global__ void finalize_kernel(const float* __restrict__ ba, const int* __restrict__ labelPtr,
                                float* __restrict__ out_att)
{
    __shared__ unsigned sk0, sk1;
    if (threadIdx.x == 0) { sk0 = 0u; sk1 = 0u; }
    __syncthreads();
    int i = blockIdx.x * blockDim.x + threadIdx.x;
    int lab = labelPtr ? *labelPtr : 0;
    float a0 = g_A[2 * i] + ba[0];
    float a1 = g_A[2 * i + 1] + ba[1];
    g_A[2 * i] = a0; g_A[2 * i + 1] = a1;
    out_att[i] = a0;
    out_att[NROWS + i] = a1;
    atomicMax(&sk0, monoKey(a0));
    atomicMax(&sk1, monoKey(a1));
    float sel = lab ? a1 : a0;
    atomicAdd(&g_hist[monoKey(sel) >> 18], 1);
    __syncthreads();
    if (threadIdx.x == 0) {
        atomicMax(&g_maxkey[0], sk0);
        atomicMax(&g_maxkey[1], sk1);
    }
}

// ---------------- fused softmax-weighted bag accumulation (h = hi+lo) ----------------
__global__ void bag_kernel()
{
    const int t = threadIdx.x;
    const int rowsPerBlock = NROWS / gridDim.x;
    const int r0 = blockIdx.x * rowsPerBlock;
    const float m0 = monoDecode(g_maxkey[0]);
    const float m1 = monoDecode(g_maxkey[1]);

    float a00 = 0.f, a01 = 0.f, a10 = 0.f, a11 = 0.f;
    float z0 = 0.f, z1 = 0.f;
    for (int r = r0; r < r0 + rowsPerBlock; r++) {
        float w0 = expf(g_A[2 * r]     - m0);
        float w1 = expf(g_A[2 * r + 1] - m1);
        const __nv_bfloat162* hh = (const __nv_bfloat162*)(g_hhi + (size_t)r * L_DIM);
        const __nv_bfloat162* hl = (const __nv_bfloat162*)(g_hlo + (size_t)r * L_DIM);
        __nv_bfloat162 a2 = hh[t], b2 = hl[t];
        float v0 = __low2float(a2)  + __low2float(b2);
        float v1 = __high2float(a2) + __high2float(b2);
        a00 = fmaf(w0, v0, a00); a01 = fmaf(w0, v1, a01);
        a10 = fmaf(w1, v0, a10); a11 = fmaf(w1, v1, a11);
        if (t == 0) { z0 += w0; z1 += w1; }
    }
    atomicAdd(&g_bag[2 * t], a00);
    atomicAdd(&g_bag[2 * t + 1], a01);
    atomicAdd(&g_bag[L_DIM + 2 * t], a10);
    atomicAdd(&g_bag[L_DIM + 2 * t + 1], a11);
    if (t == 0) { atomicAdd(&g_Z[0], z0); atomicAdd(&g_Z[1], z1); }
}

// ---------------- top-k machinery ----------------
__global__ void scan_kernel()
{
    __shared__ int csum[256];
    int t = threadIdx.x;
    int s = 0;
    for (int b = t * 64; b < t * 64 + 64; b++) s += g_hist[b];
    csum[t] = s;
    __syncthreads();
    if (t == 0) {
        int cum = 0, binhi = 0;
        for (int c = 255; c >= 0; c--) {
            if (cum + csum[c] >= NI) {
                for (int b = c * 64 + 63; b >= c * 64; b--) {
                    cum += g_hist[b];
                    if (cum >= NI) { binhi = b; break; }
                }
                break;
            }
            cum += csum[c];
        }
        g_binhi = binhi;
        cum = 0; int binlo = 16383;
        for (int c = 0; c < 256; c++) {
            if (cum + csum[c] >= NI) {
                for (int b = c * 64; b < c * 64 + 64; b++) {
                    cum += g_hist[b];
                    if (cum >= NI) { binlo = b; break; }
                }
                break;
            }
            cum += csum[c];
        }
        g_binlo = binlo;
        g_nhi = 0; g_nlo = 0;
    }
}

__global__ void cand_kernel(const int* __restrict__ labelPtr)
{
    int lab = labelPtr ? *labelPtr : 0;
    int binhi = g_binhi, binlo = g_binlo;
    for (int i = blockIdx.x * blockDim.x + threadIdx.x; i < NROWS; i += gridDim.x * blockDim.x) {
        float v = g_A[2 * i + lab];
        unsigned key = monoKey(v) >> 18;
        if ((int)key >= binhi) {
            int p = atomicAdd(&g_nhi, 1);
            g_chv[p] = v; g_chi[p] = i;
        }
        if ((int)key <= binlo) {
            int p = atomicAdd(&g_nlo, 1);
            g_clv[p] = v; g_cli[p] = i;
        }
    }
}

__global__ void select_kernel()
{
    __shared__ float sv[256];
    __shared__ int   si[256];
    __shared__ int   sp[256];
    const int t = threadIdx.x;
    const float NEG_INF = __int_as_float(0xFF800000);
    const float POS_INF = __int_as_float(0x7F800000);
    int nhi = g_nhi, nlo = g_nlo;

    for (int it = 0; it < NI; it++) {
        float bv = NEG_INF; int bi = 0x7FFFFFFF; int bp = -1;
        for (int p = t; p < nhi; p += 256) {
            float v = g_chv[p]; int idx = g_chi[p];
            if (v > bv || (v == bv && idx < bi)) { bv = v; bi = idx; bp = p; }
        }
        sv[t] = bv; si[t] = bi; sp[t] = bp;
        __syncthreads();
        for (int s = 128; s; s >>= 1) {
            if (t < s) {
                if (sv[t + s] > sv[t] || (sv[t + s] == sv[t] && si[t + s] < si[t])) {
                    sv[t] = sv[t + s]; si[t] = si[t + s]; sp[t] = sp[t + s];
                }
            }
            __syncthreads();
        }
        if (t == 0) { g_inst[it] = si[0]; g_chv[sp[0]] = NEG_INF; }
        __syncthreads();
    }
    for (int it = 0; it < NI; it++) {
        float bv = POS_INF; int bi = 0x7FFFFFFF; int bp = -1;
        for (int p = t; p < nlo; p += 256) {
            float v = g_clv[p]; int idx = g_cli[p];
            if (v < bv || (v == bv && idx < bi)) { bv = v; bi = idx; bp = p; }
        }
        sv[t] = bv; si[t] = bi; sp[t] = bp;
        __syncthreads();
        for (int s = 128; s; s >>= 1) {
            if (t < s) {
                if (sv[t + s] < sv[t] || (sv[t + s] == sv[t] && si[t + s] < si[t])) {
                    sv[t] = sv[t + s]; si[t] = si[t + s]; sp[t] = sp[t + s];
                }
            }
            __syncthreads();
        }
        if (t == 0) { g_inst[NI + it] = si[0]; g_clv[sp[0]] = POS_INF; }
        __syncthreads();
    }
}

// ---------------- instance loss ----------------
__global__ void loss_kernel(const int* __restrict__ labelPtr,
                            const float* __restrict__ Winst, const float* __restrict__ binst,
                            float* __restrict__ out_loss)
{
    __shared__ float sl[4];
    int lab = labelPtr ? *labelPtr : 0;
    const float* W0 = Winst + ((size_t)lab * 2 + 0) * L_DIM;
    const float* W1 = Winst + ((size_t)lab * 2 + 1) * L_DIM;
    float b0 = binst[lab * 2], b1 = binst[lab * 2 + 1];

    int warp = threadIdx.x >> 5, lane = threadIdx.x & 31;
    float lsum = 0.f;
    for (int r = warp; r < 2 * NI; r += 4) {
        const __nv_bfloat16* hh = g_hhi + (size_t)g_inst[r] * L_DIM;
        const __nv_bfloat16* hl = g_hlo + (size_t)g_inst[r] * L_DIM;
        float s0 = 0.f, s1 = 0.f;
        for (int k = lane; k < L_DIM; k += 32) {
            float v = __bfloat162float(hh[k]) + __bfloat162float(hl[k]);
            s0 = fmaf(v, W0[k], s0);
            s1 = fmaf(v, W1[k], s1);
        }
#pragma unroll
        for (int o = 16; o; o >>= 1) {
            s0 += __shfl_xor_sync(0xFFFFFFFFu, s0, o);
            s1 += __shfl_xor_sync(0xFFFFFFFFu, s1, o);
        }
        if (lane == 0) {
            float l0 = s0 + b0, l1 = s1 + b1;
            int tgt = (r < NI) ? 1 : 0;
            float u0 = l0 + ((tgt != 0) ? 1.f : 0.f);
            float u1 = l1 + ((tgt != 1) ? 1.f : 0.f);
            float m = fmaxf(u0, u1);
            float lse = m + logf(expf(u0 - m) + expf(u1 - m));
            float sy = (tgt == 0) ? l0 : l1;
            lsum += lse - sy;
        }
    }
    if (lane == 0) sl[warp] = lsum;
    __syncthreads();
    if (threadIdx.x == 0)
        *out_loss = (sl[0] + sl[1] + sl[2] + sl[3]) * (1.f / (2 * NI));
}

// ---------------- bag logits + softmax ----------------
__global__ void final_kernel(const float* __restrict__ Wbag, const float* __restrict__ bbag,
                             float* __restrict__ out)
{
    __shared__ float lg[2];
    int warp = threadIdx.x >> 5, lane = threadIdx.x & 31;
    if (warp < 2) {
        float s = 0.f;
        for (int k = lane; k < L_DIM; k += 32)
            s = fmaf(g_bag[warp * L_DIM + k], Wbag[warp * L_DIM + k], s);
#pragma unroll
        for (int o = 16; o; o >>= 1) s += __shfl_xor_sync(0xFFFFFFFFu, s, o);
        if (lane == 0) lg[warp] = s / g_Z[warp] + bbag[warp];
    }
    __syncthreads();
    if (threadIdx.x == 0) {
        float l0 = lg[0], l1 = lg[1];
        out[0] = l0; out[1] = l1;
        float m = fmaxf(l0, l1);
        float e0 = expf(l0 - m), e1 = expf(l1 - m);
        float s = e0 + e1;
        out[2] = e0 / s; out[3] = e1 / s;
    }
}

// ---------------- launch ----------------
extern "C" void kernel_launch(void* const* d_in, const int* in_sizes, int n_in,
                              void* d_out, int out_size)
{
    const int off = (n_in >= 14) ? 1 : 0;
    const float* x     = (const float*)d_in[0];
    const int*   label = (n_in >= 14) ? (const int*)d_in[1] : nullptr;
    const float* Wc    = (const float*)d_in[1 + off];
    const float* bc    = (const float*)d_in[2 + off];
    const float* Wv    = (const float*)d_in[3 + off];
    const float* bv    = (const float*)d_in[4 + off];
    const float* Wu    = (const float*)d_in[5 + off];
    const float* bu    = (const float*)d_in[6 + off];
    const float* Wa    = (const float*)d_in[7 + off];
    const float* ba    = (const float*)d_in[8 + off];
    const float* Winst = (const float*)d_in[9 + off];
    const float* binst = (const float*)d_in[10 + off];
    const float* Wbag  = (const float*)d_in[11 + off];
    const float* bbag  = (const float*)d_in[12 + off];
    float* out = (float*)d_out;

    void* p;
    cudaGetSymbolAddress(&p, g_hhi);  __nv_bfloat16* hhi = (__nv_bfloat16*)p;
    cudaGetSymbolAddress(&p, g_hlo);  __nv_bfloat16* hlo = (__nv_bfloat16*)p;
    cudaGetSymbolAddress(&p, g_wchi); __nv_bfloat16* wchi = (__nv_bfloat16*)p;
    cudaGetSymbolAddress(&p, g_wclo); __nv_bfloat16* wclo = (__nv_bfloat16*)p;
    cudaGetSymbolAddress(&p, g_wthi); __nv_bfloat16* wthi = (__nv_bfloat16*)p;
    cudaGetSymbolAddress(&p, g_wtlo); __nv_bfloat16* wtlo = (__nv_bfloat16*)p;
    cudaGetSymbolAddress(&p, g_bcat); float* bcat = (float*)p;

    cudaFuncSetAttribute(gemm1_fused, cudaFuncAttributeMaxDynamicSharedMemorySize, G1_SMEM);
    cudaFuncSetAttribute(gemm2_hmma,  cudaFuncAttributeMaxDynamicSharedMemorySize, GSMEM);

    // launch #1..#3: prep (gemm1 lands at launch #4 for the ncu capture window)
    init_kernel<<<1024, 256>>>();
    split_kernel<<<256, 256>>>((const float4*)Wc, (__nv_bfloat162*)wchi, (__nv_bfloat162*)wclo,
                               (L_DIM * E_DIM) / 4);
    cat_kernel<<<(2 * D_DIM * L_DIM + 255) / 256, 256>>>(Wv, Wu, bv, bu, wthi, wtlo, bcat);

    // GEMM1 (launch #4): h = relu(x @ Wc^T + bc), fp32 x converted in-kernel
    gemm1_fused<<<dim3(4, NROWS / 128), 256, G1_SMEM>>>(x, wchi, wclo, bc, hhi, hlo);

    // GEMM2+3 + attention fused: atomic partial A = (tanh*sigmoid) @ Wa^T into g_A
    gemm2_hmma<<<dim3(4, NROWS / 128), 256, GSMEM>>>(
        hhi, hlo, wthi, wtlo, bcat, Wa, L_DIM, L_DIM / 64);

    // finalize: +ba, raw_attention, per-class max, label-class histogram
    finalize_kernel<<<NROWS / 256, 256>>>(ba, label, out + 4);

    // top-50 / bottom-50 of A[:, label]
    scan_kernel<<<1, 256>>>();
    cand_kernel<<<NROWS / 256, 256>>>(label);
    select_kernel<<<1, 256>>>();

    // instance loss
    loss_kernel<<<1, 128>>>(label, Winst, binst, out + 4 + 2 * NROWS);

    // softmax denominators + unnormalized bag_rep
    bag_kernel<<<512, 256>>>();

    // bag logits + softmax
    final_kernel<<<1, 64>>>(Wbag, bbag, out);
}

// round 7
// speedup vs baseline: 2.6640x; 1.0639x over previous
#include <cuda_runtime.h>
#include <cuda_bf16.h>
#include <math.h>
#include <stdint.h>

#define NROWS 131072
#define E_DIM 1024
#define L_DIM 512
#define D_DIM 256
#define NI    50

// ---------------- device scratch (allocation-free rule) ----------------
__device__ __nv_bfloat16 g_hhi[(size_t)NROWS * L_DIM];
__device__ __nv_bfloat16 g_hlo[(size_t)NROWS * L_DIM];
__device__ __nv_bfloat16 g_wchi[L_DIM * E_DIM];
__device__ __nv_bfloat16 g_wclo[L_DIM * E_DIM];
__device__ __nv_bfloat16 g_wthi[2 * D_DIM * L_DIM];
__device__ __nv_bfloat16 g_wtlo[2 * D_DIM * L_DIM];
__device__ float g_bcat[2 * D_DIM];
__device__ float g_A[(size_t)NROWS * 2];
__device__ int      g_hist[16384];
__device__ unsigned g_maxkey[2];
__device__ float    g_Z[2];
__device__ float    g_bag[2 * L_DIM];
__device__ int      g_binhi, g_binlo;
__device__ int      g_nhi, g_nlo;
__device__ float g_chv[NROWS]; __device__ int g_chi[NROWS];
__device__ float g_clv[NROWS]; __device__ int g_cli[NROWS];
__device__ int   g_inst[2 * NI];

// ---------------- PTX helpers ----------------
__device__ __forceinline__ uint32_t smem_u32(const void* p) {
    uint32_t a;
    asm("{ .reg .u64 t; cvta.to.shared.u64 t, %1; cvt.u32.u64 %0, t; }" : "=r"(a) : "l"(p));
    return a;
}
__device__ __forceinline__ void cp16(uint32_t s, const void* g) {
    asm volatile("cp.async.cg.shared.global [%0], [%1], 16;" :: "r"(s), "l"(g));
}
__device__ __forceinline__ void ldsm4(uint32_t* r, uint32_t addr) {
    asm volatile("ldmatrix.sync.aligned.m8n8.x4.shared.b16 {%0,%1,%2,%3}, [%4];"
                 : "=r"(r[0]), "=r"(r[1]), "=r"(r[2]), "=r"(r[3]) : "r"(addr));
}
__device__ __forceinline__ void mma16816(float* c, const uint32_t* a, const uint32_t* b) {
    asm volatile(
        "mma.sync.aligned.m16n8k16.row.col.f32.bf16.bf16.f32 "
        "{%0,%1,%2,%3}, {%4,%5,%6,%7}, {%8,%9}, {%0,%1,%2,%3};"
        : "+f"(c[0]), "+f"(c[1]), "+f"(c[2]), "+f"(c[3])
        : "r"(a[0]), "r"(a[1]), "r"(a[2]), "r"(a[3]), "r"(b[0]), "r"(b[1]));
}

// monotone float <-> uint key
__device__ __forceinline__ unsigned monoKey(float f) {
    unsigned u = __float_as_uint(f);
    return (u & 0x80000000u) ? ~u : (u | 0x80000000u);
}
__device__ __forceinline__ float monoDecode(unsigned k) {
    unsigned u = (k & 0x80000000u) ? (k & 0x7FFFFFFFu) : ~k;
    return __uint_as_float(u);
}

__device__ __forceinline__ uint32_t pack2(float a, float b) {
    __nv_bfloat162 t = __halves2bfloat162(__float2bfloat16(a), __float2bfloat16(b));
    return *(uint32_t*)&t;
}

// ---------------- init ----------------
__global__ void init_kernel() {
    int i = blockIdx.x * blockDim.x + threadIdx.x;
    if (i < 2 * NROWS) g_A[i] = 0.f;
    if (i < 16384) g_hist[i] = 0;
    if (i < 2 * L_DIM) g_bag[i] = 0.f;
    if (i < 2) { g_Z[i] = 0.f; g_maxkey[i] = 0u; }
    if (i == 0) { g_nhi = 0; g_nlo = 0; }
}

// ---------------- fp32 -> bf16 hi/lo split (weights only) ----------------
__global__ void split_kernel(const float4* __restrict__ in, __nv_bfloat162* __restrict__ hi,
                             __nv_bfloat162* __restrict__ lo, int n4) {
    int i = blockIdx.x * blockDim.x + threadIdx.x;
    int stride = gridDim.x * blockDim.x;
    for (; i < n4; i += stride) {
        float4 v = in[i];
        __nv_bfloat16 h0 = __float2bfloat16(v.x), h1 = __float2bfloat16(v.y);
        __nv_bfloat16 h2 = __float2bfloat16(v.z), h3 = __float2bfloat16(v.w);
        hi[2 * i]     = __halves2bfloat162(h0, h1);
        hi[2 * i + 1] = __halves2bfloat162(h2, h3);
        lo[2 * i]     = __halves2bfloat162(__float2bfloat16(v.x - __bfloat162float(h0)),
                                           __float2bfloat16(v.y - __bfloat162float(h1)));
        lo[2 * i + 1] = __halves2bfloat162(__float2bfloat16(v.z - __bfloat162float(h2)),
                                           __float2bfloat16(v.w - __bfloat162float(h3)));
    }
}

// build interleaved Wcat (row 2j = Wv[j], row 2j+1 = Wu[j]) hi/lo + bcat
__global__ void cat_kernel(const float* __restrict__ Wv, const float* __restrict__ Wu,
                           const float* __restrict__ bv, const float* __restrict__ bu,
                           __nv_bfloat16* __restrict__ whi, __nv_bfloat16* __restrict__ wlo,
                           float* __restrict__ bcat) {
    int i = blockIdx.x * blockDim.x + threadIdx.x;
    if (i < 2 * D_DIM * L_DIM) {
        int row = i >> 9, k = i & 511;
        int j = row >> 1, e = row & 1;
        float v = e ? Wu[j * L_DIM + k] : Wv[j * L_DIM + k];
        __nv_bfloat16 h = __float2bfloat16(v);
        whi[i] = h;
        wlo[i] = __float2bfloat16(v - __bfloat162float(h));
    }
    if (i < 2 * D_DIM) {
        int j = i >> 1, e = i & 1;
        bcat[i] = e ? bu[j] : bv[j];
    }
}

// ================= shared GEMM machinery: BK=32, 64B smem rows, 2 CTA/SM =================
// tile = 128 rows x 32 bf16 = 8KB, row stride 64B, swizzle: col16 ^= (row>>1)&3
#define TB32 8192

// GEMM1: A = x fp32 (in-kernel conversion), B = Wc hi/lo.  smem: conv 2x16KB + B 3x16KB = 80KB
#define G1_SMEM (2 * 16384 + 3 * 16384)
// GEMM2: 4 bf16 tiles per stage (Ahi,Alo,Bhi,Blo) x 3 stages = 96KB
#define G2_SMEM (3 * 4 * TB32)

__global__ __launch_bounds__(256, 2)
void gemm1_fused(const float* __restrict__ X,
                 const __nv_bfloat16* __restrict__ Bhi, const __nv_bfloat16* __restrict__ Blo,
                 const float* __restrict__ bias,
                 __nv_bfloat16* __restrict__ OutHi, __nv_bfloat16* __restrict__ OutLo)
{
    extern __shared__ __align__(1024) unsigned char dsm[];
    const int tid  = threadIdx.x;
    const int bn   = blockIdx.x;
    const int bm   = blockIdx.y;
    const int wid  = tid >> 5, lane = tid & 31;
    const int wm   = wid & 3, wn = wid >> 2;
    const int m0   = bm * 128, n0 = bn * 128;
    const int K = E_DIM, NC = E_DIM / 32;    // 32
    const uint32_t sb = smem_u32(dsm);
    const uint32_t convB = sb;               // conv[c]: hi 8KB + lo 8KB at sb + c*16384
    const uint32_t bBase = sb + 32768;       // B stage s: hi 8KB + lo 8KB at bBase + s*16384

    auto loadBtile = [&](uint32_t dst, const __nv_bfloat16* p, int k0) {
#pragma unroll
        for (int it = 0; it < 2; it++) {
            int q = tid + it * 256;          // 0..511
            int row = q >> 2;
            int c16 = q & 3;
            uint32_t off = (uint32_t)(row * 64) + (uint32_t)((c16 ^ ((row >> 1) & 3)) << 4);
            cp16(dst + off, (const char*)p + ((size_t)(n0 + row) * K + k0 + c16 * 8) * 2);
        }
    };
    auto loadB = [&](int s, int k0) {
        uint32_t st = bBase + s * 16384;
        loadBtile(st, Bhi, k0);
        loadBtile(st + TB32, Blo, k0);
        asm volatile("cp.async.commit_group;" ::: "memory");
    };

    // in-kernel x conversion: thread -> row = tid>>1, half = tid&1 (16 floats)
    auto cvtX = [&](int k0, int buf) {
        const int row = tid >> 1, half = tid & 1;
        const float* src = X + (size_t)(m0 + row) * K + k0 + half * 16;
        float4 f0 = *(const float4*)(src + 0);
        float4 f1 = *(const float4*)(src + 4);
        float4 f2 = *(const float4*)(src + 8);
        float4 f3 = *(const float4*)(src + 12);
        unsigned char* hiP = dsm + buf * 16384;
        unsigned char* loP = hiP + TB32;
        const uint32_t sw = (uint32_t)((row >> 1) & 3);
#pragma unroll
        for (int c = 0; c < 2; c++) {
            float4 a = c ? f2 : f0;
            float4 b = c ? f3 : f1;
            uint32_t off = (uint32_t)(row * 64) +
                           (uint32_t)((((uint32_t)(half * 2 + c)) ^ sw) << 4);
            uint4 hv, lv;
            hv.x = pack2(a.x, a.y); hv.y = pack2(a.z, a.w);
            hv.z = pack2(b.x, b.y); hv.w = pack2(b.z, b.w);
            lv.x = pack2(a.x - __bfloat162float(__float2bfloat16(a.x)),
                         a.y - __bfloat162float(__float2bfloat16(a.y)));
            lv.y = pack2(a.z - __bfloat162float(__float2bfloat16(a.z)),
                         a.w - __bfloat162float(__float2bfloat16(a.w)));
            lv.z = pack2(b.x - __bfloat162float(__float2bfloat16(b.x)),
                         b.y - __bfloat162float(__float2bfloat16(b.y)));
            lv.w = pack2(b.z - __bfloat162float(__float2bfloat16(b.z)),
                         b.w - __bfloat162float(__float2bfloat16(b.w)));
            *(uint4*)(hiP + off) = hv;
            *(uint4*)(loP + off) = lv;
        }
    };

    const int aRow = wm * 32 + (lane & 15);
    const uint32_t aK  = ((lane >> 4) & 1) * 16;
    const uint32_t aSw = (uint32_t)((aRow >> 1) & 3) << 4;
    const int bRow = wn * 64 + (lane & 7) + (((lane >> 4) & 1) << 3);
    const uint32_t bK  = ((lane >> 3) & 1) * 16;
    const uint32_t bSw = (uint32_t)((bRow >> 1) & 3) << 4;

    float acc[2][8][4];
#pragma unroll
    for (int mi = 0; mi < 2; mi++)
#pragma unroll
        for (int ni = 0; ni < 8; ni++)
#pragma unroll
            for (int e = 0; e < 4; e++) acc[mi][ni][e] = 0.f;

    loadB(0, 0);
    loadB(1, 32);
    cvtX(0, 0);

    for (int i = 0; i < NC; i++) {
        if (i + 1 < NC) asm volatile("cp.async.wait_group 1;" ::: "memory");
        else            asm volatile("cp.async.wait_group 0;" ::: "memory");
        __syncthreads();
        if (i + 2 < NC) loadB((i + 2) % 3, (i + 2) * 32);
        if (i + 1 < NC) cvtX((i + 1) * 32, (i + 1) & 1);

        const uint32_t sAh = convB + (i & 1) * 16384, sAl = sAh + TB32;
        const uint32_t sBh = bBase + (i % 3) * 16384, sBl = sBh + TB32;

#pragma unroll
        for (int ks = 0; ks < 2; ks++) {
            uint32_t ahh[2][4], all[2][4], bb[4][4];
            const uint32_t akc = (uint32_t)(ks * 32) + aK;
            const uint32_t bkc = (uint32_t)(ks * 32) + bK;
            uint32_t bro[4];
#pragma unroll
            for (int mi = 0; mi < 2; mi++) {
                uint32_t ro = (uint32_t)((aRow + mi * 16) * 64) + (akc ^ aSw);
                ldsm4(ahh[mi], sAh + ro);
                ldsm4(all[mi], sAl + ro);
            }
#pragma unroll
            for (int nj = 0; nj < 4; nj++) {
                bro[nj] = (uint32_t)((bRow + nj * 16) * 64) + (bkc ^ bSw);
                ldsm4(bb[nj], sBh + bro[nj]);
            }
            // P1: hi*hi
#pragma unroll
            for (int mi = 0; mi < 2; mi++)
#pragma unroll
                for (int nj = 0; nj < 4; nj++) {
                    mma16816(acc[mi][2 * nj],     ahh[mi], &bb[nj][0]);
                    mma16816(acc[mi][2 * nj + 1], ahh[mi], &bb[nj][2]);
                }
            // P2: lo*hi
#pragma unroll
            for (int mi = 0; mi < 2; mi++)
#pragma unroll
                for (int nj = 0; nj < 4; nj++) {
                    mma16816(acc[mi][2 * nj],     all[mi], &bb[nj][0]);
                    mma16816(acc[mi][2 * nj + 1], all[mi], &bb[nj][2]);
                }
            // reload B as lo, P3: hi*lo
#pragma unroll
            for (int nj = 0; nj < 4; nj++) ldsm4(bb[nj], sBl + bro[nj]);
#pragma unroll
            for (int mi = 0; mi < 2; mi++)
#pragma unroll
                for (int nj = 0; nj < 4; nj++) {
                    mma16816(acc[mi][2 * nj],     ahh[mi], &bb[nj][0]);
                    mma16816(acc[mi][2 * nj + 1], ahh[mi], &bb[nj][2]);
                }
        }
    }

    const int rBase = m0 + wm * 32 + (lane >> 2);
    const int cBase = n0 + wn * 64 + 2 * (lane & 3);
#pragma unroll
    for (int mi = 0; mi < 2; mi++) {
#pragma unroll
        for (int ni = 0; ni < 8; ni++) {
            const int c = cBase + ni * 8;
            const float b0 = bias[c], b1 = bias[c + 1];
#pragma unroll
            for (int half = 0; half < 2; half++) {
                const int r = rBase + mi * 16 + half * 8;
                float v0 = fmaxf(acc[mi][ni][2 * half]     + b0, 0.f);
                float v1 = fmaxf(acc[mi][ni][2 * half + 1] + b1, 0.f);
                __nv_bfloat16 h0 = __float2bfloat16(v0), h1 = __float2bfloat16(v1);
                size_t o = ((size_t)r * 512 + c) >> 1;
                ((__nv_bfloat162*)OutHi)[o] = __halves2bfloat162(h0, h1);
                ((__nv_bfloat162*)OutLo)[o] = __halves2bfloat162(
                    __float2bfloat16(v0 - __bfloat162float(h0)),
                    __float2bfloat16(v1 - __bfloat162float(h1)));
            }
        }
    }
}

__global__ __launch_bounds__(256, 2)
void gemm2_hmma(const __nv_bfloat16* __restrict__ Ahi, const __nv_bfloat16* __restrict__ Alo,
                const __nv_bfloat16* __restrict__ Bhi, const __nv_bfloat16* __restrict__ Blo,
                const float* __restrict__ bias, const float* __restrict__ Wa)
{
    extern __shared__ __align__(1024) unsigned char dsm[];
    const int tid  = threadIdx.x;
    const int bn   = blockIdx.x;
    const int bm   = blockIdx.y;
    const int wid  = tid >> 5, lane = tid & 31;
    const int wm   = wid & 3, wn = wid >> 2;
    const int m0   = bm * 128, n0 = bn * 128;
    const int K = L_DIM, NC = L_DIM / 32;   // 16
    const uint32_t sb = smem_u32(dsm);

    auto loadTile = [&](uint32_t dst, const __nv_bfloat16* p, int gr0, int k0) {
#pragma unroll
        for (int it = 0; it < 2; it++) {
            int q = tid + it * 256;
            int row = q >> 2;
            int c16 = q & 3;
            uint32_t off = (uint32_t)(row * 64) + (uint32_t)((c16 ^ ((row >> 1) & 3)) << 4);
            cp16(dst + off, (const char*)p + ((size_t)(gr0 + row) * K + k0 + c16 * 8) * 2);
        }
    };
    auto loadStage = [&](int s, int k0) {
        uint32_t st = sb + s * (4 * TB32);
        loadTile(st,            Ahi, m0, k0);
        loadTile(st + TB32,     Alo, m0, k0);
        loadTile(st + 2 * TB32, Bhi, n0, k0);
        loadTile(st + 3 * TB32, Blo, n0, k0);
        asm volatile("cp.async.commit_group;" ::: "memory");
    };

    const int aRow = wm * 32 + (lane & 15);
    const uint32_t aK  = ((lane >> 4) & 1) * 16;
    const uint32_t aSw = (uint32_t)((aRow >> 1) & 3) << 4;
    const int bRow = wn * 64 + (lane & 7) + (((lane >> 4) & 1) << 3);
    const uint32_t bK  = ((lane >> 3) & 1) * 16;
    const uint32_t bSw = (uint32_t)((bRow >> 1) & 3) << 4;

    float acc[2][8][4];
#pragma unroll
    for (int mi = 0; mi < 2; mi++)
#pragma unroll
        for (int ni = 0; ni < 8; ni++)
#pragma unroll
            for (int e = 0; e < 4; e++) acc[mi][ni][e] = 0.f;

    loadStage(0, 0);
    loadStage(1, 32);

    for (int i = 0; i < NC; i++) {
        if (i + 1 < NC) asm volatile("cp.async.wait_group 1;" ::: "memory");
        else            asm volatile("cp.async.wait_group 0;" ::: "memory");
        __syncthreads();
        if (i + 2 < NC) loadStage((i + 2) % 3, (i + 2) * 32);

        const uint32_t st  = sb + (i % 3) * (4 * TB32);
        const uint32_t sAh = st, sAl = st + TB32;
        const uint32_t sBh = st + 2 * TB32, sBl = st + 3 * TB32;

#pragma unroll
        for (int ks = 0; ks < 2; ks++) {
            uint32_t ahh[2][4], all[2][4], bb[4][4];
            const uint32_t akc = (uint32_t)(ks * 32) + aK;
            const uint32_t bkc = (uint32_t)(ks * 32) + bK;
            uint32_t bro[4];
#pragma unroll
            for (int mi = 0; mi < 2; mi++) {
                uint32_t ro = (uint32_t)((aRow + mi * 16) * 64) + (akc ^ aSw);
                ldsm4(ahh[mi], sAh + ro);
                ldsm4(all[mi], sAl + ro);
            }
#pragma unroll
            for (int nj = 0; nj < 4; nj++) {
                bro[nj] = (uint32_t)((bRow + nj * 16) * 64) + (bkc ^ bSw);
                ldsm4(bb[nj], sBh + bro[nj]);
            }
#pragma unroll
            for (int mi = 0; mi < 2; mi++)
#pragma unroll
                for (int nj = 0; nj < 4; nj++) {
                    mma16816(acc[mi][2 * nj],     ahh[mi], &bb[nj][0]);
                    mma16816(acc[mi][2 * nj + 1], ahh[mi], &bb[nj][2]);
                }
#pragma unroll
            for (int mi = 0; mi < 2; mi++)
#pragma unroll
                for (int nj = 0; nj < 4; nj++) {
                    mma16816(acc[mi][2 * nj],     all[mi], &bb[nj][0]);
                    mma16816(acc[mi][2 * nj + 1], all[mi], &bb[nj][2]);
                }
#pragma unroll
            for (int nj = 0; nj < 4; nj++) ldsm4(bb[nj], sBl + bro[nj]);
#pragma unroll
            for (int mi = 0; mi < 2; mi++)
#pragma unroll
                for (int nj = 0; nj < 4; nj++) {
                    mma16816(acc[mi][2 * nj],     ahh[mi], &bb[nj][0]);
                    mma16816(acc[mi][2 * nj + 1], ahh[mi], &bb[nj][2]);
                }
        }
    }

    // fused gated-attention projection epilogue
    const int rBase = m0 + wm * 32 + (lane >> 2);
    const int cBase = n0 + wn * 64 + 2 * (lane & 3);
#pragma unroll
    for (int mi = 0; mi < 2; mi++) {
#pragma unroll
        for (int half = 0; half < 2; half++) {
            const int r = rBase + mi * 16 + half * 8;
            float s0 = 0.f, s1 = 0.f;
#pragma unroll
            for (int ni = 0; ni < 8; ni++) {
                const int c = cBase + ni * 8;
                float v0 = acc[mi][ni][2 * half]     + bias[c];
                float v1 = acc[mi][ni][2 * half + 1] + bias[c + 1];
                float gg = tanhf(v0) / (1.f + expf(-v1));
                const int gc = c >> 1;
                s0 = fmaf(gg, Wa[gc], s0);
                s1 = fmaf(gg, Wa[D_DIM + gc], s1);
            }
            s0 += __shfl_xor_sync(0xFFFFFFFFu, s0, 1);
            s0 += __shfl_xor_sync(0xFFFFFFFFu, s0, 2);
            s1 += __shfl_xor_sync(0xFFFFFFFFu, s1, 1);
            s1 += __shfl_xor_sync(0xFFFFFFFFu, s1, 2);
            if ((lane & 3) == 0) {
                atomicAdd(&g_A[2 * r],     s0);
                atomicAdd(&g_A[2 * r + 1], s1);
            }
        }
    }
}

// ---------------- finalize: +ba, raw_attention out, per-class max, histogram ----------------
__global__ void finalize_kernel(const float* __restrict__ ba, const int* __restrict__ labelPtr,
                                float* __restrict__ out_att)
{
    __shared__ unsigned sk0, sk1;
    if (threadIdx.x == 0) { sk0 = 0u; sk1 = 0u; }
    __syncthreads();
    int i = blockIdx.x * blockDim.x + threadIdx.x;
    int lab = labelPtr ? *labelPtr : 0;
    float a0 = g_A[2 * i] + ba[0];
    float a1 = g_A[2 * i + 1] + ba[1];
    g_A[2 * i] = a0; g_A[2 * i + 1] = a1;
    out_att[i] = a0;
    out_att[NROWS + i] = a1;
    atomicMax(&sk0, monoKey(a0));
    atomicMax(&sk1, monoKey(a1));
    float sel = lab ? a1 : a0;
    atomicAdd(&g_hist[monoKey(sel) >> 18], 1);
    __syncthreads();
    if (threadIdx.x == 0) {
        atomicMax(&g_maxkey[0], sk0);
        atomicMax(&g_maxkey[1], sk1);
    }
}

// ---------------- fused softmax-weighted bag accumulation (h = hi+lo) ----------------
__global__ void bag_kernel()
{
    const int t = threadIdx.x;
    const int rowsPerBlock = NROWS / gridDim.x;
    const int r0 = blockIdx.x * rowsPerBlock;
    const float m0 = monoDecode(g_maxkey[0]);
    const float m1 = monoDecode(g_maxkey[1]);

    float a00 = 0.f, a01 = 0.f, a10 = 0.f, a11 = 0.f;
    float z0 = 0.f, z1 = 0.f;
    for (int r = r0; r < r0 + rowsPerBlock; r++) {
        float w0 = expf(g_A[2 * r]     - m0);
        float w1 = expf(g_A[2 * r + 1] - m1);
        const __nv_bfloat162* hh = (const __nv_bfloat162*)(g_hhi + (size_t)r * L_DIM);
        const __nv_bfloat162* hl = (const __nv_bfloat162*)(g_hlo + (size_t)r * L_DIM);
        __nv_bfloat162 a2 = hh[t], b2 = hl[t];
        float v0 = __low2float(a2)  + __low2float(b2);
        float v1 = __high2float(a2) + __high2float(b2);
        a00 = fmaf(w0, v0, a00); a01 = fmaf(w0, v1, a01);
        a10 = fmaf(w1, v0, a10); a11 = fmaf(w1, v1, a11);
        if (t == 0) { z0 += w0; z1 += w1; }
    }
    atomicAdd(&g_bag[2 * t], a00);
    atomicAdd(&g_bag[2 * t + 1], a01);
    atomicAdd(&g_bag[L_DIM + 2 * t], a10);
    atomicAdd(&g_bag[L_DIM + 2 * t + 1], a11);
    if (t == 0) { atomicAdd(&g_Z[0], z0); atomicAdd(&g_Z[1], z1); }
}

// ---------------- top-k machinery ----------------
__global__ void scan_kernel()
{
    __shared__ int csum[256];
    int t = threadIdx.x;
    int s = 0;
    for (int b = t * 64; b < t * 64 + 64; b++) s += g_hist[b];
    csum[t] = s;
    __syncthreads();
    if (t == 0) {
        int cum = 0, binhi = 0;
        for (int c = 255; c >= 0; c--) {
            if (cum + csum[c] >= NI) {
                for (int b = c * 64 + 63; b >= c * 64; b--) {
                    cum += g_hist[b];
                    if (cum >= NI) { binhi = b; break; }
                }
                break;
            }
            cum += csum[c];
        }
        g_binhi = binhi;
        cum = 0; int binlo = 16383;
        for (int c = 0; c < 256; c++) {
            if (cum + csum[c] >= NI) {
                for (int b = c * 64; b < c * 64 + 64; b++) {
                    cum += g_hist[b];
                    if (cum >= NI) { binlo = b; break; }
                }
                break;
            }
            cum += csum[c];
        }
        g_binlo = binlo;
        g_nhi = 0; g_nlo = 0;
    }
}

__global__ void cand_kernel(const int* __restrict__ labelPtr)
{
    int lab = labelPtr ? *labelPtr : 0;
    int binhi = g_binhi, binlo = g_binlo;
    for (int i = blockIdx.x * blockDim.x + threadIdx.x; i < NROWS; i += gridDim.x * blockDim.x) {
        float v = g_A[2 * i + lab];
        unsigned key = monoKey(v) >> 18;
        if ((int)key >= binhi) {
            int p = atomicAdd(&g_nhi, 1);
            g_chv[p] = v; g_chi[p] = i;
        }
        if ((int)key <= binlo) {
            int p = atomicAdd(&g_nlo, 1);
            g_clv[p] = v; g_cli[p] = i;
        }
    }
}

__global__ void select_kernel()
{
    __shared__ float sv[256];
    __shared__ int   si[256];
    __shared__ int   sp[256];
    const int t = threadIdx.x;
    const float NEG_INF = __int_as_float(0xFF800000);
    const float POS_INF = __int_as_float(0x7F800000);
    int nhi = g_nhi, nlo = g_nlo;

    for (int it = 0; it < NI; it++) {
        float bv = NEG_INF; int bi = 0x7FFFFFFF; int bp = -1;
        for (int p = t; p < nhi; p += 256) {
            float v = g_chv[p]; int idx = g_chi[p];
            if (v > bv || (v == bv && idx < bi)) { bv = v; bi = idx; bp = p; }
        }
        sv[t] = bv; si[t] = bi; sp[t] = bp;
        __syncthreads();
        for (int s = 128; s; s >>= 1) {
            if (t < s) {
                if (sv[t + s] > sv[t] || (sv[t + s] == sv[t] && si[t + s] < si[t])) {
                    sv[t] = sv[t + s]; si[t] = si[t + s]; sp[t] = sp[t + s];
                }
            }
            __syncthreads();
        }
        if (t == 0) { g_inst[it] = si[0]; g_chv[sp[0]] = NEG_INF; }
        __syncthreads();
    }
    for (int it = 0; it < NI; it++) {
        float bv = POS_INF; int bi = 0x7FFFFFFF; int bp = -1;
        for (int p = t; p < nlo; p += 256) {
            float v = g_clv[p]; int idx = g_cli[p];
            if (v < bv || (v == bv && idx < bi)) { bv = v; bi = idx; bp = p; }
        }
        sv[t] = bv; si[t] = bi; sp[t] = bp;
        __syncthreads();
        for (int s = 128; s; s >>= 1) {
            if (t < s) {
                if (sv[t + s] < sv[t] || (sv[t + s] == sv[t] && si[t + s] < si[t])) {
                    sv[t] = sv[t + s]; si[t] = si[t + s]; sp[t] = sp[t + s];
                }
            }
            __syncthreads();
        }
        if (t == 0) { g_inst[NI + it] = si[0]; g_clv[sp[0]] = POS_INF; }
        __syncthreads();
    }
}

// ---------------- instance loss ----------------
__global__ void loss_kernel(const int* __restrict__ labelPtr,
                            const float* __restrict__ Winst, const float* __restrict__ binst,
                            float* __restrict__ out_loss)
{
    __shared__ float sl[4];
    int lab = labelPtr ? *labelPtr : 0;
    const float* W0 = Winst + ((size_t)lab * 2 + 0) * L_DIM;
    const float* W1 = Winst + ((size_t)lab * 2 + 1) * L_DIM;
    float b0 = binst[lab * 2], b1 = binst[lab * 2 + 1];

    int warp = threadIdx.x >> 5, lane = threadIdx.x & 31;
    float lsum = 0.f;
    for (int r = warp; r < 2 * NI; r += 4) {
        const __nv_bfloat16* hh = g_hhi + (size_t)g_inst[r] * L_DIM;
        const __nv_bfloat16* hl = g_hlo + (size_t)g_inst[r] * L_DIM;
        float s0 = 0.f, s1 = 0.f;
        for (int k = lane; k < L_DIM; k += 32) {
            float v = __bfloat162float(hh[k]) + __bfloat162float(hl[k]);
            s0 = fmaf(v, W0[k], s0);
            s1 = fmaf(v, W1[k], s1);
        }
#pragma unroll
        for (int o = 16; o; o >>= 1) {
            s0 += __shfl_xor_sync(0xFFFFFFFFu, s0, o);
            s1 += __shfl_xor_sync(0xFFFFFFFFu, s1, o);
        }
        if (lane == 0) {
            float l0 = s0 + b0, l1 = s1 + b1;
            int tgt = (r < NI) ? 1 : 0;
            float u0 = l0 + ((tgt != 0) ? 1.f : 0.f);
            float u1 = l1 + ((tgt != 1) ? 1.f : 0.f);
            float m = fmaxf(u0, u1);
            float lse = m + logf(expf(u0 - m) + expf(u1 - m));
            float sy = (tgt == 0) ? l0 : l1;
            lsum += lse - sy;
        }
    }
    if (lane == 0) sl[warp] = lsum;
    __syncthreads();
    if (threadIdx.x == 0)
        *out_loss = (sl[0] + sl[1] + sl[2] + sl[3]) * (1.f / (2 * NI));
}

// ---------------- bag logits + softmax ----------------
__global__ void final_kernel(const float* __restrict__ Wbag, const float* __restrict__ bbag,
                             float* __restrict__ out)
{
    __shared__ float lg[2];
    int warp = threadIdx.x >> 5, lane = threadIdx.x & 31;
    if (warp < 2) {
        float s = 0.f;
        for (int k = lane; k < L_DIM; k += 32)
            s = fmaf(g_bag[warp * L_DIM + k], Wbag[warp * L_DIM + k], s);
#pragma unroll
        for (int o = 16; o; o >>= 1) s += __shfl_xor_sync(0xFFFFFFFFu, s, o);
        if (lane == 0) lg[warp] = s / g_Z[warp] + bbag[warp];
    }
    __syncthreads();
    if (threadIdx.x == 0) {
        float l0 = lg[0], l1 = lg[1];
        out[0] = l0; out[1] = l1;
        float m = fmaxf(l0, l1);
        float e0 = expf(l0 - m), e1 = expf(l1 - m);
        float s = e0 + e1;
        out[2] = e0 / s; out[3] = e1 / s;
    }
}

// ---------------- launch ----------------
extern "C" void kernel_launch(void* const* d_in, const int* in_sizes, int n_in,
                              void* d_out, int out_size)
{
    const int off = (n_in >= 14) ? 1 : 0;
    const float* x     = (const float*)d_in[0];
    const int*   label = (n_in >= 14) ? (const int*)d_in[1] : nullptr;
    const float* Wc    = (const float*)d_in[1 + off];
    const float* bc    = (const float*)d_in[2 + off];
    const float* Wv    = (const float*)d_in[3 + off];
    const float* bv    = (const float*)d_in[4 + off];
    const float* Wu    = (const float*)d_in[5 + off];
    const float* bu    = (const float*)d_in[6 + off];
    const float* Wa    = (const float*)d_in[7 + off];
    const float* ba    = (const float*)d_in[8 + off];
    const float* Winst = (const float*)d_in[9 + off];
    const float* binst = (const float*)d_in[10 + off];
    const float* Wbag  = (const float*)d_in[11 + off];
    const float* bbag  = (const float*)d_in[12 + off];
    float* out = (float*)d_out;

    void* p;
    cudaGetSymbolAddress(&p, g_hhi);  __nv_bfloat16* hhi = (__nv_bfloat16*)p;
    cudaGetSymbolAddress(&p, g_hlo);  __nv_bfloat16* hlo = (__nv_bfloat16*)p;
    cudaGetSymbolAddress(&p, g_wchi); __nv_bfloat16* wchi = (__nv_bfloat16*)p;
    cudaGetSymbolAddress(&p, g_wclo); __nv_bfloat16* wclo = (__nv_bfloat16*)p;
    cudaGetSymbolAddress(&p, g_wthi); __nv_bfloat16* wthi = (__nv_bfloat16*)p;
    cudaGetSymbolAddress(&p, g_wtlo); __nv_bfloat16* wtlo = (__nv_bfloat16*)p;
    cudaGetSymbolAddress(&p, g_bcat); float* bcat = (float*)p;

    cudaFuncSetAttribute(gemm1_fused, cudaFuncAttributeMaxDynamicSharedMemorySize, G1_SMEM);
    cudaFuncSetAttribute(gemm2_hmma,  cudaFuncAttributeMaxDynamicSharedMemorySize, G2_SMEM);

    // launches #1..#3 (gemm1 stays launch #4 for ncu)
    init_kernel<<<1024, 256>>>();
    split_kernel<<<256, 256>>>((const float4*)Wc, (__nv_bfloat162*)wchi, (__nv_bfloat162*)wclo,
                               (L_DIM * E_DIM) / 4);
    cat_kernel<<<(2 * D_DIM * L_DIM + 255) / 256, 256>>>(Wv, Wu, bv, bu, wthi, wtlo, bcat);

    // GEMM1 (launch #4): h = relu(x @ Wc^T + bc), fp32 x converted in-kernel
    gemm1_fused<<<dim3(4, NROWS / 128), 256, G1_SMEM>>>(x, wchi, wclo, bc, hhi, hlo);

    // GEMM2+3 + attention fused
    gemm2_hmma<<<dim3(4, NROWS / 128), 256, G2_SMEM>>>(hhi, hlo, wthi, wtlo, bcat, Wa);

    finalize_kernel<<<NROWS / 256, 256>>>(ba, label, out + 4);
    scan_kernel<<<1, 256>>>();
    cand_kernel<<<NROWS / 256, 256>>>(label);
    select_kernel<<<1, 256>>>();
    loss_kernel<<<1, 128>>>(label, Winst, binst, out + 4 + 2 * NROWS);
    bag_kernel<<<512, 256>>>();
    final_kernel<<<1, 64>>>(Wbag, bbag, out);
}

// round 8
// speedup vs baseline: 2.6806x; 1.0062x over previous
#include <cuda_runtime.h>
#include <cuda_bf16.h>
#include <math.h>
#include <stdint.h>

#define NROWS 131072
#define E_DIM 1024
#define L_DIM 512
#define D_DIM 256
#define NI    50

// ---------------- device scratch (allocation-free rule) ----------------
__device__ __nv_bfloat16 g_hhi[(size_t)NROWS * L_DIM];
__device__ __nv_bfloat16 g_hlo[(size_t)NROWS * L_DIM];
__device__ __nv_bfloat16 g_wchi[L_DIM * E_DIM];
__device__ __nv_bfloat16 g_wclo[L_DIM * E_DIM];
__device__ __nv_bfloat16 g_wthi[2 * D_DIM * L_DIM];
__device__ __nv_bfloat16 g_wtlo[2 * D_DIM * L_DIM];
__device__ float g_bcat[2 * D_DIM];
__device__ float g_A[(size_t)NROWS * 2];
__device__ int      g_hist[16384];
__device__ unsigned g_maxkey[2];
__device__ float    g_Z[2];
__device__ float    g_bag[2 * L_DIM];
__device__ int      g_binhi, g_binlo;
__device__ int      g_nhi, g_nlo;
__device__ float g_chv[NROWS]; __device__ int g_chi[NROWS];
__device__ float g_clv[NROWS]; __device__ int g_cli[NROWS];
__device__ int   g_inst[2 * NI];

// ---------------- PTX helpers ----------------
__device__ __forceinline__ uint32_t smem_u32(const void* p) {
    uint32_t a;
    asm("{ .reg .u64 t; cvta.to.shared.u64 t, %1; cvt.u32.u64 %0, t; }" : "=r"(a) : "l"(p));
    return a;
}
__device__ __forceinline__ void cp16(uint32_t s, const void* g) {
    asm volatile("cp.async.cg.shared.global [%0], [%1], 16;" :: "r"(s), "l"(g));
}
__device__ __forceinline__ void ldsm4(uint32_t* r, uint32_t addr) {
    asm volatile("ldmatrix.sync.aligned.m8n8.x4.shared.b16 {%0,%1,%2,%3}, [%4];"
                 : "=r"(r[0]), "=r"(r[1]), "=r"(r[2]), "=r"(r[3]) : "r"(addr));
}
__device__ __forceinline__ void mma16816(float* c, const uint32_t* a, const uint32_t* b) {
    asm volatile(
        "mma.sync.aligned.m16n8k16.row.col.f32.bf16.bf16.f32 "
        "{%0,%1,%2,%3}, {%4,%5,%6,%7}, {%8,%9}, {%0,%1,%2,%3};"
        : "+f"(c[0]), "+f"(c[1]), "+f"(c[2]), "+f"(c[3])
        : "r"(a[0]), "r"(a[1]), "r"(a[2]), "r"(a[3]), "r"(b[0]), "r"(b[1]));
}

// monotone float <-> uint key
__device__ __forceinline__ unsigned monoKey(float f) {
    unsigned u = __float_as_uint(f);
    return (u & 0x80000000u) ? ~u : (u | 0x80000000u);
}
__device__ __forceinline__ float monoDecode(unsigned k) {
    unsigned u = (k & 0x80000000u) ? (k & 0x7FFFFFFFu) : ~k;
    return __uint_as_float(u);
}

__device__ __forceinline__ uint32_t pack2(float a, float b) {
    __nv_bfloat162 t = __halves2bfloat162(__float2bfloat16(a), __float2bfloat16(b));
    return *(uint32_t*)&t;
}

// ---------------- init ----------------
__global__ void init_kernel() {
    int i = blockIdx.x * blockDim.x + threadIdx.x;
    if (i < 2 * NROWS) g_A[i] = 0.f;
    if (i < 16384) g_hist[i] = 0;
    if (i < 2 * L_DIM) g_bag[i] = 0.f;
    if (i < 2) { g_Z[i] = 0.f; g_maxkey[i] = 0u; }
    if (i == 0) { g_nhi = 0; g_nlo = 0; }
}

// ---------------- fp32 -> bf16 hi/lo split (weights only) ----------------
__global__ void split_kernel(const float4* __restrict__ in, __nv_bfloat162* __restrict__ hi,
                             __nv_bfloat162* __restrict__ lo, int n4) {
    int i = blockIdx.x * blockDim.x + threadIdx.x;
    int stride = gridDim.x * blockDim.x;
    for (; i < n4; i += stride) {
        float4 v = in[i];
        __nv_bfloat16 h0 = __float2bfloat16(v.x), h1 = __float2bfloat16(v.y);
        __nv_bfloat16 h2 = __float2bfloat16(v.z), h3 = __float2bfloat16(v.w);
        hi[2 * i]     = __halves2bfloat162(h0, h1);
        hi[2 * i + 1] = __halves2bfloat162(h2, h3);
        lo[2 * i]     = __halves2bfloat162(__float2bfloat16(v.x - __bfloat162float(h0)),
                                           __float2bfloat16(v.y - __bfloat162float(h1)));
        lo[2 * i + 1] = __halves2bfloat162(__float2bfloat16(v.z - __bfloat162float(h2)),
                                           __float2bfloat16(v.w - __bfloat162float(h3)));
    }
}

// build interleaved Wcat (row 2j = Wv[j], row 2j+1 = Wu[j]) hi/lo + bcat
__global__ void cat_kernel(const float* __restrict__ Wv, const float* __restrict__ Wu,
                           const float* __restrict__ bv, const float* __restrict__ bu,
                           __nv_bfloat16* __restrict__ whi, __nv_bfloat16* __restrict__ wlo,
                           float* __restrict__ bcat) {
    int i = blockIdx.x * blockDim.x + threadIdx.x;
    if (i < 2 * D_DIM * L_DIM) {
        int row = i >> 9, k = i & 511;
        int j = row >> 1, e = row & 1;
        float v = e ? Wu[j * L_DIM + k] : Wv[j * L_DIM + k];
        __nv_bfloat16 h = __float2bfloat16(v);
        whi[i] = h;
        wlo[i] = __float2bfloat16(v - __bfloat162float(h));
    }
    if (i < 2 * D_DIM) {
        int j = i >> 1, e = i & 1;
        bcat[i] = e ? bu[j] : bv[j];
    }
}

// ================= GEMM: 128 threads, warp grid 2x2, warp tile 64x64, BK=32 =================
// tile = 128 rows x 32 bf16 = 8KB, row stride 64B, swizzle: col16 ^= (row>>1)&3
#define TB32 8192
#define G1_SMEM (2 * 16384 + 3 * 16384)   // conv 2x(hi+lo) + B 3x(hi+lo) = 80KB
#define G2_SMEM (3 * 4 * TB32)            // 3 stages x (Ahi,Alo,Bhi,Blo) = 96KB

__global__ __launch_bounds__(128, 2)
void gemm1_fused(const float* __restrict__ X,
                 const __nv_bfloat16* __restrict__ Bhi, const __nv_bfloat16* __restrict__ Blo,
                 const float* __restrict__ bias,
                 __nv_bfloat16* __restrict__ OutHi, __nv_bfloat16* __restrict__ OutLo)
{
    extern __shared__ __align__(1024) unsigned char dsm[];
    const int tid  = threadIdx.x;
    const int bn   = blockIdx.x;
    const int bm   = blockIdx.y;
    const int wid  = tid >> 5, lane = tid & 31;
    const int wm   = wid & 1, wn = wid >> 1;       // 2x2 warp grid
    const int m0   = bm * 128, n0 = bn * 128;
    const int K = E_DIM, NC = E_DIM / 32;          // 32
    const uint32_t sb = smem_u32(dsm);
    const uint32_t convB = sb;                     // conv[c]: hi 8KB + lo 8KB
    const uint32_t bBase = sb + 32768;

    auto loadBtile = [&](uint32_t dst, const __nv_bfloat16* p, int k0) {
#pragma unroll
        for (int it = 0; it < 4; it++) {
            int q = tid + it * 128;
            int row = q >> 2;
            int c16 = q & 3;
            uint32_t off = (uint32_t)(row * 64) + (uint32_t)((c16 ^ ((row >> 1) & 3)) << 4);
            cp16(dst + off, (const char*)p + ((size_t)(n0 + row) * K + k0 + c16 * 8) * 2);
        }
    };
    auto loadB = [&](int s, int k0) {
        uint32_t st = bBase + s * 16384;
        loadBtile(st, Bhi, k0);
        loadBtile(st + TB32, Blo, k0);
        asm volatile("cp.async.commit_group;" ::: "memory");
    };

    // in-kernel x conversion: 4 passes, thread -> (row = q>>2, seg = q&3 of 8 floats)
    auto cvtX = [&](int k0, int buf) {
        unsigned char* hiP = dsm + buf * 16384;
        unsigned char* loP = hiP + TB32;
#pragma unroll
        for (int pass = 0; pass < 4; pass++) {
            int q = tid + pass * 128;
            int row = q >> 2, seg = q & 3;
            const float* src = X + (size_t)(m0 + row) * K + k0 + seg * 8;
            float4 a = *(const float4*)(src + 0);
            float4 b = *(const float4*)(src + 4);
            uint32_t off = (uint32_t)(row * 64) +
                           (uint32_t)(((uint32_t)seg ^ ((uint32_t)(row >> 1) & 3)) << 4);
            uint4 hv, lv;
            hv.x = pack2(a.x, a.y); hv.y = pack2(a.z, a.w);
            hv.z = pack2(b.x, b.y); hv.w = pack2(b.z, b.w);
            lv.x = pack2(a.x - __bfloat162float(__float2bfloat16(a.x)),
                         a.y - __bfloat162float(__float2bfloat16(a.y)));
            lv.y = pack2(a.z - __bfloat162float(__float2bfloat16(a.z)),
                         a.w - __bfloat162float(__float2bfloat16(a.w)));
            lv.z = pack2(b.x - __bfloat162float(__float2bfloat16(b.x)),
                         b.y - __bfloat162float(__float2bfloat16(b.y)));
            lv.w = pack2(b.z - __bfloat162float(__float2bfloat16(b.z)),
                         b.w - __bfloat162float(__float2bfloat16(b.w)));
            *(uint4*)(hiP + off) = hv;
            *(uint4*)(loP + off) = lv;
        }
    };

    const int aRow = wm * 64 + (lane & 15);
    const uint32_t aK  = ((lane >> 4) & 1) * 16;
    const uint32_t aSw = (uint32_t)((aRow >> 1) & 3) << 4;
    const int bRow = wn * 64 + (lane & 7) + (((lane >> 4) & 1) << 3);
    const uint32_t bK  = ((lane >> 3) & 1) * 16;
    const uint32_t bSw = (uint32_t)((bRow >> 1) & 3) << 4;

    float acc[4][8][4];
#pragma unroll
    for (int mi = 0; mi < 4; mi++)
#pragma unroll
        for (int ni = 0; ni < 8; ni++)
#pragma unroll
            for (int e = 0; e < 4; e++) acc[mi][ni][e] = 0.f;

    loadB(0, 0);
    loadB(1, 32);
    cvtX(0, 0);

    for (int i = 0; i < NC; i++) {
        if (i + 1 < NC) asm volatile("cp.async.wait_group 1;" ::: "memory");
        else            asm volatile("cp.async.wait_group 0;" ::: "memory");
        __syncthreads();
        if (i + 2 < NC) loadB((i + 2) % 3, (i + 2) * 32);
        if (i + 1 < NC) cvtX((i + 1) * 32, (i + 1) & 1);

        const uint32_t sAh = convB + (i & 1) * 16384, sAl = sAh + TB32;
        const uint32_t sBh = bBase + (i % 3) * 16384, sBl = sBh + TB32;

#pragma unroll
        for (int ks = 0; ks < 2; ks++) {
            uint32_t ahh[4][4], all[4][4], bb[4][4], bro[4];
            const uint32_t akc = (uint32_t)(ks * 32) + aK;
            const uint32_t bkc = (uint32_t)(ks * 32) + bK;
#pragma unroll
            for (int mi = 0; mi < 4; mi++) {
                uint32_t ro = (uint32_t)((aRow + mi * 16) * 64) + (akc ^ aSw);
                ldsm4(ahh[mi], sAh + ro);
                ldsm4(all[mi], sAl + ro);
            }
#pragma unroll
            for (int nj = 0; nj < 4; nj++) {
                bro[nj] = (uint32_t)((bRow + nj * 16) * 64) + (bkc ^ bSw);
                ldsm4(bb[nj], sBh + bro[nj]);
            }
            // P1: hi*hi
#pragma unroll
            for (int mi = 0; mi < 4; mi++)
#pragma unroll
                for (int nj = 0; nj < 4; nj++) {
                    mma16816(acc[mi][2 * nj],     ahh[mi], &bb[nj][0]);
                    mma16816(acc[mi][2 * nj + 1], ahh[mi], &bb[nj][2]);
                }
            // P2: lo*hi
#pragma unroll
            for (int mi = 0; mi < 4; mi++)
#pragma unroll
                for (int nj = 0; nj < 4; nj++) {
                    mma16816(acc[mi][2 * nj],     all[mi], &bb[nj][0]);
                    mma16816(acc[mi][2 * nj + 1], all[mi], &bb[nj][2]);
                }
            // reload B lo, P3: hi*lo
#pragma unroll
            for (int nj = 0; nj < 4; nj++) ldsm4(bb[nj], sBl + bro[nj]);
#pragma unroll
            for (int mi = 0; mi < 4; mi++)
#pragma unroll
                for (int nj = 0; nj < 4; nj++) {
                    mma16816(acc[mi][2 * nj],     ahh[mi], &bb[nj][0]);
                    mma16816(acc[mi][2 * nj + 1], ahh[mi], &bb[nj][2]);
                }
        }
    }

    const int rBase = m0 + wm * 64 + (lane >> 2);
    const int cBase = n0 + wn * 64 + 2 * (lane & 3);
#pragma unroll
    for (int mi = 0; mi < 4; mi++) {
#pragma unroll
        for (int ni = 0; ni < 8; ni++) {
            const int c = cBase + ni * 8;
            const float b0 = bias[c], b1 = bias[c + 1];
#pragma unroll
            for (int half = 0; half < 2; half++) {
                const int r = rBase + mi * 16 + half * 8;
                float v0 = fmaxf(acc[mi][ni][2 * half]     + b0, 0.f);
                float v1 = fmaxf(acc[mi][ni][2 * half + 1] + b1, 0.f);
                __nv_bfloat16 h0 = __float2bfloat16(v0), h1 = __float2bfloat16(v1);
                size_t o = ((size_t)r * 512 + c) >> 1;
                ((__nv_bfloat162*)OutHi)[o] = __halves2bfloat162(h0, h1);
                ((__nv_bfloat162*)OutLo)[o] = __halves2bfloat162(
                    __float2bfloat16(v0 - __bfloat162float(h0)),
                    __float2bfloat16(v1 - __bfloat162float(h1)));
            }
        }
    }
}

__global__ __launch_bounds__(128, 2)
void gemm2_hmma(const __nv_bfloat16* __restrict__ Ahi, const __nv_bfloat16* __restrict__ Alo,
                const __nv_bfloat16* __restrict__ Bhi, const __nv_bfloat16* __restrict__ Blo,
                const float* __restrict__ bias, const float* __restrict__ Wa)
{
    extern __shared__ __align__(1024) unsigned char dsm[];
    const int tid  = threadIdx.x;
    const int bn   = blockIdx.x;
    const int bm   = blockIdx.y;
    const int wid  = tid >> 5, lane = tid & 31;
    const int wm   = wid & 1, wn = wid >> 1;
    const int m0   = bm * 128, n0 = bn * 128;
    const int K = L_DIM, NC = L_DIM / 32;   // 16
    const uint32_t sb = smem_u32(dsm);

    auto loadTile = [&](uint32_t dst, const __nv_bfloat16* p, int gr0, int k0) {
#pragma unroll
        for (int it = 0; it < 4; it++) {
            int q = tid + it * 128;
            int row = q >> 2;
            int c16 = q & 3;
            uint32_t off = (uint32_t)(row * 64) + (uint32_t)((c16 ^ ((row >> 1) & 3)) << 4);
            cp16(dst + off, (const char*)p + ((size_t)(gr0 + row) * K + k0 + c16 * 8) * 2);
        }
    };
    auto loadStage = [&](int s, int k0) {
        uint32_t st = sb + s * (4 * TB32);
        loadTile(st,            Ahi, m0, k0);
        loadTile(st + TB32,     Alo, m0, k0);
        loadTile(st + 2 * TB32, Bhi, n0, k0);
        loadTile(st + 3 * TB32, Blo, n0, k0);
        asm volatile("cp.async.commit_group;" ::: "memory");
    };

    const int aRow = wm * 64 + (lane & 15);
    const uint32_t aK  = ((lane >> 4) & 1) * 16;
    const uint32_t aSw = (uint32_t)((aRow >> 1) & 3) << 4;
    const int bRow = wn * 64 + (lane & 7) + (((lane >> 4) & 1) << 3);
    const uint32_t bK  = ((lane >> 3) & 1) * 16;
    const uint32_t bSw = (uint32_t)((bRow >> 1) & 3) << 4;

    float acc[4][8][4];
#pragma unroll
    for (int mi = 0; mi < 4; mi++)
#pragma unroll
        for (int ni = 0; ni < 8; ni++)
#pragma unroll
            for (int e = 0; e < 4; e++) acc[mi][ni][e] = 0.f;

    loadStage(0, 0);
    loadStage(1, 32);

    for (int i = 0; i < NC; i++) {
        if (i + 1 < NC) asm volatile("cp.async.wait_group 1;" ::: "memory");
        else            asm volatile("cp.async.wait_group 0;" ::: "memory");
        __syncthreads();
        if (i + 2 < NC) loadStage((i + 2) % 3, (i + 2) * 32);

        const uint32_t st  = sb + (i % 3) * (4 * TB32);
        const uint32_t sAh = st, sAl = st + TB32;
        const uint32_t sBh = st + 2 * TB32, sBl = st + 3 * TB32;

#pragma unroll
        for (int ks = 0; ks < 2; ks++) {
            uint32_t ahh[4][4], all[4][4], bb[4][4], bro[4];
            const uint32_t akc = (uint32_t)(ks * 32) + aK;
            const uint32_t bkc = (uint32_t)(ks * 32) + bK;
#pragma unroll
            for (int mi = 0; mi < 4; mi++) {
                uint32_t ro = (uint32_t)((aRow + mi * 16) * 64) + (akc ^ aSw);
                ldsm4(ahh[mi], sAh + ro);
                ldsm4(all[mi], sAl + ro);
            }
#pragma unroll
            for (int nj = 0; nj < 4; nj++) {
                bro[nj] = (uint32_t)((bRow + nj * 16) * 64) + (bkc ^ bSw);
                ldsm4(bb[nj], sBh + bro[nj]);
            }
#pragma unroll
            for (int mi = 0; mi < 4; mi++)
#pragma unroll
                for (int nj = 0; nj < 4; nj++) {
                    mma16816(acc[mi][2 * nj],     ahh[mi], &bb[nj][0]);
                    mma16816(acc[mi][2 * nj + 1], ahh[mi], &bb[nj][2]);
                }
#pragma unroll
            for (int mi = 0; mi < 4; mi++)
#pragma unroll
                for (int nj = 0; nj < 4; nj++) {
                    mma16816(acc[mi][2 * nj],     all[mi], &bb[nj][0]);
                    mma16816(acc[mi][2 * nj + 1], all[mi], &bb[nj][2]);
                }
#pragma unroll
            for (int nj = 0; nj < 4; nj++) ldsm4(bb[nj], sBl + bro[nj]);
#pragma unroll
            for (int mi = 0; mi < 4; mi++)
#pragma unroll
                for (int nj = 0; nj < 4; nj++) {
                    mma16816(acc[mi][2 * nj],     ahh[mi], &bb[nj][0]);
                    mma16816(acc[mi][2 * nj + 1], ahh[mi], &bb[nj][2]);
                }
        }
    }

    // fused gated-attention projection epilogue
    const int rBase = m0 + wm * 64 + (lane >> 2);
    const int cBase = n0 + wn * 64 + 2 * (lane & 3);
#pragma unroll
    for (int mi = 0; mi < 4; mi++) {
#pragma unroll
        for (int half = 0; half < 2; half++) {
            const int r = rBase + mi * 16 + half * 8;
            float s0 = 0.f, s1 = 0.f;
#pragma unroll
            for (int ni = 0; ni < 8; ni++) {
                const int c = cBase + ni * 8;
                float v0 = acc[mi][ni][2 * half]     + bias[c];
                float v1 = acc[mi][ni][2 * half + 1] + bias[c + 1];
                float gg = tanhf(v0) / (1.f + expf(-v1));
                const int gc = c >> 1;
                s0 = fmaf(gg, Wa[gc], s0);
                s1 = fmaf(gg, Wa[D_DIM + gc], s1);
            }
            s0 += __shfl_xor_sync(0xFFFFFFFFu, s0, 1);
            s0 += __shfl_xor_sync(0xFFFFFFFFu, s0, 2);
            s1 += __shfl_xor_sync(0xFFFFFFFFu, s1, 1);
            s1 += __shfl_xor_sync(0xFFFFFFFFu, s1, 2);
            if ((lane & 3) == 0) {
                atomicAdd(&g_A[2 * r],     s0);
                atomicAdd(&g_A[2 * r + 1], s1);
            }
        }
    }
}

// ---------------- finalize: +ba, raw_attention out, per-class max, histogram ----------------
__global__ void finalize_kernel(const float* __restrict__ ba, const int* __restrict__ labelPtr,
                                float* __restrict__ out_att)
{
    __shared__ unsigned sk0, sk1;
    if (threadIdx.x == 0) { sk0 = 0u; sk1 = 0u; }
    __syncthreads();
    int i = blockIdx.x * blockDim.x + threadIdx.x;
    int lab = labelPtr ? *labelPtr : 0;
    float a0 = g_A[2 * i] + ba[0];
    float a1 = g_A[2 * i + 1] + ba[1];
    g_A[2 * i] = a0; g_A[2 * i + 1] = a1;
    out_att[i] = a0;
    out_att[NROWS + i] = a1;
    atomicMax(&sk0, monoKey(a0));
    atomicMax(&sk1, monoKey(a1));
    float sel = lab ? a1 : a0;
    atomicAdd(&g_hist[monoKey(sel) >> 18], 1);
    __syncthreads();
    if (threadIdx.x == 0) {
        atomicMax(&g_maxkey[0], sk0);
        atomicMax(&g_maxkey[1], sk1);
    }
}

// ---------------- fused softmax-weighted bag accumulation (h = hi+lo) ----------------
__global__ void bag_kernel()
{
    const int t = threadIdx.x;
    const int rowsPerBlock = NROWS / gridDim.x;
    const int r0 = blockIdx.x * rowsPerBlock;
    const float m0 = monoDecode(g_maxkey[0]);
    const float m1 = monoDecode(g_maxkey[1]);

    float a00 = 0.f, a01 = 0.f, a10 = 0.f, a11 = 0.f;
    float z0 = 0.f, z1 = 0.f;
    for (int r = r0; r < r0 + rowsPerBlock; r++) {
        float w0 = expf(g_A[2 * r]     - m0);
        float w1 = expf(g_A[2 * r + 1] - m1);
        const __nv_bfloat162* hh = (const __nv_bfloat162*)(g_hhi + (size_t)r * L_DIM);
        const __nv_bfloat162* hl = (const __nv_bfloat162*)(g_hlo + (size_t)r * L_DIM);
        __nv_bfloat162 a2 = hh[t], b2 = hl[t];
        float v0 = __low2float(a2)  + __low2float(b2);
        float v1 = __high2float(a2) + __high2float(b2);
        a00 = fmaf(w0, v0, a00); a01 = fmaf(w0, v1, a01);
        a10 = fmaf(w1, v0, a10); a11 = fmaf(w1, v1, a11);
        if (t == 0) { z0 += w0; z1 += w1; }
    }
    atomicAdd(&g_bag[2 * t], a00);
    atomicAdd(&g_bag[2 * t + 1], a01);
    atomicAdd(&g_bag[L_DIM + 2 * t], a10);
    atomicAdd(&g_bag[L_DIM + 2 * t + 1], a11);
    if (t == 0) { atomicAdd(&g_Z[0], z0); atomicAdd(&g_Z[1], z1); }
}

// ---------------- top-k machinery ----------------
__global__ void scan_kernel()
{
    __shared__ int csum[256];
    int t = threadIdx.x;
    int s = 0;
    for (int b = t * 64; b < t * 64 + 64; b++) s += g_hist[b];
    csum[t] = s;
    __syncthreads();
    if (t == 0) {
        int cum = 0, binhi = 0;
        for (int c = 255; c >= 0; c--) {
            if (cum + csum[c] >= NI) {
                for (int b = c * 64 + 63; b >= c * 64; b--) {
                    cum += g_hist[b];
                    if (cum >= NI) { binhi = b; break; }
                }
                break;
            }
            cum += csum[c];
        }
        g_binhi = binhi;
        cum = 0; int binlo = 16383;
        for (int c = 0; c < 256; c++) {
            if (cum + csum[c] >= NI) {
                for (int b = c * 64; b < c * 64 + 64; b++) {
                    cum += g_hist[b];
                    if (cum >= NI) { binlo = b; break; }
                }
                break;
            }
            cum += csum[c];
        }
        g_binlo = binlo;
        g_nhi = 0; g_nlo = 0;
    }
}

__global__ void cand_kernel(const int* __restrict__ labelPtr)
{
    int lab = labelPtr ? *labelPtr : 0;
    int binhi = g_binhi, binlo = g_binlo;
    for (int i = blockIdx.x * blockDim.x + threadIdx.x; i < NROWS; i += gridDim.x * blockDim.x) {
        float v = g_A[2 * i + lab];
        unsigned key = monoKey(v) >> 18;
        if ((int)key >= binhi) {
            int p = atomicAdd(&g_nhi, 1);
            g_chv[p] = v; g_chi[p] = i;
        }
        if ((int)key <= binlo) {
            int p = atomicAdd(&g_nlo, 1);
            g_clv[p] = v; g_cli[p] = i;
        }
    }
}

__global__ void select_kernel()
{
    __shared__ float sv[256];
    __shared__ int   si[256];
    __shared__ int   sp[256];
    const int t = threadIdx.x;
    const float NEG_INF = __int_as_float(0xFF800000);
    const float POS_INF = __int_as_float(0x7F800000);
    int nhi = g_nhi, nlo = g_nlo;

    for (int it = 0; it < NI; it++) {
        float bv = NEG_INF; int bi = 0x7FFFFFFF; int bp = -1;
        for (int p = t; p < nhi; p += 256) {
            float v = g_chv[p]; int idx = g_chi[p];
            if (v > bv || (v == bv && idx < bi)) { bv = v; bi = idx; bp = p; }
        }
        sv[t] = bv; si[t] = bi; sp[t] = bp;
        __syncthreads();
        for (int s = 128; s; s >>= 1) {
            if (t < s) {
                if (sv[t + s] > sv[t] || (sv[t + s] == sv[t] && si[t + s] < si[t])) {
                    sv[t] = sv[t + s]; si[t] = si[t + s]; sp[t] = sp[t + s];
                }
            }
            __syncthreads();
        }
        if (t == 0) { g_inst[it] = si[0]; g_chv[sp[0]] = NEG_INF; }
        __syncthreads();
    }
    for (int it = 0; it < NI; it++) {
        float bv = POS_INF; int bi = 0x7FFFFFFF; int bp = -1;
        for (int p = t; p < nlo; p += 256) {
            float v = g_clv[p]; int idx = g_cli[p];
            if (v < bv || (v == bv && idx < bi)) { bv = v; bi = idx; bp = p; }
        }
        sv[t] = bv; si[t] = bi; sp[t] = bp;
        __syncthreads();
        for (int s = 128; s; s >>= 1) {
            if (t < s) {
                if (sv[t + s] < sv[t] || (sv[t + s] == sv[t] && si[t + s] < si[t])) {
                    sv[t] = sv[t + s]; si[t] = si[t + s]; sp[t] = sp[t + s];
                }
            }
            __syncthreads();
        }
        if (t == 0) { g_inst[NI + it] = si[0]; g_clv[sp[0]] = POS_INF; }
        __syncthreads();
    }
}

// ---------------- instance loss ----------------
__global__ void loss_kernel(const int* __restrict__ labelPtr,
                            const float* __restrict__ Winst, const float* __restrict__ binst,
                            float* __restrict__ out_loss)
{
    __shared__ float sl[4];
    int lab = labelPtr ? *labelPtr : 0;
    const float* W0 = Winst + ((size_t)lab * 2 + 0) * L_DIM;
    const float* W1 = Winst + ((size_t)lab * 2 + 1) * L_DIM;
    float b0 = binst[lab * 2], b1 = binst[lab * 2 + 1];

    int warp = threadIdx.x >> 5, lane = threadIdx.x & 31;
    float lsum = 0.f;
    for (int r = warp; r < 2 * NI; r += 4) {
        const __nv_bfloat16* hh = g_hhi + (size_t)g_inst[r] * L_DIM;
        const __nv_bfloat16* hl = g_hlo + (size_t)g_inst[r] * L_DIM;
        float s0 = 0.f, s1 = 0.f;
        for (int k = lane; k < L_DIM; k += 32) {
            float v = __bfloat162float(hh[k]) + __bfloat162float(hl[k]);
            s0 = fmaf(v, W0[k], s0);
            s1 = fmaf(v, W1[k], s1);
        }
#pragma unroll
        for (int o = 16; o; o >>= 1) {
            s0 += __shfl_xor_sync(0xFFFFFFFFu, s0, o);
            s1 += __shfl_xor_sync(0xFFFFFFFFu, s1, o);
        }
        if (lane == 0) {
            float l0 = s0 + b0, l1 = s1 + b1;
            int tgt = (r < NI) ? 1 : 0;
            float u0 = l0 + ((tgt != 0) ? 1.f : 0.f);
            float u1 = l1 + ((tgt != 1) ? 1.f : 0.f);
            float m = fmaxf(u0, u1);
            float lse = m + logf(expf(u0 - m) + expf(u1 - m));
            float sy = (tgt == 0) ? l0 : l1;
            lsum += lse - sy;
        }
    }
    if (lane == 0) sl[warp] = lsum;
    __syncthreads();
    if (threadIdx.x == 0)
        *out_loss = (sl[0] + sl[1] + sl[2] + sl[3]) * (1.f / (2 * NI));
}

// ---------------- bag logits + softmax ----------------
__global__ void final_kernel(const float* __restrict__ Wbag, const float* __restrict__ bbag,
                             float* __restrict__ out)
{
    __shared__ float lg[2];
    int warp = threadIdx.x >> 5, lane = threadIdx.x & 31;
    if (warp < 2) {
        float s = 0.f;
        for (int k = lane; k < L_DIM; k += 32)
            s = fmaf(g_bag[warp * L_DIM + k], Wbag[warp * L_DIM + k], s);
#pragma unroll
        for (int o = 16; o; o >>= 1) s += __shfl_xor_sync(0xFFFFFFFFu, s, o);
        if (lane == 0) lg[warp] = s / g_Z[warp] + bbag[warp];
    }
    __syncthreads();
    if (threadIdx.x == 0) {
        float l0 = lg[0], l1 = lg[1];
        out[0] = l0; out[1] = l1;
        float m = fmaxf(l0, l1);
        float e0 = expf(l0 - m), e1 = expf(l1 - m);
        float s = e0 + e1;
        out[2] = e0 / s; out[3] = e1 / s;
    }
}

// ---------------- launch ----------------
extern "C" void kernel_launch(void* const* d_in, const int* in_sizes, int n_in,
                              void* d_out, int out_size)
{
    const int off = (n_in >= 14) ? 1 : 0;
    const float* x     = (const float*)d_in[0];
    const int*   label = (n_in >= 14) ? (const int*)d_in[1] : nullptr;
    const float* Wc    = (const float*)d_in[1 + off];
    const float* bc    = (const float*)d_in[2 + off];
    const float* Wv    = (const float*)d_in[3 + off];
    const float* bv    = (const float*)d_in[4 + off];
    const float* Wu    = (const float*)d_in[5 + off];
    const float* bu    = (const float*)d_in[6 + off];
    const float* Wa    = (const float*)d_in[7 + off];
    const float* ba    = (const float*)d_in[8 + off];
    const float* Winst = (const float*)d_in[9 + off];
    const float* binst = (const float*)d_in[10 + off];
    const float* Wbag  = (const float*)d_in[11 + off];
    const float* bbag  = (const float*)d_in[12 + off];
    float* out = (float*)d_out;

    void* p;
    cudaGetSymbolAddress(&p, g_hhi);  __nv_bfloat16* hhi = (__nv_bfloat16*)p;
    cudaGetSymbolAddress(&p, g_hlo);  __nv_bfloat16* hlo = (__nv_bfloat16*)p;
    cudaGetSymbolAddress(&p, g_wchi); __nv_bfloat16* wchi = (__nv_bfloat16*)p;
    cudaGetSymbolAddress(&p, g_wclo); __nv_bfloat16* wclo = (__nv_bfloat16*)p;
    cudaGetSymbolAddress(&p, g_wthi); __nv_bfloat16* wthi = (__nv_bfloat16*)p;
    cudaGetSymbolAddress(&p, g_wtlo); __nv_bfloat16* wtlo = (__nv_bfloat16*)p;
    cudaGetSymbolAddress(&p, g_bcat); float* bcat = (float*)p;

    cudaFuncSetAttribute(gemm1_fused, cudaFuncAttributeMaxDynamicSharedMemorySize, G1_SMEM);
    cudaFuncSetAttribute(gemm2_hmma,  cudaFuncAttributeMaxDynamicSharedMemorySize, G2_SMEM);

    // launches #1..#3 (gemm1 stays launch #4 for ncu)
    init_kernel<<<1024, 256>>>();
    split_kernel<<<256, 256>>>((const float4*)Wc, (__nv_bfloat162*)wchi, (__nv_bfloat162*)wclo,
                               (L_DIM * E_DIM) / 4);
    cat_kernel<<<(2 * D_DIM * L_DIM + 255) / 256, 256>>>(Wv, Wu, bv, bu, wthi, wtlo, bcat);

    // GEMM1 (launch #4): h = relu(x @ Wc^T + bc)
    gemm1_fused<<<dim3(4, NROWS / 128), 128, G1_SMEM>>>(x, wchi, wclo, bc, hhi, hlo);

    // GEMM2+3 + attention fused
    gemm2_hmma<<<dim3(4, NROWS / 128), 128, G2_SMEM>>>(hhi, hlo, wthi, wtlo, bcat, Wa);

    finalize_kernel<<<NROWS / 256, 256>>>(ba, label, out + 4);
    scan_kernel<<<1, 256>>>();
    cand_kernel<<<NROWS / 256, 256>>>(label);
    select_kernel<<<1, 256>>>();
    loss_kernel<<<1, 128>>>(label, Winst, binst, out + 4 + 2 * NROWS);
    bag_kernel<<<512, 256>>>();
    final_kernel<<<1, 64>>>(Wbag, bbag, out);
}